// round 11
// baseline (speedup 1.0000x reference)
#include <cuda_runtime.h>
#include <cuda_bf16.h>
#include <math.h>
#include <stdint.h>

#define TTOK 2048
#define DDIM 1024
#define TD (TTOK*DDIM)

// ---------------- scratch (static device memory; no allocations) ----------------
__device__ float g_scratch[68157440];

#define OFF_XW    ((size_t)2*TD)
#define OFF_RKVG  ((size_t)7*TD)
#define OFF_W     ((size_t)11*TD)
#define OFF_XXX   ((size_t)19*TD)
#define OFF_WMID  (OFF_XXX + (size_t)TTOK*160)
#define OFF_ACTHI ((size_t)20*TD)
#define OFF_ACTLO ((size_t)22*TD)
#define OFF_WTHI  ((size_t)24*TD)
#define OFF_WTLO  (OFF_WTHI + (size_t)2621440)
#define OFF_YGHI  (OFF_WTLO + (size_t)2621440)
#define OFF_YGLO  (OFF_YGHI + (size_t)(TD/2))
#define OFF_BF    (OFF_YGLO + (size_t)(TD/2))

static __device__ __forceinline__ float clip60(float x) {
    return fminf(fmaxf(x, -60.f), 60.f);
}
static __device__ __forceinline__ uint32_t smem_u32(const void* p) {
    uint32_t a;
    asm("{ .reg .u64 t; cvta.to.shared.u64 t, %1; cvt.u32.u64 %0, t; }" : "=r"(a) : "l"(p));
    return a;
}

#define LDSM_X4(r, addr) \
    asm volatile("ldmatrix.sync.aligned.m8n8.x4.shared.b16 {%0,%1,%2,%3}, [%4];" \
                 : "=r"((r)[0]), "=r"((r)[1]), "=r"((r)[2]), "=r"((r)[3]) : "r"(addr))
#define LDSM_X4_T(r, addr) \
    asm volatile("ldmatrix.sync.aligned.m8n8.x4.trans.shared.b16 {%0,%1,%2,%3}, [%4];" \
                 : "=r"((r)[0]), "=r"((r)[1]), "=r"((r)[2]), "=r"((r)[3]) : "r"(addr))
#define MMA16816(d, a, b) \
    asm volatile("mma.sync.aligned.m16n8k16.row.col.f32.bf16.bf16.f32 " \
                 "{%0,%1,%2,%3}, {%4,%5,%6,%7}, {%8,%9}, {%0,%1,%2,%3};" \
                 : "+f"((d)[0]), "+f"((d)[1]), "+f"((d)[2]), "+f"((d)[3]) \
                 : "r"((a)[0]), "r"((a)[1]), "r"((a)[2]), "r"((a)[3]), \
                   "r"((b)[0]), "r"((b)[1]))
#define CPASYNC16(s, g) \
    asm volatile("cp.async.cg.shared.global [%0], [%1], 16;" :: "r"(s), "l"(g))
#define CPCOMMIT() asm volatile("cp.async.commit_group;" ::: "memory")
#define CPWAIT1()  asm volatile("cp.async.wait_group 1;" ::: "memory")
#define CPWAIT0()  asm volatile("cp.async.wait_group 0;" ::: "memory")
#define SWZ(o) ((o) ^ (((o) >> 3) & 0x70))

static __device__ __forceinline__ void split2(float a, float b,
                                              __nv_bfloat162* hi, __nv_bfloat162* lo) {
    __nv_bfloat162 h, l;
    h.x = __float2bfloat16(a);
    h.y = __float2bfloat16(b);
    l.x = __float2bfloat16(a - __bfloat162float(h.x));
    l.y = __float2bfloat16(b - __bfloat162float(h.y));
    *hi = h; *lo = l;
}
static __device__ __forceinline__ uint32_t packsplit(float a, float b, uint32_t* lo) {
    __nv_bfloat162 h, l;
    split2(a, b, &h, &l);
    *lo = *(uint32_t*)&l;
    return *(uint32_t*)&h;
}

// ---------------- 2. xxx = tanh(z @ maa_w1), z computed inline ----------------
__global__ __launch_bounds__(160) void xxx_k(const float* __restrict__ x,
                                             const float* __restrict__ maa_x,
                                             const float* __restrict__ w1,
                                             float* __restrict__ xxx) {
    __shared__ float zs[4][1024];
    int t0 = blockIdx.x * 4;
    int tid = threadIdx.x;
    for (int i = tid; i < 4 * 1024; i += 160) {
        int r = i >> 10, c = i & 1023;
        int t = t0 + r;
        float xv = x[(size_t)t * 1024 + c];
        float prev = (t > 0) ? x[(size_t)(t - 1) * 1024 + c] : 0.f;
        float nxt  = (t < TTOK - 1) ? x[(size_t)(t + 1) * 1024 + c] : 0.f;
        float dxv = 0.5f * (prev + nxt) - xv;
        zs[r][c] = xv + dxv * maa_x[c];
    }
    __syncthreads();
    float acc[4] = {0.f, 0.f, 0.f, 0.f};
    for (int d = 0; d < 1024; d++) {
        float w = w1[d * 160 + tid];
        acc[0] += zs[0][d] * w;
        acc[1] += zs[1][d] * w;
        acc[2] += zs[2][d] * w;
        acc[3] += zs[3][d] * w;
    }
#pragma unroll
    for (int r = 0; r < 4; r++)
        xxx[(size_t)(t0 + r) * 160 + tid] = tanhf(acc[r]);
}

// ---------------- 3. mixer: dx recomputed inline ----------------
__global__ __launch_bounds__(256) void mix_k(const float* __restrict__ x,
                                             const float* __restrict__ xxx,
                                             const float* __restrict__ w2,
                                             const float* __restrict__ maa_w,
                                             const float* __restrict__ maa_k,
                                             const float* __restrict__ maa_v,
                                             const float* __restrict__ maa_r,
                                             const float* __restrict__ maa_g,
                                             float* __restrict__ xw,
                                             __nv_bfloat16* __restrict__ actHi,
                                             __nv_bfloat16* __restrict__ actLo) {
    __shared__ float xs[4][160];
    int t0 = blockIdx.x * 4;
    int tid = threadIdx.x;
    for (int i = tid; i < 640; i += 256) {
        int r = i / 160, c = i - r * 160;
        xs[r][c] = xxx[(size_t)(t0 + r) * 160 + c];
    }
    __syncthreads();
    int d = tid * 4;
    float4 xv[4], dxv[4];
#pragma unroll
    for (int r = 0; r < 4; r++) {
        int t = t0 + r;
        xv[r] = *(const float4*)(x + (size_t)t * 1024 + d);
        float4 pv = (t > 0) ? *(const float4*)(x + (size_t)(t - 1) * 1024 + d)
                            : make_float4(0.f, 0.f, 0.f, 0.f);
        float4 nv = (t < TTOK - 1) ? *(const float4*)(x + (size_t)(t + 1) * 1024 + d)
                                   : make_float4(0.f, 0.f, 0.f, 0.f);
        dxv[r].x = 0.5f * (pv.x + nv.x) - xv[r].x;
        dxv[r].y = 0.5f * (pv.y + nv.y) - xv[r].y;
        dxv[r].z = 0.5f * (pv.z + nv.z) - xv[r].z;
        dxv[r].w = 0.5f * (pv.w + nv.w) - xv[r].w;
    }
#pragma unroll
    for (int f = 0; f < 5; f++) {
        float4 acc[4];
#pragma unroll
        for (int r = 0; r < 4; r++) acc[r] = make_float4(0.f, 0.f, 0.f, 0.f);
        for (int mi = 0; mi < 32; mi++) {
            float4 w = *(const float4*)(w2 + (size_t)(f * 32 + mi) * 1024 + d);
#pragma unroll
            for (int r = 0; r < 4; r++) {
                float s = xs[r][f * 32 + mi];
                acc[r].x += s * w.x; acc[r].y += s * w.y;
                acc[r].z += s * w.z; acc[r].w += s * w.w;
            }
        }
        const float* maa = (f == 0) ? maa_w : (f == 1) ? maa_k : (f == 2) ? maa_v
                         : (f == 3) ? maa_r : maa_g;
        float4 mv = *(const float4*)(maa + d);
        int slot = (f == 3) ? 0 : (f == 1) ? 1 : (f == 2) ? 2 : 3;
#pragma unroll
        for (int r = 0; r < 4; r++) {
            float4 o;
            o.x = xv[r].x + dxv[r].x * (mv.x + acc[r].x);
            o.y = xv[r].y + dxv[r].y * (mv.y + acc[r].y);
            o.z = xv[r].z + dxv[r].z * (mv.z + acc[r].z);
            o.w = xv[r].w + dxv[r].w * (mv.w + acc[r].w);
            if (f == 0) {
                *(float4*)(xw + (size_t)(t0 + r) * 1024 + d) = o;
            } else {
                size_t ofs = (size_t)slot * TD + (size_t)(t0 + r) * 1024 + d;
                __nv_bfloat162 h0, l0, h1, l1;
                split2(o.x, o.y, &h0, &l0);
                split2(o.z, o.w, &h1, &l1);
                *(__nv_bfloat162*)(actHi + ofs)     = h0;
                *(__nv_bfloat162*)(actHi + ofs + 2) = h1;
                *(__nv_bfloat162*)(actLo + ofs)     = l0;
                *(__nv_bfloat162*)(actLo + ofs + 2) = l1;
            }
        }
    }
}

// ---------------- weight transpose + split ----------------
__global__ __launch_bounds__(256) void conv_wt_k(const float* __restrict__ W0,
                                                 const float* __restrict__ W1,
                                                 const float* __restrict__ W2,
                                                 const float* __restrict__ W3,
                                                 const float* __restrict__ W4,
                                                 __nv_bfloat16* __restrict__ hi,
                                                 __nv_bfloat16* __restrict__ lo) {
    __shared__ float tile[32][33];
    int z = blockIdx.z;
    const float* W = (z == 0) ? W0 : (z == 1) ? W1 : (z == 2) ? W2 : (z == 3) ? W3 : W4;
    int k0 = blockIdx.x * 32, n0 = blockIdx.y * 32;
    int tx = threadIdx.x & 31, ty = threadIdx.x >> 5;
#pragma unroll
    for (int i = 0; i < 32; i += 8)
        tile[ty + i][tx] = W[(size_t)(k0 + ty + i) * 1024 + n0 + tx];
    __syncthreads();
    size_t base = (size_t)z * 1048576;
#pragma unroll
    for (int i = 0; i < 32; i += 8) {
        float v = tile[tx][ty + i];
        size_t o = base + (size_t)(n0 + ty + i) * 1024 + k0 + tx;
        __nv_bfloat16 h = __float2bfloat16(v);
        hi[o] = h;
        lo[o] = __float2bfloat16(v - __bfloat162float(h));
    }
}

// ---------------- mma.sync split-bf16 GEMM: 128x64 CTA tile, occ 2 ----------------
__global__ __launch_bounds__(256, 2)
void gemm_mma_k(const __nv_bfloat16* __restrict__ aHi,
                const __nv_bfloat16* __restrict__ aLo,
                const __nv_bfloat16* __restrict__ bHi,
                const __nv_bfloat16* __restrict__ bLo,
                float* __restrict__ C, int siluZ,
                __nv_bfloat16* __restrict__ vHi,
                __nv_bfloat16* __restrict__ vLo, int vz) {
    extern __shared__ unsigned char smraw[];
    const int tid = threadIdx.x;
    const int z = blockIdx.z;
    const int bm = blockIdx.y * 128;
    const int bn = blockIdx.x * 64;
    const __nv_bfloat16* srcA[2] = { aHi + (size_t)z * TD, aLo + (size_t)z * TD };
    const __nv_bfloat16* srcB[2] = { bHi + (size_t)z * 1048576, bLo + (size_t)z * 1048576 };
    float* Cz = C + (size_t)z * TD;

    const uint32_t sbase = smem_u32(smraw);
    const int w = tid >> 5, lane = tid & 31;
    const int mw = w >> 1, nw = w & 1;

    float acc[2][4][4];
#pragma unroll
    for (int mt = 0; mt < 2; mt++)
#pragma unroll
        for (int nt = 0; nt < 4; nt++)
#pragma unroll
            for (int q = 0; q < 4; q++) acc[mt][nt][q] = 0.f;

    auto issue = [&](int c) {
        uint32_t stg = sbase + (c & 1) * 49152;
        int k0 = c * 64;
#pragma unroll 4
        for (int i = tid; i < 3072; i += 256) {
            const char* g;
            uint32_t dst;
            if (i < 2048) {
                int tile = i >> 10, idx = i & 1023;
                int row = idx >> 3, ch = idx & 7;
                g = (const char*)srcA[tile] + ((size_t)(bm + row) * 1024 + k0) * 2 + ch * 16;
                dst = stg + tile * 16384 + SWZ(row * 128 + ch * 16);
            } else {
                int j = i - 2048;
                int tile = j >> 9, idx = j & 511;
                int row = idx >> 3, ch = idx & 7;
                g = (const char*)srcB[tile] + ((size_t)(bn + row) * 1024 + k0) * 2 + ch * 16;
                dst = stg + 32768 + tile * 8192 + SWZ(row * 128 + ch * 16);
            }
            CPASYNC16(dst, g);
        }
        CPCOMMIT();
    };

    issue(0);
    issue(1);

    for (int c = 0; c < 16; c++) {
        if (c < 15) CPWAIT1(); else CPWAIT0();
        __syncthreads();
        uint32_t st = sbase + (c & 1) * 49152;
#pragma unroll
        for (int kk = 0; kk < 4; kk++) {
            int cb = kk * 2 + (lane >> 4);
            uint32_t ah[2][4], al[2][4];
#pragma unroll
            for (int mt = 0; mt < 2; mt++) {
                int r = mw * 32 + mt * 16 + (lane & 15);
                uint32_t o = SWZ(r * 128 + cb * 16);
                LDSM_X4(ah[mt], st + o);
                LDSM_X4(al[mt], st + 16384 + o);
            }
            uint32_t bh[4][2], bl[4][2];
#pragma unroll
            for (int p = 0; p < 2; p++) {
                int r = nw * 32 + p * 16 + (lane & 15);
                uint32_t o = SWZ(r * 128 + cb * 16);
                uint32_t t4[4];
                LDSM_X4(t4, st + 32768 + o);
                bh[2 * p][0] = t4[0]; bh[2 * p][1] = t4[2];
                bh[2 * p + 1][0] = t4[1]; bh[2 * p + 1][1] = t4[3];
                LDSM_X4(t4, st + 40960 + o);
                bl[2 * p][0] = t4[0]; bl[2 * p][1] = t4[2];
                bl[2 * p + 1][0] = t4[1]; bl[2 * p + 1][1] = t4[3];
            }
#pragma unroll
            for (int mt = 0; mt < 2; mt++)
#pragma unroll
                for (int nt = 0; nt < 4; nt++) {
                    MMA16816(acc[mt][nt], ah[mt], bh[nt]);
                    MMA16816(acc[mt][nt], ah[mt], bl[nt]);
                    MMA16816(acc[mt][nt], al[mt], bh[nt]);
                }
        }
        __syncthreads();
        if (c + 2 < 16) issue(c + 2);
    }

    bool silu = (z == siluZ);
    bool isv = (z == vz);
    int r0 = bm + mw * 32, c0 = bn + nw * 32;
#pragma unroll
    for (int mt = 0; mt < 2; mt++)
#pragma unroll
        for (int nt = 0; nt < 4; nt++) {
            float* d = acc[mt][nt];
            int row = r0 + mt * 16 + (lane >> 2);
            int col = c0 + nt * 8 + (lane & 3) * 2;
            if (isv) {
                __nv_bfloat162 h, l;
                split2(d[0], d[1], &h, &l);
                *(__nv_bfloat162*)(vHi + (size_t)row * 1024 + col) = h;
                *(__nv_bfloat162*)(vLo + (size_t)row * 1024 + col) = l;
                split2(d[2], d[3], &h, &l);
                *(__nv_bfloat162*)(vHi + (size_t)(row + 8) * 1024 + col) = h;
                *(__nv_bfloat162*)(vLo + (size_t)(row + 8) * 1024 + col) = l;
            } else {
                if (silu) {
#pragma unroll
                    for (int q = 0; q < 4; q++) d[q] = d[q] / (1.f + expf(-d[q]));
                }
                *(float2*)&Cz[(size_t)row * 1024 + col]       = make_float2(d[0], d[1]);
                *(float2*)&Cz[(size_t)(row + 8) * 1024 + col] = make_float2(d[2], d[3]);
            }
        }
}

// ---------------- 5. decay MLP stage 1 ----------------
__global__ __launch_bounds__(256) void decay1_k(const float* __restrict__ xw,
                                                const float* __restrict__ dw1,
                                                float* __restrict__ wmid) {
    __shared__ float xs[8][1024];
    __shared__ float part[4][64][8];
    int t0 = blockIdx.x * 8;
    int tid = threadIdx.x;
    for (int i = tid; i < 8 * 256; i += 256) {
        int r = i >> 8;
        int c4 = (i & 255) * 4;
        *(float4*)(&xs[r][c4]) = *(const float4*)(xw + (size_t)(t0 + r) * 1024 + c4);
    }
    __syncthreads();
    int n = tid & 63;
    int kq = tid >> 6;
    int kbase = kq * 256;
    float acc[8] = {0.f, 0.f, 0.f, 0.f, 0.f, 0.f, 0.f, 0.f};
    for (int dd = 0; dd < 256; dd++) {
        int d = kbase + dd;
        float w = dw1[d * 64 + n];
#pragma unroll
        for (int r = 0; r < 8; r++) acc[r] += xs[r][d] * w;
    }
#pragma unroll
    for (int r = 0; r < 8; r++) part[kq][n][r] = acc[r];
    __syncthreads();
    for (int i = tid; i < 512; i += 256) {
        int nn = i & 63, r = i >> 6;
        float s = part[0][nn][r] + part[1][nn][r] + part[2][nn][r] + part[3][nn][r];
        wmid[(size_t)(t0 + r) * 64 + nn] = tanhf(s);
    }
}

// ---------------- 6. decay MLP stage 2 ----------------
__global__ __launch_bounds__(256) void decay2_k(const float* __restrict__ wmid,
                                                const float* __restrict__ dw2,
                                                const float* __restrict__ td,
                                                float* __restrict__ w) {
    __shared__ float ws[4][64];
    int t0 = blockIdx.x * 4;
    int tid = threadIdx.x;
    {
        int r = tid >> 6, c = tid & 63;
        ws[r][c] = wmid[(size_t)(t0 + r) * 64 + c];
    }
    __syncthreads();
    int d = tid * 4;
    float4 tdv = *(const float4*)(td + d);
    float4 acc[4];
#pragma unroll
    for (int r = 0; r < 4; r++) acc[r] = tdv;
    for (int j = 0; j < 64; j++) {
        float4 wv = *(const float4*)(dw2 + (size_t)j * 1024 + d);
#pragma unroll
        for (int r = 0; r < 4; r++) {
            float s = ws[r][j];
            acc[r].x += s * wv.x; acc[r].y += s * wv.y;
            acc[r].z += s * wv.z; acc[r].w += s * wv.w;
        }
    }
#pragma unroll
    for (int r = 0; r < 4; r++)
        *(float4*)(w + (size_t)(t0 + r) * 1024 + d) = acc[r];
}

// ---------------- 7+8 fused: cumsum + premult -> bf16 hi/lo operands ----------------
// 32 blocks x 1024 thr; block owns 32 channels; thread = (segment j of 32 t) x (channel pair)
__global__ __launch_bounds__(1024) void cspm_k(const float* __restrict__ r,
                                               const float* __restrict__ k,
                                               const float* __restrict__ w,
                                               __nv_bfloat16* __restrict__ bfB) {
    __shared__ float seg[64][34];
    int tid = threadIdx.x;
    int cp = tid & 15;
    int j = tid >> 4;
    int d0 = blockIdx.x * 32 + cp * 2;
    int tb = j * 32;
    float s0 = 0.f, s1 = 0.f;
    for (int t = 0; t < 32; t++) {
        size_t o = (size_t)(tb + t) * 1024 + d0;
        s0 -= expf(w[o]);
        s1 -= expf(w[o + 1]);
    }
    seg[j][cp * 2] = s0;
    seg[j][cp * 2 + 1] = s1;
    __syncthreads();
    if (tid < 16) {
        float r0 = 0.f, r1 = 0.f;
        for (int jj = 0; jj < 64; jj++) {
            float a = seg[jj][cp * 2], b = seg[jj][cp * 2 + 1];
            seg[jj][cp * 2] = r0; seg[jj][cp * 2 + 1] = r1;
            r0 += a; r1 += b;
        }
    }
    __syncthreads();
    float pref0 = seg[32][cp * 2], pref1 = seg[32][cp * 2 + 1];  // cs_b mid (t=1024)
    size_t mo = (size_t)(TTOK / 2) * 1024 + d0;
    float whm0 = -expf(w[mo]), whm1 = -expf(w[mo + 1]);
    float csm0 = pref0 + whm0, csm1 = pref1 + whm1;               // cs mid
    float run0 = seg[j][cp * 2], run1 = seg[j][cp * 2 + 1];
    for (int t = 0; t < 32; t++) {
        size_t o = (size_t)(tb + t) * 1024 + d0;
        float wh0 = -expf(w[o]), wh1 = -expf(w[o + 1]);
        run0 += wh0; run1 += wh1;
        float csf0 = clip60(run0 - csm0), csf1 = clip60(run1 - csm1);
        float csb0 = clip60(run0 - wh0 - pref0), csb1 = clip60(run1 - wh1 - pref1);
        float rv0 = r[o], rv1 = r[o + 1];
        float kv0 = k[o], kv1 = k[o + 1];
        float v0[4], v1[4];
        v0[0] = rv0 * expf(csf0);  v1[0] = rv1 * expf(csf1);
        v0[1] = kv0 * expf(-csf0); v1[1] = kv1 * expf(-csf1);
        v0[2] = rv0 * expf(-csb0); v1[2] = rv1 * expf(-csb1);
        v0[3] = kv0 * expf(csb0);  v1[3] = kv1 * expf(csb1);
#pragma unroll
        for (int a = 0; a < 4; a++) {
            __nv_bfloat162 h, l;
            split2(v0[a], v1[a], &h, &l);
            *(__nv_bfloat162*)(bfB + (size_t)(2 * a) * TD + o) = h;
            *(__nv_bfloat162*)(bfB + (size_t)(2 * a + 1) * TD + o) = l;
        }
    }
}

// ---------------- 9. attention + fused groupnorm/gate epilogue ----------------
__global__ __launch_bounds__(256, 2) void attn_mma_k(const __nv_bfloat16* __restrict__ bfB,
                                                     const float* __restrict__ log_tau,
                                                     const float* __restrict__ g,
                                                     const float* __restrict__ ln_g,
                                                     const float* __restrict__ ln_b,
                                                     __nv_bfloat16* __restrict__ ygHi,
                                                     __nv_bfloat16* __restrict__ ygLo) {
    extern __shared__ unsigned char sm8[];
    __shared__ float redA[64], redS[64];
    const uint32_t sb = smem_u32(sm8);
    int h = blockIdx.y, it = blockIdx.x;
    int t0 = it * 64;
    int tid = threadIdx.x, w = tid >> 5, lane = tid & 31;
    int mw = w >> 1, sw = w & 1;
    size_t hb = (size_t)h * 64;
    float tau = expf(log_tau[h]);
    int grp = lane >> 2, qp = lane & 3;

    if (tid < 64) { redA[tid] = 0.f; redS[tid] = 0.f; }

    for (int i = tid; i < 2048; i += 256) {
        int tile = i >> 9, idx = i & 511;
        int row = idx >> 3, ch = idx & 7;
        int arr = (tile & 1) + (tile >> 1) * 4;
        const char* gp = (const char*)(bfB + (size_t)arr * TD
                        + (size_t)(t0 + row) * 1024 + hb) + ch * 16;
        CPASYNC16(sb + tile * 8192 + SWZ(row * 128 + ch * 16), gp);
    }
    CPCOMMIT();
    CPWAIT0();
    __syncthreads();

    float accY[8][4];
#pragma unroll
    for (int nt = 0; nt < 8; nt++)
#pragma unroll
        for (int q = 0; q < 4; q++) accY[nt][q] = 0.f;
    float sA[2] = {0.f, 0.f};
    float sS[2] = {0.f, 0.f};

    for (int jt = 0; jt < 32; jt++) {
        int s0 = jt * 64;
        bool needF = (jt <= it);
        bool needB = (jt >= it);
        for (int i = tid; i < 3072; i += 256) {
            int tile = i >> 9;
            if (tile < 2 && !needF) continue;
            if (tile >= 2 && tile < 4 && !needB) continue;
            int idx = i & 511, row = idx >> 3, ch = idx & 7;
            int arr = (tile < 4) ? (2 + (tile & 1) + (tile >> 1) * 4) : (tile + 4);
            const char* gp = (const char*)(bfB + (size_t)arr * TD
                            + (size_t)(s0 + row) * 1024 + hb) + ch * 16;
            CPASYNC16(sb + 32768 + tile * 8192 + SWZ(row * 128 + ch * 16), gp);
        }
        CPCOMMIT();
        CPWAIT0();
        __syncthreads();

        float accF[4][4], accB[4][4];
#pragma unroll
        for (int nt = 0; nt < 4; nt++)
#pragma unroll
            for (int q = 0; q < 4; q++) { accF[nt][q] = 0.f; accB[nt][q] = 0.f; }

#pragma unroll
        for (int ks = 0; ks < 4; ks++) {
            uint32_t abyte = ks * 32 + (lane >> 4) * 16;
            uint32_t oA = SWZ((mw * 16 + (lane & 15)) * 128 + abyte);
            if (needF) {
                uint32_t aH[4], aL[4];
                LDSM_X4(aH, sb + oA);
                LDSM_X4(aL, sb + 8192 + oA);
                uint32_t bh[4][2], bl[4][2];
#pragma unroll
                for (int p = 0; p < 2; p++) {
                    uint32_t o = SWZ((sw * 32 + p * 16 + (lane & 15)) * 128 + abyte);
                    uint32_t t4[4], u4[4];
                    LDSM_X4(t4, sb + 32768 + o);
                    LDSM_X4(u4, sb + 40960 + o);
                    bh[2 * p][0] = t4[0]; bh[2 * p][1] = t4[2];
                    bh[2 * p + 1][0] = t4[1]; bh[2 * p + 1][1] = t4[3];
                    bl[2 * p][0] = u4[0]; bl[2 * p][1] = u4[2];
                    bl[2 * p + 1][0] = u4[1]; bl[2 * p + 1][1] = u4[3];
                }
#pragma unroll
                for (int nt = 0; nt < 4; nt++) {
                    MMA16816(accF[nt], aH, bh[nt]);
                    MMA16816(accF[nt], aH, bl[nt]);
                    MMA16816(accF[nt], aL, bh[nt]);
                }
            }
            if (needB) {
                uint32_t aH[4], aL[4];
                LDSM_X4(aH, sb + 16384 + oA);
                LDSM_X4(aL, sb + 24576 + oA);
                uint32_t bh[4][2], bl[4][2];
#pragma unroll
                for (int p = 0; p < 2; p++) {
                    uint32_t o = SWZ((sw * 32 + p * 16 + (lane & 15)) * 128 + abyte);
                    uint32_t t4[4], u4[4];
                    LDSM_X4(t4, sb + 49152 + o);
                    LDSM_X4(u4, sb + 57344 + o);
                    bh[2 * p][0] = t4[0]; bh[2 * p][1] = t4[2];
                    bh[2 * p + 1][0] = t4[1]; bh[2 * p + 1][1] = t4[3];
                    bl[2 * p][0] = u4[0]; bl[2 * p][1] = u4[2];
                    bl[2 * p + 1][0] = u4[1]; bl[2 * p + 1][1] = u4[3];
                }
#pragma unroll
                for (int nt = 0; nt < 4; nt++) {
                    MMA16816(accB[nt], aH, bh[nt]);
                    MMA16816(accB[nt], aH, bl[nt]);
                    MMA16816(accB[nt], aL, bh[nt]);
                }
            }
        }

        uint32_t pH[2][4], pL[2][4];
#pragma unroll
        for (int nt = 0; nt < 4; nt++) {
            float ash[4];
#pragma unroll
            for (int q = 0; q < 4; q++) {
                int trow = t0 + mw * 16 + grp + (q >> 1) * 8;
                int scol = s0 + sw * 32 + nt * 8 + qp * 2 + (q & 1);
                float val;
                if (jt < it) val = accF[nt][q];
                else if (jt > it) val = accB[nt][q];
                else val = (scol > trow) ? accB[nt][q] : accF[nt][q];
                float a = fmaxf(val, 0.f);
                sA[q >> 1] += a;
                float as = (a > 0.f) ? __powf(a + 1e-12f, tau) : 0.f;
                sS[q >> 1] += as;
                ash[q] = as;
            }
            int kc = nt >> 1, half = nt & 1;
            pH[kc][half * 2]     = packsplit(ash[0], ash[1], &pL[kc][half * 2]);
            pH[kc][half * 2 + 1] = packsplit(ash[2], ash[3], &pL[kc][half * 2 + 1]);
        }

#pragma unroll
        for (int kc = 0; kc < 2; kc++) {
#pragma unroll
            for (int dblk = 0; dblk < 4; dblk++) {
                uint32_t ov = SWZ((sw * 32 + kc * 16 + (lane & 15)) * 128
                                  + dblk * 32 + (lane >> 4) * 16);
                uint32_t t4[4], u4[4];
                LDSM_X4_T(t4, sb + 65536 + ov);
                LDSM_X4_T(u4, sb + 73728 + ov);
                uint32_t bvh[2][2] = {{t4[0], t4[1]}, {t4[2], t4[3]}};
                uint32_t bvl[2][2] = {{u4[0], u4[1]}, {u4[2], u4[3]}};
#pragma unroll
                for (int x = 0; x < 2; x++) {
                    int nt = dblk * 2 + x;
                    MMA16816(accY[nt], pH[kc], bvh[x]);
                    MMA16816(accY[nt], pH[kc], bvl[x]);
                    MMA16816(accY[nt], pL[kc], bvh[x]);
                }
            }
        }
        __syncthreads();
    }

#pragma unroll
    for (int qh = 0; qh < 2; qh++) {
        float va = sA[qh], vs = sS[qh];
        va += __shfl_xor_sync(0xFFFFFFFFu, va, 1);
        va += __shfl_xor_sync(0xFFFFFFFFu, va, 2);
        vs += __shfl_xor_sync(0xFFFFFFFFu, vs, 1);
        vs += __shfl_xor_sync(0xFFFFFFFFu, vs, 2);
        if ((lane & 3) == 0) {
            int trow = mw * 16 + grp + qh * 8;
            atomicAdd(&redA[trow], va);
            atomicAdd(&redS[trow], vs);
        }
    }

    float* red = (float*)sm8;
    __syncthreads();
    if (sw == 1) {
#pragma unroll
        for (int nt = 0; nt < 8; nt++) {
            int r0 = mw * 16 + grp;
            int col = nt * 8 + qp * 2;
            *(float2*)&red[(r0)     * 64 + col] = make_float2(accY[nt][0], accY[nt][1]);
            *(float2*)&red[(r0 + 8) * 64 + col] = make_float2(accY[nt][2], accY[nt][3]);
        }
    }
    __syncthreads();
    if (sw == 0) {
        int r0 = mw * 16 + grp;
        int r1 = r0 + 8;
        float sc0 = fmaxf(redA[r0], 1e-12f) / fmaxf(redS[r0], 1e-12f);
        float sc1 = fmaxf(redA[r1], 1e-12f) / fmaxf(redS[r1], 1e-12f);
        float s0 = 0.f, q0 = 0.f, s1 = 0.f, q1 = 0.f;
#pragma unroll
        for (int nt = 0; nt < 8; nt++) {
            int col = nt * 8 + qp * 2;
            float2 o0 = *(float2*)&red[r0 * 64 + col];
            float2 o1 = *(float2*)&red[r1 * 64 + col];
            accY[nt][0] = (accY[nt][0] + o0.x) * sc0;
            accY[nt][1] = (accY[nt][1] + o0.y) * sc0;
            accY[nt][2] = (accY[nt][2] + o1.x) * sc1;
            accY[nt][3] = (accY[nt][3] + o1.y) * sc1;
            s0 += accY[nt][0] + accY[nt][1];
            q0 += accY[nt][0] * accY[nt][0] + accY[nt][1] * accY[nt][1];
            s1 += accY[nt][2] + accY[nt][3];
            q1 += accY[nt][2] * accY[nt][2] + accY[nt][3] * accY[nt][3];
        }
        s0 += __shfl_xor_sync(0xFFFFFFFFu, s0, 1);
        s0 += __shfl_xor_sync(0xFFFFFFFFu, s0, 2);
        q0 += __shfl_xor_sync(0xFFFFFFFFu, q0, 1);
        q0 += __shfl_xor_sync(0xFFFFFFFFu, q0, 2);
        s1 += __shfl_xor_sync(0xFFFFFFFFu, s1, 1);
        s1 += __shfl_xor_sync(0xFFFFFFFFu, s1, 2);
        q1 += __shfl_xor_sync(0xFFFFFFFFu, q1, 1);
        q1 += __shfl_xor_sync(0xFFFFFFFFu, q1, 2);
        float mu0 = s0 * (1.f / 64.f);
        float var0 = q0 * (1.f / 64.f) - mu0 * mu0;
        float inv0 = rsqrtf(var0 + 6.4e-4f);
        float mu1 = s1 * (1.f / 64.f);
        float var1 = q1 * (1.f / 64.f) - mu1 * mu1;
        float inv1 = rsqrtf(var1 + 6.4e-4f);
#pragma unroll
        for (int nt = 0; nt < 8; nt++) {
            int col = nt * 8 + qp * 2;
            int dch = (int)hb + col;
            float2 lg = *(const float2*)&ln_g[dch];
            float2 lb = *(const float2*)&ln_b[dch];
            float2 gg0 = *(const float2*)&g[(size_t)(t0 + r0) * 1024 + dch];
            float2 gg1 = *(const float2*)&g[(size_t)(t0 + r1) * 1024 + dch];
            float ox0 = ((accY[nt][0] - mu0) * inv0 * lg.x + lb.x) * gg0.x;
            float oy0 = ((accY[nt][1] - mu0) * inv0 * lg.y + lb.y) * gg0.y;
            float ox1 = ((accY[nt][2] - mu1) * inv1 * lg.x + lb.x) * gg1.x;
            float oy1 = ((accY[nt][3] - mu1) * inv1 * lg.y + lb.y) * gg1.y;
            __nv_bfloat162 hh, ll;
            split2(ox0, oy0, &hh, &ll);
            *(__nv_bfloat162*)(ygHi + (size_t)(t0 + r0) * 1024 + dch) = hh;
            *(__nv_bfloat162*)(ygLo + (size_t)(t0 + r0) * 1024 + dch) = ll;
            split2(ox1, oy1, &hh, &ll);
            *(__nv_bfloat162*)(ygHi + (size_t)(t0 + r1) * 1024 + dch) = hh;
            *(__nv_bfloat162*)(ygLo + (size_t)(t0 + r1) * 1024 + dch) = ll;
        }
    }
}

// ---------------- launch ----------------
extern "C" void kernel_launch(void* const* d_in, const int* in_sizes, int n_in,
                              void* d_out, int out_size) {
    const float* x          = (const float*)d_in[0];
    const float* maa_x      = (const float*)d_in[1];
    const float* maa_w      = (const float*)d_in[2];
    const float* maa_k      = (const float*)d_in[3];
    const float* maa_v      = (const float*)d_in[4];
    const float* maa_r      = (const float*)d_in[5];
    const float* maa_g      = (const float*)d_in[6];
    const float* maa_w1     = (const float*)d_in[7];
    const float* maa_w2     = (const float*)d_in[8];
    const float* time_decay = (const float*)d_in[9];
    const float* decay_w1   = (const float*)d_in[10];
    const float* decay_w2   = (const float*)d_in[11];
    const float* log_tau    = (const float*)d_in[12];
    const float* Wr         = (const float*)d_in[13];
    const float* Wk         = (const float*)d_in[14];
    const float* Wv         = (const float*)d_in[15];
    const float* Wg         = (const float*)d_in[16];
    const float* Wo         = (const float*)d_in[17];
    const float* ln_g       = (const float*)d_in[18];
    const float* ln_b       = (const float*)d_in[19];

    float* S = nullptr;
    cudaGetSymbolAddress((void**)&S, g_scratch);
    float* xwb   = S + OFF_XW;
    float* rkvg  = S + OFF_RKVG;
    float* wb    = S + OFF_W;
    float* xxxb  = S + OFF_XXX;
    float* wmidb = S + OFF_WMID;
    __nv_bfloat16* actHi = (__nv_bfloat16*)(S + OFF_ACTHI);
    __nv_bfloat16* actLo = (__nv_bfloat16*)(S + OFF_ACTLO);
    __nv_bfloat16* wtHi  = (__nv_bfloat16*)(S + OFF_WTHI);
    __nv_bfloat16* wtLo  = (__nv_bfloat16*)(S + OFF_WTLO);
    __nv_bfloat16* ygHi  = (__nv_bfloat16*)(S + OFF_YGHI);
    __nv_bfloat16* ygLo  = (__nv_bfloat16*)(S + OFF_YGLO);
    __nv_bfloat16* bfB   = (__nv_bfloat16*)(S + OFF_BF);

    int gemm_smem = 98304;
    cudaFuncSetAttribute(gemm_mma_k, cudaFuncAttributeMaxDynamicSharedMemorySize, gemm_smem);
    int attn_smem = 81920;
    cudaFuncSetAttribute(attn_mma_k, cudaFuncAttributeMaxDynamicSharedMemorySize, attn_smem);

    xxx_k<<<TTOK / 4, 160>>>(x, maa_x, maa_w1, xxxb);
    mix_k<<<TTOK / 4, 256>>>(x, xxxb, maa_w2,
                             maa_w, maa_k, maa_v, maa_r, maa_g, xwb, actHi, actLo);
    {
        dim3 grid(32, 32, 5);
        conv_wt_k<<<grid, 256>>>(Wr, Wk, Wv, Wg, Wo, wtHi, wtLo);
    }
    {
        dim3 grid(16, 16, 4);
        gemm_mma_k<<<grid, 256, gemm_smem>>>(actHi, actLo, wtHi, wtLo, rkvg, 3,
                                             bfB + (size_t)8 * TD, bfB + (size_t)9 * TD, 2);
    }
    decay1_k<<<TTOK / 8, 256>>>(xwb, decay_w1, wmidb);
    decay2_k<<<TTOK / 4, 256>>>(wmidb, decay_w2, time_decay, wb);
    cspm_k<<<DDIM / 32, 1024>>>(rkvg, rkvg + (size_t)TD, wb, bfB);
    {
        dim3 grid(32, 16);
        attn_mma_k<<<grid, 256, attn_smem>>>(bfB, log_tau, rkvg + (size_t)3 * TD,
                                             ln_g, ln_b, ygHi, ygLo);
    }
    {
        dim3 grid(16, 16, 1);
        gemm_mma_k<<<grid, 256, gemm_smem>>>(ygHi, ygLo, wtHi + (size_t)4 * 1048576,
                                             wtLo + (size_t)4 * 1048576,
                                             (float*)d_out, -1, nullptr, nullptr, -1);
    }
}

// round 12
// speedup vs baseline: 1.0281x; 1.0281x over previous
#include <cuda_runtime.h>
#include <cuda_bf16.h>
#include <math.h>
#include <stdint.h>

#define TTOK 2048
#define DDIM 1024
#define TD (TTOK*DDIM)

// ---------------- scratch (static device memory; no allocations) ----------------
__device__ float g_scratch[68157440];

#define OFF_XW    ((size_t)2*TD)
#define OFF_RKVG  ((size_t)7*TD)
#define OFF_W     ((size_t)11*TD)
#define OFF_CS    ((size_t)12*TD)
#define OFF_XXX   ((size_t)19*TD)
#define OFF_WMID  (OFF_XXX + (size_t)TTOK*160)
#define OFF_ACTHI ((size_t)20*TD)
#define OFF_ACTLO ((size_t)22*TD)
#define OFF_WTHI  ((size_t)24*TD)
#define OFF_WTLO  (OFF_WTHI + (size_t)2621440)
#define OFF_YGHI  (OFF_WTLO + (size_t)2621440)
#define OFF_YGLO  (OFF_YGHI + (size_t)(TD/2))
#define OFF_BF    (OFF_YGLO + (size_t)(TD/2))

static __device__ __forceinline__ float clip60(float x) {
    return fminf(fmaxf(x, -60.f), 60.f);
}
static __device__ __forceinline__ uint32_t smem_u32(const void* p) {
    uint32_t a;
    asm("{ .reg .u64 t; cvta.to.shared.u64 t, %1; cvt.u32.u64 %0, t; }" : "=r"(a) : "l"(p));
    return a;
}

#define LDSM_X4(r, addr) \
    asm volatile("ldmatrix.sync.aligned.m8n8.x4.shared.b16 {%0,%1,%2,%3}, [%4];" \
                 : "=r"((r)[0]), "=r"((r)[1]), "=r"((r)[2]), "=r"((r)[3]) : "r"(addr))
#define LDSM_X4_T(r, addr) \
    asm volatile("ldmatrix.sync.aligned.m8n8.x4.trans.shared.b16 {%0,%1,%2,%3}, [%4];" \
                 : "=r"((r)[0]), "=r"((r)[1]), "=r"((r)[2]), "=r"((r)[3]) : "r"(addr))
#define MMA16816(d, a, b) \
    asm volatile("mma.sync.aligned.m16n8k16.row.col.f32.bf16.bf16.f32 " \
                 "{%0,%1,%2,%3}, {%4,%5,%6,%7}, {%8,%9}, {%0,%1,%2,%3};" \
                 : "+f"((d)[0]), "+f"((d)[1]), "+f"((d)[2]), "+f"((d)[3]) \
                 : "r"((a)[0]), "r"((a)[1]), "r"((a)[2]), "r"((a)[3]), \
                   "r"((b)[0]), "r"((b)[1]))
#define CPASYNC16(s, g) \
    asm volatile("cp.async.cg.shared.global [%0], [%1], 16;" :: "r"(s), "l"(g))
#define CPCOMMIT() asm volatile("cp.async.commit_group;" ::: "memory")
#define CPWAIT1()  asm volatile("cp.async.wait_group 1;" ::: "memory")
#define CPWAIT0()  asm volatile("cp.async.wait_group 0;" ::: "memory")
#define SWZ(o) ((o) ^ (((o) >> 3) & 0x70))

static __device__ __forceinline__ void split2(float a, float b,
                                              __nv_bfloat162* hi, __nv_bfloat162* lo) {
    __nv_bfloat162 h, l;
    h.x = __float2bfloat16(a);
    h.y = __float2bfloat16(b);
    l.x = __float2bfloat16(a - __bfloat162float(h.x));
    l.y = __float2bfloat16(b - __bfloat162float(h.y));
    *hi = h; *lo = l;
}
static __device__ __forceinline__ uint32_t packsplit(float a, float b, uint32_t* lo) {
    __nv_bfloat162 h, l;
    split2(a, b, &h, &l);
    *lo = *(uint32_t*)&l;
    return *(uint32_t*)&h;
}

// ---------------- 2. xxx = tanh(z @ maa_w1), z computed inline ----------------
__global__ __launch_bounds__(160) void xxx_k(const float* __restrict__ x,
                                             const float* __restrict__ maa_x,
                                             const float* __restrict__ w1,
                                             float* __restrict__ xxx) {
    __shared__ float zs[4][1024];
    int t0 = blockIdx.x * 4;
    int tid = threadIdx.x;
    for (int i = tid; i < 4 * 1024; i += 160) {
        int r = i >> 10, c = i & 1023;
        int t = t0 + r;
        float xv = x[(size_t)t * 1024 + c];
        float prev = (t > 0) ? x[(size_t)(t - 1) * 1024 + c] : 0.f;
        float nxt  = (t < TTOK - 1) ? x[(size_t)(t + 1) * 1024 + c] : 0.f;
        float dxv = 0.5f * (prev + nxt) - xv;
        zs[r][c] = xv + dxv * maa_x[c];
    }
    __syncthreads();
    float acc[4] = {0.f, 0.f, 0.f, 0.f};
    for (int d = 0; d < 1024; d++) {
        float w = w1[d * 160 + tid];
        acc[0] += zs[0][d] * w;
        acc[1] += zs[1][d] * w;
        acc[2] += zs[2][d] * w;
        acc[3] += zs[3][d] * w;
    }
#pragma unroll
    for (int r = 0; r < 4; r++)
        xxx[(size_t)(t0 + r) * 160 + tid] = tanhf(acc[r]);
}

// ---------------- 3. mixer: dx recomputed inline ----------------
__global__ __launch_bounds__(256) void mix_k(const float* __restrict__ x,
                                             const float* __restrict__ xxx,
                                             const float* __restrict__ w2,
                                             const float* __restrict__ maa_w,
                                             const float* __restrict__ maa_k,
                                             const float* __restrict__ maa_v,
                                             const float* __restrict__ maa_r,
                                             const float* __restrict__ maa_g,
                                             float* __restrict__ xw,
                                             __nv_bfloat16* __restrict__ actHi,
                                             __nv_bfloat16* __restrict__ actLo) {
    __shared__ float xs[4][160];
    int t0 = blockIdx.x * 4;
    int tid = threadIdx.x;
    for (int i = tid; i < 640; i += 256) {
        int r = i / 160, c = i - r * 160;
        xs[r][c] = xxx[(size_t)(t0 + r) * 160 + c];
    }
    __syncthreads();
    int d = tid * 4;
    float4 xv[4], dxv[4];
#pragma unroll
    for (int r = 0; r < 4; r++) {
        int t = t0 + r;
        xv[r] = *(const float4*)(x + (size_t)t * 1024 + d);
        float4 pv = (t > 0) ? *(const float4*)(x + (size_t)(t - 1) * 1024 + d)
                            : make_float4(0.f, 0.f, 0.f, 0.f);
        float4 nv = (t < TTOK - 1) ? *(const float4*)(x + (size_t)(t + 1) * 1024 + d)
                                   : make_float4(0.f, 0.f, 0.f, 0.f);
        dxv[r].x = 0.5f * (pv.x + nv.x) - xv[r].x;
        dxv[r].y = 0.5f * (pv.y + nv.y) - xv[r].y;
        dxv[r].z = 0.5f * (pv.z + nv.z) - xv[r].z;
        dxv[r].w = 0.5f * (pv.w + nv.w) - xv[r].w;
    }
#pragma unroll
    for (int f = 0; f < 5; f++) {
        float4 acc[4];
#pragma unroll
        for (int r = 0; r < 4; r++) acc[r] = make_float4(0.f, 0.f, 0.f, 0.f);
        for (int mi = 0; mi < 32; mi++) {
            float4 w = *(const float4*)(w2 + (size_t)(f * 32 + mi) * 1024 + d);
#pragma unroll
            for (int r = 0; r < 4; r++) {
                float s = xs[r][f * 32 + mi];
                acc[r].x += s * w.x; acc[r].y += s * w.y;
                acc[r].z += s * w.z; acc[r].w += s * w.w;
            }
        }
        const float* maa = (f == 0) ? maa_w : (f == 1) ? maa_k : (f == 2) ? maa_v
                         : (f == 3) ? maa_r : maa_g;
        float4 mv = *(const float4*)(maa + d);
        int slot = (f == 3) ? 0 : (f == 1) ? 1 : (f == 2) ? 2 : 3;
#pragma unroll
        for (int r = 0; r < 4; r++) {
            float4 o;
            o.x = xv[r].x + dxv[r].x * (mv.x + acc[r].x);
            o.y = xv[r].y + dxv[r].y * (mv.y + acc[r].y);
            o.z = xv[r].z + dxv[r].z * (mv.z + acc[r].z);
            o.w = xv[r].w + dxv[r].w * (mv.w + acc[r].w);
            if (f == 0) {
                *(float4*)(xw + (size_t)(t0 + r) * 1024 + d) = o;
            } else {
                size_t ofs = (size_t)slot * TD + (size_t)(t0 + r) * 1024 + d;
                __nv_bfloat162 h0, l0, h1, l1;
                split2(o.x, o.y, &h0, &l0);
                split2(o.z, o.w, &h1, &l1);
                *(__nv_bfloat162*)(actHi + ofs)     = h0;
                *(__nv_bfloat162*)(actHi + ofs + 2) = h1;
                *(__nv_bfloat162*)(actLo + ofs)     = l0;
                *(__nv_bfloat162*)(actLo + ofs + 2) = l1;
            }
        }
    }
}

// ---------------- weight transpose + split ----------------
__global__ __launch_bounds__(256) void conv_wt_k(const float* __restrict__ W0,
                                                 const float* __restrict__ W1,
                                                 const float* __restrict__ W2,
                                                 const float* __restrict__ W3,
                                                 const float* __restrict__ W4,
                                                 __nv_bfloat16* __restrict__ hi,
                                                 __nv_bfloat16* __restrict__ lo) {
    __shared__ float tile[32][33];
    int z = blockIdx.z;
    const float* W = (z == 0) ? W0 : (z == 1) ? W1 : (z == 2) ? W2 : (z == 3) ? W3 : W4;
    int k0 = blockIdx.x * 32, n0 = blockIdx.y * 32;
    int tx = threadIdx.x & 31, ty = threadIdx.x >> 5;
#pragma unroll
    for (int i = 0; i < 32; i += 8)
        tile[ty + i][tx] = W[(size_t)(k0 + ty + i) * 1024 + n0 + tx];
    __syncthreads();
    size_t base = (size_t)z * 1048576;
#pragma unroll
    for (int i = 0; i < 32; i += 8) {
        float v = tile[tx][ty + i];
        size_t o = base + (size_t)(n0 + ty + i) * 1024 + k0 + tx;
        __nv_bfloat16 h = __float2bfloat16(v);
        hi[o] = h;
        lo[o] = __float2bfloat16(v - __bfloat162float(h));
    }
}

// ---------------- mma.sync split-bf16 GEMM: 128x64 CTA tile, occ 2 ----------------
__global__ __launch_bounds__(256, 2)
void gemm_mma_k(const __nv_bfloat16* __restrict__ aHi,
                const __nv_bfloat16* __restrict__ aLo,
                const __nv_bfloat16* __restrict__ bHi,
                const __nv_bfloat16* __restrict__ bLo,
                float* __restrict__ C, int siluZ,
                __nv_bfloat16* __restrict__ vHi,
                __nv_bfloat16* __restrict__ vLo, int vz) {
    extern __shared__ unsigned char smraw[];
    const int tid = threadIdx.x;
    const int z = blockIdx.z;
    const int bm = blockIdx.y * 128;
    const int bn = blockIdx.x * 64;
    const __nv_bfloat16* srcA[2] = { aHi + (size_t)z * TD, aLo + (size_t)z * TD };
    const __nv_bfloat16* srcB[2] = { bHi + (size_t)z * 1048576, bLo + (size_t)z * 1048576 };
    float* Cz = C + (size_t)z * TD;

    const uint32_t sbase = smem_u32(smraw);
    const int w = tid >> 5, lane = tid & 31;
    const int mw = w >> 1, nw = w & 1;

    float acc[2][4][4];
#pragma unroll
    for (int mt = 0; mt < 2; mt++)
#pragma unroll
        for (int nt = 0; nt < 4; nt++)
#pragma unroll
            for (int q = 0; q < 4; q++) acc[mt][nt][q] = 0.f;

    auto issue = [&](int c) {
        uint32_t stg = sbase + (c & 1) * 49152;
        int k0 = c * 64;
#pragma unroll 4
        for (int i = tid; i < 3072; i += 256) {
            const char* g;
            uint32_t dst;
            if (i < 2048) {
                int tile = i >> 10, idx = i & 1023;
                int row = idx >> 3, ch = idx & 7;
                g = (const char*)srcA[tile] + ((size_t)(bm + row) * 1024 + k0) * 2 + ch * 16;
                dst = stg + tile * 16384 + SWZ(row * 128 + ch * 16);
            } else {
                int j = i - 2048;
                int tile = j >> 9, idx = j & 511;
                int row = idx >> 3, ch = idx & 7;
                g = (const char*)srcB[tile] + ((size_t)(bn + row) * 1024 + k0) * 2 + ch * 16;
                dst = stg + 32768 + tile * 8192 + SWZ(row * 128 + ch * 16);
            }
            CPASYNC16(dst, g);
        }
        CPCOMMIT();
    };

    issue(0);
    issue(1);

    for (int c = 0; c < 16; c++) {
        if (c < 15) CPWAIT1(); else CPWAIT0();
        __syncthreads();
        uint32_t st = sbase + (c & 1) * 49152;
#pragma unroll
        for (int kk = 0; kk < 4; kk++) {
            int cb = kk * 2 + (lane >> 4);
            uint32_t ah[2][4], al[2][4];
#pragma unroll
            for (int mt = 0; mt < 2; mt++) {
                int r = mw * 32 + mt * 16 + (lane & 15);
                uint32_t o = SWZ(r * 128 + cb * 16);
                LDSM_X4(ah[mt], st + o);
                LDSM_X4(al[mt], st + 16384 + o);
            }
            uint32_t bh[4][2], bl[4][2];
#pragma unroll
            for (int p = 0; p < 2; p++) {
                int r = nw * 32 + p * 16 + (lane & 15);
                uint32_t o = SWZ(r * 128 + cb * 16);
                uint32_t t4[4];
                LDSM_X4(t4, st + 32768 + o);
                bh[2 * p][0] = t4[0]; bh[2 * p][1] = t4[2];
                bh[2 * p + 1][0] = t4[1]; bh[2 * p + 1][1] = t4[3];
                LDSM_X4(t4, st + 40960 + o);
                bl[2 * p][0] = t4[0]; bl[2 * p][1] = t4[2];
                bl[2 * p + 1][0] = t4[1]; bl[2 * p + 1][1] = t4[3];
            }
#pragma unroll
            for (int mt = 0; mt < 2; mt++)
#pragma unroll
                for (int nt = 0; nt < 4; nt++) {
                    MMA16816(acc[mt][nt], ah[mt], bh[nt]);
                    MMA16816(acc[mt][nt], ah[mt], bl[nt]);
                    MMA16816(acc[mt][nt], al[mt], bh[nt]);
                }
        }
        __syncthreads();
        if (c + 2 < 16) issue(c + 2);
    }

    bool silu = (z == siluZ);
    bool isv = (z == vz);
    int r0 = bm + mw * 32, c0 = bn + nw * 32;
#pragma unroll
    for (int mt = 0; mt < 2; mt++)
#pragma unroll
        for (int nt = 0; nt < 4; nt++) {
            float* d = acc[mt][nt];
            int row = r0 + mt * 16 + (lane >> 2);
            int col = c0 + nt * 8 + (lane & 3) * 2;
            if (isv) {
                __nv_bfloat162 h, l;
                split2(d[0], d[1], &h, &l);
                *(__nv_bfloat162*)(vHi + (size_t)row * 1024 + col) = h;
                *(__nv_bfloat162*)(vLo + (size_t)row * 1024 + col) = l;
                split2(d[2], d[3], &h, &l);
                *(__nv_bfloat162*)(vHi + (size_t)(row + 8) * 1024 + col) = h;
                *(__nv_bfloat162*)(vLo + (size_t)(row + 8) * 1024 + col) = l;
            } else {
                if (silu) {
#pragma unroll
                    for (int q = 0; q < 4; q++) d[q] = d[q] / (1.f + expf(-d[q]));
                }
                *(float2*)&Cz[(size_t)row * 1024 + col]       = make_float2(d[0], d[1]);
                *(float2*)&Cz[(size_t)(row + 8) * 1024 + col] = make_float2(d[2], d[3]);
            }
        }
}

// ---------------- 5. decay MLP stage 1 ----------------
__global__ __launch_bounds__(256) void decay1_k(const float* __restrict__ xw,
                                                const float* __restrict__ dw1,
                                                float* __restrict__ wmid) {
    __shared__ float xs[8][1024];
    __shared__ float part[4][64][8];
    int t0 = blockIdx.x * 8;
    int tid = threadIdx.x;
    for (int i = tid; i < 8 * 256; i += 256) {
        int r = i >> 8;
        int c4 = (i & 255) * 4;
        *(float4*)(&xs[r][c4]) = *(const float4*)(xw + (size_t)(t0 + r) * 1024 + c4);
    }
    __syncthreads();
    int n = tid & 63;
    int kq = tid >> 6;
    int kbase = kq * 256;
    float acc[8] = {0.f, 0.f, 0.f, 0.f, 0.f, 0.f, 0.f, 0.f};
    for (int dd = 0; dd < 256; dd++) {
        int d = kbase + dd;
        float w = dw1[d * 64 + n];
#pragma unroll
        for (int r = 0; r < 8; r++) acc[r] += xs[r][d] * w;
    }
#pragma unroll
    for (int r = 0; r < 8; r++) part[kq][n][r] = acc[r];
    __syncthreads();
    for (int i = tid; i < 512; i += 256) {
        int nn = i & 63, r = i >> 6;
        float s = part[0][nn][r] + part[1][nn][r] + part[2][nn][r] + part[3][nn][r];
        wmid[(size_t)(t0 + r) * 64 + nn] = tanhf(s);
    }
}

// ---------------- 6. decay MLP stage 2 ----------------
__global__ __launch_bounds__(256) void decay2_k(const float* __restrict__ wmid,
                                                const float* __restrict__ dw2,
                                                const float* __restrict__ td,
                                                float* __restrict__ w) {
    __shared__ float ws[4][64];
    int t0 = blockIdx.x * 4;
    int tid = threadIdx.x;
    {
        int r = tid >> 6, c = tid & 63;
        ws[r][c] = wmid[(size_t)(t0 + r) * 64 + c];
    }
    __syncthreads();
    int d = tid * 4;
    float4 tdv = *(const float4*)(td + d);
    float4 acc[4];
#pragma unroll
    for (int r = 0; r < 4; r++) acc[r] = tdv;
    for (int j = 0; j < 64; j++) {
        float4 wv = *(const float4*)(dw2 + (size_t)j * 1024 + d);
#pragma unroll
        for (int r = 0; r < 4; r++) {
            float s = ws[r][j];
            acc[r].x += s * wv.x; acc[r].y += s * wv.y;
            acc[r].z += s * wv.z; acc[r].w += s * wv.w;
        }
    }
#pragma unroll
    for (int r = 0; r < 4; r++)
        *(float4*)(w + (size_t)(t0 + r) * 1024 + d) = acc[r];
}

// ---------------- 7. per-channel cumsum (scan only) ----------------
__global__ __launch_bounds__(1024) void cumsum_k(const float* __restrict__ w,
                                                 float* __restrict__ cs) {
    __shared__ float seg[32][33];
    int c = threadIdx.x & 31;
    int j = threadIdx.x >> 5;
    int d = blockIdx.x * 32 + c;
    int tb = j * 64;
    float s = 0.f;
    for (int t = 0; t < 64; t++)
        s -= expf(w[(size_t)(tb + t) * 1024 + d]);
    seg[j][c] = s;
    __syncthreads();
    if (j == 0) {
        float run = 0.f;
        for (int jj = 0; jj < 32; jj++) {
            float tmp = seg[jj][c];
            seg[jj][c] = run;
            run += tmp;
        }
    }
    __syncthreads();
    float run = seg[j][c];
    for (int t = 0; t < 64; t++) {
        run -= expf(w[(size_t)(tb + t) * 1024 + d]);
        cs[(size_t)(tb + t) * 1024 + d] = run;
    }
}

// ---------------- 8. premult -> bf16 hi/lo operands (wide grid) ----------------
__global__ __launch_bounds__(256) void premult_bf_k(const float* __restrict__ r,
                                                    const float* __restrict__ k,
                                                    const float* __restrict__ w,
                                                    const float* __restrict__ cs,
                                                    __nv_bfloat16* __restrict__ bfB) {
    int idx = blockIdx.x * 256 + threadIdx.x;
    if (idx >= TD) return;
    int d = idx & 1023;
    size_t midoff = (size_t)(TTOK / 2) * 1024 + d;
    float csv = cs[idx];
    float csm = cs[midoff];
    float wh   = -expf(w[idx]);
    float whm  = -expf(w[midoff]);
    float csf = clip60(csv - csm);
    float csb = clip60((csv - wh) - (csm - whm));
    float rv = r[idx], kv = k[idx];
    float vals[4];
    vals[0] = rv * expf(csf);
    vals[1] = kv * expf(-csf);
    vals[2] = rv * expf(-csb);
    vals[3] = kv * expf(csb);
#pragma unroll
    for (int j = 0; j < 4; j++) {
        __nv_bfloat16 h = __float2bfloat16(vals[j]);
        bfB[(size_t)(2 * j) * TD + idx] = h;
        bfB[(size_t)(2 * j + 1) * TD + idx] = __float2bfloat16(vals[j] - __bfloat162float(h));
    }
}

// ---------------- 9. attention + fused groupnorm/gate epilogue ----------------
__global__ __launch_bounds__(256, 2) void attn_mma_k(const __nv_bfloat16* __restrict__ bfB,
                                                     const float* __restrict__ log_tau,
                                                     const float* __restrict__ g,
                                                     const float* __restrict__ ln_g,
                                                     const float* __restrict__ ln_b,
                                                     __nv_bfloat16* __restrict__ ygHi,
                                                     __nv_bfloat16* __restrict__ ygLo) {
    extern __shared__ unsigned char sm8[];
    __shared__ float redA[64], redS[64];
    const uint32_t sb = smem_u32(sm8);
    int h = blockIdx.y, it = blockIdx.x;
    int t0 = it * 64;
    int tid = threadIdx.x, w = tid >> 5, lane = tid & 31;
    int mw = w >> 1, sw = w & 1;
    size_t hb = (size_t)h * 64;
    float tau = expf(log_tau[h]);
    int grp = lane >> 2, qp = lane & 3;

    if (tid < 64) { redA[tid] = 0.f; redS[tid] = 0.f; }

    for (int i = tid; i < 2048; i += 256) {
        int tile = i >> 9, idx = i & 511;
        int row = idx >> 3, ch = idx & 7;
        int arr = (tile & 1) + (tile >> 1) * 4;
        const char* gp = (const char*)(bfB + (size_t)arr * TD
                        + (size_t)(t0 + row) * 1024 + hb) + ch * 16;
        CPASYNC16(sb + tile * 8192 + SWZ(row * 128 + ch * 16), gp);
    }
    CPCOMMIT();
    CPWAIT0();
    __syncthreads();

    float accY[8][4];
#pragma unroll
    for (int nt = 0; nt < 8; nt++)
#pragma unroll
        for (int q = 0; q < 4; q++) accY[nt][q] = 0.f;
    float sA[2] = {0.f, 0.f};
    float sS[2] = {0.f, 0.f};

    for (int jt = 0; jt < 32; jt++) {
        int s0 = jt * 64;
        bool needF = (jt <= it);
        bool needB = (jt >= it);
        for (int i = tid; i < 3072; i += 256) {
            int tile = i >> 9;
            if (tile < 2 && !needF) continue;
            if (tile >= 2 && tile < 4 && !needB) continue;
            int idx = i & 511, row = idx >> 3, ch = idx & 7;
            int arr = (tile < 4) ? (2 + (tile & 1) + (tile >> 1) * 4) : (tile + 4);
            const char* gp = (const char*)(bfB + (size_t)arr * TD
                            + (size_t)(s0 + row) * 1024 + hb) + ch * 16;
            CPASYNC16(sb + 32768 + tile * 8192 + SWZ(row * 128 + ch * 16), gp);
        }
        CPCOMMIT();
        CPWAIT0();
        __syncthreads();

        float accF[4][4], accB[4][4];
#pragma unroll
        for (int nt = 0; nt < 4; nt++)
#pragma unroll
            for (int q = 0; q < 4; q++) { accF[nt][q] = 0.f; accB[nt][q] = 0.f; }

#pragma unroll
        for (int ks = 0; ks < 4; ks++) {
            uint32_t abyte = ks * 32 + (lane >> 4) * 16;
            uint32_t oA = SWZ((mw * 16 + (lane & 15)) * 128 + abyte);
            if (needF) {
                uint32_t aH[4], aL[4];
                LDSM_X4(aH, sb + oA);
                LDSM_X4(aL, sb + 8192 + oA);
                uint32_t bh[4][2], bl[4][2];
#pragma unroll
                for (int p = 0; p < 2; p++) {
                    uint32_t o = SWZ((sw * 32 + p * 16 + (lane & 15)) * 128 + abyte);
                    uint32_t t4[4], u4[4];
                    LDSM_X4(t4, sb + 32768 + o);
                    LDSM_X4(u4, sb + 40960 + o);
                    bh[2 * p][0] = t4[0]; bh[2 * p][1] = t4[2];
                    bh[2 * p + 1][0] = t4[1]; bh[2 * p + 1][1] = t4[3];
                    bl[2 * p][0] = u4[0]; bl[2 * p][1] = u4[2];
                    bl[2 * p + 1][0] = u4[1]; bl[2 * p + 1][1] = u4[3];
                }
#pragma unroll
                for (int nt = 0; nt < 4; nt++) {
                    MMA16816(accF[nt], aH, bh[nt]);
                    MMA16816(accF[nt], aH, bl[nt]);
                    MMA16816(accF[nt], aL, bh[nt]);
                }
            }
            if (needB) {
                uint32_t aH[4], aL[4];
                LDSM_X4(aH, sb + 16384 + oA);
                LDSM_X4(aL, sb + 24576 + oA);
                uint32_t bh[4][2], bl[4][2];
#pragma unroll
                for (int p = 0; p < 2; p++) {
                    uint32_t o = SWZ((sw * 32 + p * 16 + (lane & 15)) * 128 + abyte);
                    uint32_t t4[4], u4[4];
                    LDSM_X4(t4, sb + 49152 + o);
                    LDSM_X4(u4, sb + 57344 + o);
                    bh[2 * p][0] = t4[0]; bh[2 * p][1] = t4[2];
                    bh[2 * p + 1][0] = t4[1]; bh[2 * p + 1][1] = t4[3];
                    bl[2 * p][0] = u4[0]; bl[2 * p][1] = u4[2];
                    bl[2 * p + 1][0] = u4[1]; bl[2 * p + 1][1] = u4[3];
                }
#pragma unroll
                for (int nt = 0; nt < 4; nt++) {
                    MMA16816(accB[nt], aH, bh[nt]);
                    MMA16816(accB[nt], aH, bl[nt]);
                    MMA16816(accB[nt], aL, bh[nt]);
                }
            }
        }

        uint32_t pH[2][4], pL[2][4];
#pragma unroll
        for (int nt = 0; nt < 4; nt++) {
            float ash[4];
#pragma unroll
            for (int q = 0; q < 4; q++) {
                int trow = t0 + mw * 16 + grp + (q >> 1) * 8;
                int scol = s0 + sw * 32 + nt * 8 + qp * 2 + (q & 1);
                float val;
                if (jt < it) val = accF[nt][q];
                else if (jt > it) val = accB[nt][q];
                else val = (scol > trow) ? accB[nt][q] : accF[nt][q];
                float a = fmaxf(val, 0.f);
                sA[q >> 1] += a;
                float as = (a > 0.f) ? __powf(a + 1e-12f, tau) : 0.f;
                sS[q >> 1] += as;
                ash[q] = as;
            }
            int kc = nt >> 1, half = nt & 1;
            pH[kc][half * 2]     = packsplit(ash[0], ash[1], &pL[kc][half * 2]);
            pH[kc][half * 2 + 1] = packsplit(ash[2], ash[3], &pL[kc][half * 2 + 1]);
        }

#pragma unroll
        for (int kc = 0; kc < 2; kc++) {
#pragma unroll
            for (int dblk = 0; dblk < 4; dblk++) {
                uint32_t ov = SWZ((sw * 32 + kc * 16 + (lane & 15)) * 128
                                  + dblk * 32 + (lane >> 4) * 16);
                uint32_t t4[4], u4[4];
                LDSM_X4_T(t4, sb + 65536 + ov);
                LDSM_X4_T(u4, sb + 73728 + ov);
                uint32_t bvh[2][2] = {{t4[0], t4[1]}, {t4[2], t4[3]}};
                uint32_t bvl[2][2] = {{u4[0], u4[1]}, {u4[2], u4[3]}};
#pragma unroll
                for (int x = 0; x < 2; x++) {
                    int nt = dblk * 2 + x;
                    MMA16816(accY[nt], pH[kc], bvh[x]);
                    MMA16816(accY[nt], pH[kc], bvl[x]);
                    MMA16816(accY[nt], pL[kc], bvh[x]);
                }
            }
        }
        __syncthreads();
    }

#pragma unroll
    for (int qh = 0; qh < 2; qh++) {
        float va = sA[qh], vs = sS[qh];
        va += __shfl_xor_sync(0xFFFFFFFFu, va, 1);
        va += __shfl_xor_sync(0xFFFFFFFFu, va, 2);
        vs += __shfl_xor_sync(0xFFFFFFFFu, vs, 1);
        vs += __shfl_xor_sync(0xFFFFFFFFu, vs, 2);
        if ((lane & 3) == 0) {
            int trow = mw * 16 + grp + qh * 8;
            atomicAdd(&redA[trow], va);
            atomicAdd(&redS[trow], vs);
        }
    }

    float* red = (float*)sm8;
    __syncthreads();
    if (sw == 1) {
#pragma unroll
        for (int nt = 0; nt < 8; nt++) {
            int r0 = mw * 16 + grp;
            int col = nt * 8 + qp * 2;
            *(float2*)&red[(r0)     * 64 + col] = make_float2(accY[nt][0], accY[nt][1]);
            *(float2*)&red[(r0 + 8) * 64 + col] = make_float2(accY[nt][2], accY[nt][3]);
        }
    }
    __syncthreads();
    if (sw == 0) {
        int r0 = mw * 16 + grp;
        int r1 = r0 + 8;
        float sc0 = fmaxf(redA[r0], 1e-12f) / fmaxf(redS[r0], 1e-12f);
        float sc1 = fmaxf(redA[r1], 1e-12f) / fmaxf(redS[r1], 1e-12f);
        float s0 = 0.f, q0 = 0.f, s1 = 0.f, q1 = 0.f;
#pragma unroll
        for (int nt = 0; nt < 8; nt++) {
            int col = nt * 8 + qp * 2;
            float2 o0 = *(float2*)&red[r0 * 64 + col];
            float2 o1 = *(float2*)&red[r1 * 64 + col];
            accY[nt][0] = (accY[nt][0] + o0.x) * sc0;
            accY[nt][1] = (accY[nt][1] + o0.y) * sc0;
            accY[nt][2] = (accY[nt][2] + o1.x) * sc1;
            accY[nt][3] = (accY[nt][3] + o1.y) * sc1;
            s0 += accY[nt][0] + accY[nt][1];
            q0 += accY[nt][0] * accY[nt][0] + accY[nt][1] * accY[nt][1];
            s1 += accY[nt][2] + accY[nt][3];
            q1 += accY[nt][2] * accY[nt][2] + accY[nt][3] * accY[nt][3];
        }
        s0 += __shfl_xor_sync(0xFFFFFFFFu, s0, 1);
        s0 += __shfl_xor_sync(0xFFFFFFFFu, s0, 2);
        q0 += __shfl_xor_sync(0xFFFFFFFFu, q0, 1);
        q0 += __shfl_xor_sync(0xFFFFFFFFu, q0, 2);
        s1 += __shfl_xor_sync(0xFFFFFFFFu, s1, 1);
        s1 += __shfl_xor_sync(0xFFFFFFFFu, s1, 2);
        q1 += __shfl_xor_sync(0xFFFFFFFFu, q1, 1);
        q1 += __shfl_xor_sync(0xFFFFFFFFu, q1, 2);
        float mu0 = s0 * (1.f / 64.f);
        float var0 = q0 * (1.f / 64.f) - mu0 * mu0;
        float inv0 = rsqrtf(var0 + 6.4e-4f);
        float mu1 = s1 * (1.f / 64.f);
        float var1 = q1 * (1.f / 64.f) - mu1 * mu1;
        float inv1 = rsqrtf(var1 + 6.4e-4f);
#pragma unroll
        for (int nt = 0; nt < 8; nt++) {
            int col = nt * 8 + qp * 2;
            int dch = (int)hb + col;
            float2 lg = *(const float2*)&ln_g[dch];
            float2 lb = *(const float2*)&ln_b[dch];
            float2 gg0 = *(const float2*)&g[(size_t)(t0 + r0) * 1024 + dch];
            float2 gg1 = *(const float2*)&g[(size_t)(t0 + r1) * 1024 + dch];
            float ox0 = ((accY[nt][0] - mu0) * inv0 * lg.x + lb.x) * gg0.x;
            float oy0 = ((accY[nt][1] - mu0) * inv0 * lg.y + lb.y) * gg0.y;
            float ox1 = ((accY[nt][2] - mu1) * inv1 * lg.x + lb.x) * gg1.x;
            float oy1 = ((accY[nt][3] - mu1) * inv1 * lg.y + lb.y) * gg1.y;
            __nv_bfloat162 hh, ll;
            split2(ox0, oy0, &hh, &ll);
            *(__nv_bfloat162*)(ygHi + (size_t)(t0 + r0) * 1024 + dch) = hh;
            *(__nv_bfloat162*)(ygLo + (size_t)(t0 + r0) * 1024 + dch) = ll;
            split2(ox1, oy1, &hh, &ll);
            *(__nv_bfloat162*)(ygHi + (size_t)(t0 + r1) * 1024 + dch) = hh;
            *(__nv_bfloat162*)(ygLo + (size_t)(t0 + r1) * 1024 + dch) = ll;
        }
    }
}

// ---------------- launch ----------------
extern "C" void kernel_launch(void* const* d_in, const int* in_sizes, int n_in,
                              void* d_out, int out_size) {
    const float* x          = (const float*)d_in[0];
    const float* maa_x      = (const float*)d_in[1];
    const float* maa_w      = (const float*)d_in[2];
    const float* maa_k      = (const float*)d_in[3];
    const float* maa_v      = (const float*)d_in[4];
    const float* maa_r      = (const float*)d_in[5];
    const float* maa_g      = (const float*)d_in[6];
    const float* maa_w1     = (const float*)d_in[7];
    const float* maa_w2     = (const float*)d_in[8];
    const float* time_decay = (const float*)d_in[9];
    const float* decay_w1   = (const float*)d_in[10];
    const float* decay_w2   = (const float*)d_in[11];
    const float* log_tau    = (const float*)d_in[12];
    const float* Wr         = (const float*)d_in[13];
    const float* Wk         = (const float*)d_in[14];
    const float* Wv         = (const float*)d_in[15];
    const float* Wg         = (const float*)d_in[16];
    const float* Wo         = (const float*)d_in[17];
    const float* ln_g       = (const float*)d_in[18];
    const float* ln_b       = (const float*)d_in[19];

    float* S = nullptr;
    cudaGetSymbolAddress((void**)&S, g_scratch);
    float* xwb   = S + OFF_XW;
    float* rkvg  = S + OFF_RKVG;
    float* wb    = S + OFF_W;
    float* csb   = S + OFF_CS;
    float* xxxb  = S + OFF_XXX;
    float* wmidb = S + OFF_WMID;
    __nv_bfloat16* actHi = (__nv_bfloat16*)(S + OFF_ACTHI);
    __nv_bfloat16* actLo = (__nv_bfloat16*)(S + OFF_ACTLO);
    __nv_bfloat16* wtHi  = (__nv_bfloat16*)(S + OFF_WTHI);
    __nv_bfloat16* wtLo  = (__nv_bfloat16*)(S + OFF_WTLO);
    __nv_bfloat16* ygHi  = (__nv_bfloat16*)(S + OFF_YGHI);
    __nv_bfloat16* ygLo  = (__nv_bfloat16*)(S + OFF_YGLO);
    __nv_bfloat16* bfB   = (__nv_bfloat16*)(S + OFF_BF);

    int gemm_smem = 98304;
    cudaFuncSetAttribute(gemm_mma_k, cudaFuncAttributeMaxDynamicSharedMemorySize, gemm_smem);
    int attn_smem = 81920;
    cudaFuncSetAttribute(attn_mma_k, cudaFuncAttributeMaxDynamicSharedMemorySize, attn_smem);

    xxx_k<<<TTOK / 4, 160>>>(x, maa_x, maa_w1, xxxb);
    mix_k<<<TTOK / 4, 256>>>(x, xxxb, maa_w2,
                             maa_w, maa_k, maa_v, maa_r, maa_g, xwb, actHi, actLo);
    {
        dim3 grid(32, 32, 5);
        conv_wt_k<<<grid, 256>>>(Wr, Wk, Wv, Wg, Wo, wtHi, wtLo);
    }
    {
        dim3 grid(16, 16, 4);
        gemm_mma_k<<<grid, 256, gemm_smem>>>(actHi, actLo, wtHi, wtLo, rkvg, 3,
                                             bfB + (size_t)8 * TD, bfB + (size_t)9 * TD, 2);
    }
    decay1_k<<<TTOK / 8, 256>>>(xwb, decay_w1, wmidb);
    decay2_k<<<TTOK / 4, 256>>>(wmidb, decay_w2, time_decay, wb);
    cumsum_k<<<DDIM / 32, 1024>>>(wb, csb);
    premult_bf_k<<<(TD + 255) / 256, 256>>>(rkvg, rkvg + (size_t)TD, wb, csb, bfB);
    {
        dim3 grid(32, 16);
        attn_mma_k<<<grid, 256, attn_smem>>>(bfB, log_tau, rkvg + (size_t)3 * TD,
                                             ln_g, ln_b, ygHi, ygLo);
    }
    {
        dim3 grid(16, 16, 1);
        gemm_mma_k<<<grid, 256, gemm_smem>>>(ygHi, ygLo, wtHi + (size_t)4 * 1048576,
                                             wtLo + (size_t)4 * 1048576,
                                             (float*)d_out, -1, nullptr, nullptr, -1);
    }
}

// round 13
// speedup vs baseline: 1.0953x; 1.0654x over previous
#include <cuda_runtime.h>
#include <cuda_bf16.h>
#include <math.h>
#include <stdint.h>

#define TTOK 2048
#define DDIM 1024
#define TD (TTOK*DDIM)

// ---------------- scratch (static device memory; no allocations) ----------------
__device__ float g_scratch[68157440];

#define OFF_Z     ((size_t)1*TD)
#define OFF_XW    ((size_t)2*TD)
#define OFF_RKVG  ((size_t)7*TD)
#define OFF_W     ((size_t)11*TD)
#define OFF_CS    ((size_t)12*TD)
#define OFF_XXX   ((size_t)19*TD)
#define OFF_WMID  (OFF_XXX + (size_t)TTOK*160)
#define OFF_ACTHI ((size_t)20*TD)
#define OFF_ACTLO ((size_t)22*TD)
#define OFF_WTHI  ((size_t)24*TD)
#define OFF_WTLO  (OFF_WTHI + (size_t)2621440)
#define OFF_YGHI  (OFF_WTLO + (size_t)2621440)
#define OFF_YGLO  (OFF_YGHI + (size_t)(TD/2))
#define OFF_BF    (OFF_YGLO + (size_t)(TD/2))

static __device__ __forceinline__ float clip60(float x) {
    return fminf(fmaxf(x, -60.f), 60.f);
}
static __device__ __forceinline__ uint32_t smem_u32(const void* p) {
    uint32_t a;
    asm("{ .reg .u64 t; cvta.to.shared.u64 t, %1; cvt.u32.u64 %0, t; }" : "=r"(a) : "l"(p));
    return a;
}

#define LDSM_X4(r, addr) \
    asm volatile("ldmatrix.sync.aligned.m8n8.x4.shared.b16 {%0,%1,%2,%3}, [%4];" \
                 : "=r"((r)[0]), "=r"((r)[1]), "=r"((r)[2]), "=r"((r)[3]) : "r"(addr))
#define LDSM_X4_T(r, addr) \
    asm volatile("ldmatrix.sync.aligned.m8n8.x4.trans.shared.b16 {%0,%1,%2,%3}, [%4];" \
                 : "=r"((r)[0]), "=r"((r)[1]), "=r"((r)[2]), "=r"((r)[3]) : "r"(addr))
#define MMA16816(d, a, b) \
    asm volatile("mma.sync.aligned.m16n8k16.row.col.f32.bf16.bf16.f32 " \
                 "{%0,%1,%2,%3}, {%4,%5,%6,%7}, {%8,%9}, {%0,%1,%2,%3};" \
                 : "+f"((d)[0]), "+f"((d)[1]), "+f"((d)[2]), "+f"((d)[3]) \
                 : "r"((a)[0]), "r"((a)[1]), "r"((a)[2]), "r"((a)[3]), \
                   "r"((b)[0]), "r"((b)[1]))
#define CPASYNC16(s, g) \
    asm volatile("cp.async.cg.shared.global [%0], [%1], 16;" :: "r"(s), "l"(g))
#define CPCOMMIT() asm volatile("cp.async.commit_group;" ::: "memory")
#define CPWAIT1()  asm volatile("cp.async.wait_group 1;" ::: "memory")
#define CPWAIT0()  asm volatile("cp.async.wait_group 0;" ::: "memory")
#define SWZ(o) ((o) ^ (((o) >> 3) & 0x70))

static __device__ __forceinline__ void split2(float a, float b,
                                              __nv_bfloat162* hi, __nv_bfloat162* lo) {
    __nv_bfloat162 h, l;
    h.x = __float2bfloat16(a);
    h.y = __float2bfloat16(b);
    l.x = __float2bfloat16(a - __bfloat162float(h.x));
    l.y = __float2bfloat16(b - __bfloat162float(h.y));
    *hi = h; *lo = l;
}
static __device__ __forceinline__ uint32_t packsplit(float a, float b, uint32_t* lo) {
    __nv_bfloat162 h, l;
    split2(a, b, &h, &l);
    *lo = *(uint32_t*)&l;
    return *(uint32_t*)&h;
}

// ---------------- 1. token shift -> z only ----------------
__global__ __launch_bounds__(256) void prep_k(const float* __restrict__ x,
                                              const float* __restrict__ maa_x,
                                              float* __restrict__ z) {
    int idx = blockIdx.x * 256 + threadIdx.x;
    if (idx >= TD) return;
    int t = idx >> 10;
    int d = idx & 1023;
    float xv = x[idx];
    float prev = (t > 0) ? x[idx - 1024] : 0.f;
    float nxt  = (t < TTOK - 1) ? x[idx + 1024] : 0.f;
    float dxv = 0.5f * (prev + nxt) - xv;
    z[idx] = xv + dxv * maa_x[d];
}

// ---------------- 2. xxx = tanh(z @ maa_w1): 320 thr, split-K ----------------
__global__ __launch_bounds__(320) void xxx_k(const float* __restrict__ z,
                                             const float* __restrict__ w1,
                                             float* __restrict__ xxx) {
    __shared__ float zs[4][1024];
    __shared__ float part[2][4][160];
    int t0 = blockIdx.x * 4;
    int tid = threadIdx.x;
    for (int i = tid; i < 1024; i += 320) {
        int r = i >> 8, c4 = (i & 255) * 4;
        *(float4*)&zs[r][c4] = *(const float4*)(z + (size_t)(t0 + r) * 1024 + c4);
    }
    __syncthreads();
    int out = (tid < 160) ? tid : (tid - 160);
    int kh = (tid < 160) ? 0 : 1;
    int kb = kh * 512;
    float acc[4] = {0.f, 0.f, 0.f, 0.f};
    for (int dd = 0; dd < 512; dd++) {
        int d = kb + dd;
        float w = w1[d * 160 + out];
        acc[0] += zs[0][d] * w;
        acc[1] += zs[1][d] * w;
        acc[2] += zs[2][d] * w;
        acc[3] += zs[3][d] * w;
    }
#pragma unroll
    for (int r = 0; r < 4; r++) part[kh][r][out] = acc[r];
    __syncthreads();
    if (tid < 160) {
#pragma unroll
        for (int r = 0; r < 4; r++)
            xxx[(size_t)(t0 + r) * 160 + tid] =
                tanhf(part[0][r][tid] + part[1][r][tid]);
    }
}

// ---------------- 3. mixer: dx recomputed inline ----------------
__global__ __launch_bounds__(256) void mix_k(const float* __restrict__ x,
                                             const float* __restrict__ xxx,
                                             const float* __restrict__ w2,
                                             const float* __restrict__ maa_w,
                                             const float* __restrict__ maa_k,
                                             const float* __restrict__ maa_v,
                                             const float* __restrict__ maa_r,
                                             const float* __restrict__ maa_g,
                                             float* __restrict__ xw,
                                             __nv_bfloat16* __restrict__ actHi,
                                             __nv_bfloat16* __restrict__ actLo) {
    __shared__ float xs[4][160];
    int t0 = blockIdx.x * 4;
    int tid = threadIdx.x;
    for (int i = tid; i < 640; i += 256) {
        int r = i / 160, c = i - r * 160;
        xs[r][c] = xxx[(size_t)(t0 + r) * 160 + c];
    }
    __syncthreads();
    int d = tid * 4;
    float4 xv[4], dxv[4];
#pragma unroll
    for (int r = 0; r < 4; r++) {
        int t = t0 + r;
        xv[r] = *(const float4*)(x + (size_t)t * 1024 + d);
        float4 pv = (t > 0) ? *(const float4*)(x + (size_t)(t - 1) * 1024 + d)
                            : make_float4(0.f, 0.f, 0.f, 0.f);
        float4 nv = (t < TTOK - 1) ? *(const float4*)(x + (size_t)(t + 1) * 1024 + d)
                                   : make_float4(0.f, 0.f, 0.f, 0.f);
        dxv[r].x = 0.5f * (pv.x + nv.x) - xv[r].x;
        dxv[r].y = 0.5f * (pv.y + nv.y) - xv[r].y;
        dxv[r].z = 0.5f * (pv.z + nv.z) - xv[r].z;
        dxv[r].w = 0.5f * (pv.w + nv.w) - xv[r].w;
    }
#pragma unroll
    for (int f = 0; f < 5; f++) {
        float4 acc[4];
#pragma unroll
        for (int r = 0; r < 4; r++) acc[r] = make_float4(0.f, 0.f, 0.f, 0.f);
        for (int mi = 0; mi < 32; mi++) {
            float4 w = *(const float4*)(w2 + (size_t)(f * 32 + mi) * 1024 + d);
#pragma unroll
            for (int r = 0; r < 4; r++) {
                float s = xs[r][f * 32 + mi];
                acc[r].x += s * w.x; acc[r].y += s * w.y;
                acc[r].z += s * w.z; acc[r].w += s * w.w;
            }
        }
        const float* maa = (f == 0) ? maa_w : (f == 1) ? maa_k : (f == 2) ? maa_v
                         : (f == 3) ? maa_r : maa_g;
        float4 mv = *(const float4*)(maa + d);
        int slot = (f == 3) ? 0 : (f == 1) ? 1 : (f == 2) ? 2 : 3;
#pragma unroll
        for (int r = 0; r < 4; r++) {
            float4 o;
            o.x = xv[r].x + dxv[r].x * (mv.x + acc[r].x);
            o.y = xv[r].y + dxv[r].y * (mv.y + acc[r].y);
            o.z = xv[r].z + dxv[r].z * (mv.z + acc[r].z);
            o.w = xv[r].w + dxv[r].w * (mv.w + acc[r].w);
            if (f == 0) {
                *(float4*)(xw + (size_t)(t0 + r) * 1024 + d) = o;
            } else {
                size_t ofs = (size_t)slot * TD + (size_t)(t0 + r) * 1024 + d;
                __nv_bfloat162 h0, l0, h1, l1;
                split2(o.x, o.y, &h0, &l0);
                split2(o.z, o.w, &h1, &l1);
                *(__nv_bfloat162*)(actHi + ofs)     = h0;
                *(__nv_bfloat162*)(actHi + ofs + 2) = h1;
                *(__nv_bfloat162*)(actLo + ofs)     = l0;
                *(__nv_bfloat162*)(actLo + ofs + 2) = l1;
            }
        }
    }
}

// ---------------- weight transpose + split ----------------
__global__ __launch_bounds__(256) void conv_wt_k(const float* __restrict__ W0,
                                                 const float* __restrict__ W1,
                                                 const float* __restrict__ W2,
                                                 const float* __restrict__ W3,
                                                 const float* __restrict__ W4,
                                                 __nv_bfloat16* __restrict__ hi,
                                                 __nv_bfloat16* __restrict__ lo) {
    __shared__ float tile[32][33];
    int z = blockIdx.z;
    const float* W = (z == 0) ? W0 : (z == 1) ? W1 : (z == 2) ? W2 : (z == 3) ? W3 : W4;
    int k0 = blockIdx.x * 32, n0 = blockIdx.y * 32;
    int tx = threadIdx.x & 31, ty = threadIdx.x >> 5;
#pragma unroll
    for (int i = 0; i < 32; i += 8)
        tile[ty + i][tx] = W[(size_t)(k0 + ty + i) * 1024 + n0 + tx];
    __syncthreads();
    size_t base = (size_t)z * 1048576;
#pragma unroll
    for (int i = 0; i < 32; i += 8) {
        float v = tile[tx][ty + i];
        size_t o = base + (size_t)(n0 + ty + i) * 1024 + k0 + tx;
        __nv_bfloat16 h = __float2bfloat16(v);
        hi[o] = h;
        lo[o] = __float2bfloat16(v - __bfloat162float(h));
    }
}

// ---------------- mma.sync split-bf16 GEMM: 128x64 CTA tile, occ 2 ----------------
__global__ __launch_bounds__(256, 2)
void gemm_mma_k(const __nv_bfloat16* __restrict__ aHi,
                const __nv_bfloat16* __restrict__ aLo,
                const __nv_bfloat16* __restrict__ bHi,
                const __nv_bfloat16* __restrict__ bLo,
                float* __restrict__ C, int siluZ,
                __nv_bfloat16* __restrict__ vHi,
                __nv_bfloat16* __restrict__ vLo, int vz) {
    extern __shared__ unsigned char smraw[];
    const int tid = threadIdx.x;
    const int z = blockIdx.z;
    const int bm = blockIdx.y * 128;
    const int bn = blockIdx.x * 64;
    const __nv_bfloat16* srcA[2] = { aHi + (size_t)z * TD, aLo + (size_t)z * TD };
    const __nv_bfloat16* srcB[2] = { bHi + (size_t)z * 1048576, bLo + (size_t)z * 1048576 };
    float* Cz = C + (size_t)z * TD;

    const uint32_t sbase = smem_u32(smraw);
    const int w = tid >> 5, lane = tid & 31;
    const int mw = w >> 1, nw = w & 1;

    float acc[2][4][4];
#pragma unroll
    for (int mt = 0; mt < 2; mt++)
#pragma unroll
        for (int nt = 0; nt < 4; nt++)
#pragma unroll
            for (int q = 0; q < 4; q++) acc[mt][nt][q] = 0.f;

    auto issue = [&](int c) {
        uint32_t stg = sbase + (c & 1) * 49152;
        int k0 = c * 64;
#pragma unroll 4
        for (int i = tid; i < 3072; i += 256) {
            const char* g;
            uint32_t dst;
            if (i < 2048) {
                int tile = i >> 10, idx = i & 1023;
                int row = idx >> 3, ch = idx & 7;
                g = (const char*)srcA[tile] + ((size_t)(bm + row) * 1024 + k0) * 2 + ch * 16;
                dst = stg + tile * 16384 + SWZ(row * 128 + ch * 16);
            } else {
                int j = i - 2048;
                int tile = j >> 9, idx = j & 511;
                int row = idx >> 3, ch = idx & 7;
                g = (const char*)srcB[tile] + ((size_t)(bn + row) * 1024 + k0) * 2 + ch * 16;
                dst = stg + 32768 + tile * 8192 + SWZ(row * 128 + ch * 16);
            }
            CPASYNC16(dst, g);
        }
        CPCOMMIT();
    };

    issue(0);
    issue(1);

    for (int c = 0; c < 16; c++) {
        if (c < 15) CPWAIT1(); else CPWAIT0();
        __syncthreads();
        uint32_t st = sbase + (c & 1) * 49152;
#pragma unroll
        for (int kk = 0; kk < 4; kk++) {
            int cb = kk * 2 + (lane >> 4);
            uint32_t ah[2][4], al[2][4];
#pragma unroll
            for (int mt = 0; mt < 2; mt++) {
                int r = mw * 32 + mt * 16 + (lane & 15);
                uint32_t o = SWZ(r * 128 + cb * 16);
                LDSM_X4(ah[mt], st + o);
                LDSM_X4(al[mt], st + 16384 + o);
            }
            uint32_t bh[4][2], bl[4][2];
#pragma unroll
            for (int p = 0; p < 2; p++) {
                int r = nw * 32 + p * 16 + (lane & 15);
                uint32_t o = SWZ(r * 128 + cb * 16);
                uint32_t t4[4];
                LDSM_X4(t4, st + 32768 + o);
                bh[2 * p][0] = t4[0]; bh[2 * p][1] = t4[2];
                bh[2 * p + 1][0] = t4[1]; bh[2 * p + 1][1] = t4[3];
                LDSM_X4(t4, st + 40960 + o);
                bl[2 * p][0] = t4[0]; bl[2 * p][1] = t4[2];
                bl[2 * p + 1][0] = t4[1]; bl[2 * p + 1][1] = t4[3];
            }
#pragma unroll
            for (int mt = 0; mt < 2; mt++)
#pragma unroll
                for (int nt = 0; nt < 4; nt++) {
                    MMA16816(acc[mt][nt], ah[mt], bh[nt]);
                    MMA16816(acc[mt][nt], ah[mt], bl[nt]);
                    MMA16816(acc[mt][nt], al[mt], bh[nt]);
                }
        }
        __syncthreads();
        if (c + 2 < 16) issue(c + 2);
    }

    bool silu = (z == siluZ);
    bool isv = (z == vz);
    int r0 = bm + mw * 32, c0 = bn + nw * 32;
#pragma unroll
    for (int mt = 0; mt < 2; mt++)
#pragma unroll
        for (int nt = 0; nt < 4; nt++) {
            float* d = acc[mt][nt];
            int row = r0 + mt * 16 + (lane >> 2);
            int col = c0 + nt * 8 + (lane & 3) * 2;
            if (isv) {
                __nv_bfloat162 h, l;
                split2(d[0], d[1], &h, &l);
                *(__nv_bfloat162*)(vHi + (size_t)row * 1024 + col) = h;
                *(__nv_bfloat162*)(vLo + (size_t)row * 1024 + col) = l;
                split2(d[2], d[3], &h, &l);
                *(__nv_bfloat162*)(vHi + (size_t)(row + 8) * 1024 + col) = h;
                *(__nv_bfloat162*)(vLo + (size_t)(row + 8) * 1024 + col) = l;
            } else {
                if (silu) {
#pragma unroll
                    for (int q = 0; q < 4; q++) d[q] = d[q] / (1.f + expf(-d[q]));
                }
                *(float2*)&Cz[(size_t)row * 1024 + col]       = make_float2(d[0], d[1]);
                *(float2*)&Cz[(size_t)(row + 8) * 1024 + col] = make_float2(d[2], d[3]);
            }
        }
}

// ---------------- 5. decay MLP stage 1 ----------------
__global__ __launch_bounds__(256) void decay1_k(const float* __restrict__ xw,
                                                const float* __restrict__ dw1,
                                                float* __restrict__ wmid) {
    __shared__ float xs[8][1024];
    __shared__ float part[4][64][8];
    int t0 = blockIdx.x * 8;
    int tid = threadIdx.x;
    for (int i = tid; i < 8 * 256; i += 256) {
        int r = i >> 8;
        int c4 = (i & 255) * 4;
        *(float4*)(&xs[r][c4]) = *(const float4*)(xw + (size_t)(t0 + r) * 1024 + c4);
    }
    __syncthreads();
    int n = tid & 63;
    int kq = tid >> 6;
    int kbase = kq * 256;
    float acc[8] = {0.f, 0.f, 0.f, 0.f, 0.f, 0.f, 0.f, 0.f};
    for (int dd = 0; dd < 256; dd++) {
        int d = kbase + dd;
        float w = dw1[d * 64 + n];
#pragma unroll
        for (int r = 0; r < 8; r++) acc[r] += xs[r][d] * w;
    }
#pragma unroll
    for (int r = 0; r < 8; r++) part[kq][n][r] = acc[r];
    __syncthreads();
    for (int i = tid; i < 512; i += 256) {
        int nn = i & 63, r = i >> 6;
        float s = part[0][nn][r] + part[1][nn][r] + part[2][nn][r] + part[3][nn][r];
        wmid[(size_t)(t0 + r) * 64 + nn] = tanhf(s);
    }
}

// ---------------- 6. decay MLP stage 2 ----------------
__global__ __launch_bounds__(256) void decay2_k(const float* __restrict__ wmid,
                                                const float* __restrict__ dw2,
                                                const float* __restrict__ td,
                                                float* __restrict__ w) {
    __shared__ float ws[4][64];
    int t0 = blockIdx.x * 4;
    int tid = threadIdx.x;
    {
        int r = tid >> 6, c = tid & 63;
        ws[r][c] = wmid[(size_t)(t0 + r) * 64 + c];
    }
    __syncthreads();
    int d = tid * 4;
    float4 tdv = *(const float4*)(td + d);
    float4 acc[4];
#pragma unroll
    for (int r = 0; r < 4; r++) acc[r] = tdv;
    for (int j = 0; j < 64; j++) {
        float4 wv = *(const float4*)(dw2 + (size_t)j * 1024 + d);
#pragma unroll
        for (int r = 0; r < 4; r++) {
            float s = ws[r][j];
            acc[r].x += s * wv.x; acc[r].y += s * wv.y;
            acc[r].z += s * wv.z; acc[r].w += s * wv.w;
        }
    }
#pragma unroll
    for (int r = 0; r < 4; r++)
        *(float4*)(w + (size_t)(t0 + r) * 1024 + d) = acc[r];
}

// ---------------- 7. per-channel cumsum (scan only) ----------------
__global__ __launch_bounds__(1024) void cumsum_k(const float* __restrict__ w,
                                                 float* __restrict__ cs) {
    __shared__ float seg[32][33];
    int c = threadIdx.x & 31;
    int j = threadIdx.x >> 5;
    int d = blockIdx.x * 32 + c;
    int tb = j * 64;
    float s = 0.f;
    for (int t = 0; t < 64; t++)
        s -= expf(w[(size_t)(tb + t) * 1024 + d]);
    seg[j][c] = s;
    __syncthreads();
    if (j == 0) {
        float run = 0.f;
        for (int jj = 0; jj < 32; jj++) {
            float tmp = seg[jj][c];
            seg[jj][c] = run;
            run += tmp;
        }
    }
    __syncthreads();
    float run = seg[j][c];
    for (int t = 0; t < 64; t++) {
        run -= expf(w[(size_t)(tb + t) * 1024 + d]);
        cs[(size_t)(tb + t) * 1024 + d] = run;
    }
}

// ---------------- 8. premult -> bf16 hi/lo operands (wide grid) ----------------
__global__ __launch_bounds__(256) void premult_bf_k(const float* __restrict__ r,
                                                    const float* __restrict__ k,
                                                    const float* __restrict__ w,
                                                    const float* __restrict__ cs,
                                                    __nv_bfloat16* __restrict__ bfB) {
    int idx = blockIdx.x * 256 + threadIdx.x;
    if (idx >= TD) return;
    int d = idx & 1023;
    size_t midoff = (size_t)(TTOK / 2) * 1024 + d;
    float csv = cs[idx];
    float csm = cs[midoff];
    float wh   = -expf(w[idx]);
    float whm  = -expf(w[midoff]);
    float csf = clip60(csv - csm);
    float csb = clip60((csv - wh) - (csm - whm));
    float rv = r[idx], kv = k[idx];
    float vals[4];
    vals[0] = rv * expf(csf);
    vals[1] = kv * expf(-csf);
    vals[2] = rv * expf(-csb);
    vals[3] = kv * expf(csb);
#pragma unroll
    for (int j = 0; j < 4; j++) {
        __nv_bfloat16 h = __float2bfloat16(vals[j]);
        bfB[(size_t)(2 * j) * TD + idx] = h;
        bfB[(size_t)(2 * j + 1) * TD + idx] = __float2bfloat16(vals[j] - __bfloat162float(h));
    }
}

// ---------------- 9. attention + fused groupnorm/gate epilogue ----------------
__global__ __launch_bounds__(256, 2) void attn_mma_k(const __nv_bfloat16* __restrict__ bfB,
                                                     const float* __restrict__ log_tau,
                                                     const float* __restrict__ g,
                                                     const float* __restrict__ ln_g,
                                                     const float* __restrict__ ln_b,
                                                     __nv_bfloat16* __restrict__ ygHi,
                                                     __nv_bfloat16* __restrict__ ygLo) {
    extern __shared__ unsigned char sm8[];
    __shared__ float redA[64], redS[64];
    const uint32_t sb = smem_u32(sm8);
    int h = blockIdx.y, it = blockIdx.x;
    int t0 = it * 64;
    int tid = threadIdx.x, w = tid >> 5, lane = tid & 31;
    int mw = w >> 1, sw = w & 1;
    size_t hb = (size_t)h * 64;
    float tau = expf(log_tau[h]);
    int grp = lane >> 2, qp = lane & 3;

    if (tid < 64) { redA[tid] = 0.f; redS[tid] = 0.f; }

    for (int i = tid; i < 2048; i += 256) {
        int tile = i >> 9, idx = i & 511;
        int row = idx >> 3, ch = idx & 7;
        int arr = (tile & 1) + (tile >> 1) * 4;
        const char* gp = (const char*)(bfB + (size_t)arr * TD
                        + (size_t)(t0 + row) * 1024 + hb) + ch * 16;
        CPASYNC16(sb + tile * 8192 + SWZ(row * 128 + ch * 16), gp);
    }
    CPCOMMIT();
    CPWAIT0();
    __syncthreads();

    float accY[8][4];
#pragma unroll
    for (int nt = 0; nt < 8; nt++)
#pragma unroll
        for (int q = 0; q < 4; q++) accY[nt][q] = 0.f;
    float sA[2] = {0.f, 0.f};
    float sS[2] = {0.f, 0.f};

    for (int jt = 0; jt < 32; jt++) {
        int s0 = jt * 64;
        bool needF = (jt <= it);
        bool needB = (jt >= it);
        for (int i = tid; i < 3072; i += 256) {
            int tile = i >> 9;
            if (tile < 2 && !needF) continue;
            if (tile >= 2 && tile < 4 && !needB) continue;
            int idx = i & 511, row = idx >> 3, ch = idx & 7;
            int arr = (tile < 4) ? (2 + (tile & 1) + (tile >> 1) * 4) : (tile + 4);
            const char* gp = (const char*)(bfB + (size_t)arr * TD
                            + (size_t)(s0 + row) * 1024 + hb) + ch * 16;
            CPASYNC16(sb + 32768 + tile * 8192 + SWZ(row * 128 + ch * 16), gp);
        }
        CPCOMMIT();
        CPWAIT0();
        __syncthreads();

        float accF[4][4], accB[4][4];
#pragma unroll
        for (int nt = 0; nt < 4; nt++)
#pragma unroll
            for (int q = 0; q < 4; q++) { accF[nt][q] = 0.f; accB[nt][q] = 0.f; }

#pragma unroll
        for (int ks = 0; ks < 4; ks++) {
            uint32_t abyte = ks * 32 + (lane >> 4) * 16;
            uint32_t oA = SWZ((mw * 16 + (lane & 15)) * 128 + abyte);
            if (needF) {
                uint32_t aH[4], aL[4];
                LDSM_X4(aH, sb + oA);
                LDSM_X4(aL, sb + 8192 + oA);
                uint32_t bh[4][2], bl[4][2];
#pragma unroll
                for (int p = 0; p < 2; p++) {
                    uint32_t o = SWZ((sw * 32 + p * 16 + (lane & 15)) * 128 + abyte);
                    uint32_t t4[4], u4[4];
                    LDSM_X4(t4, sb + 32768 + o);
                    LDSM_X4(u4, sb + 40960 + o);
                    bh[2 * p][0] = t4[0]; bh[2 * p][1] = t4[2];
                    bh[2 * p + 1][0] = t4[1]; bh[2 * p + 1][1] = t4[3];
                    bl[2 * p][0] = u4[0]; bl[2 * p][1] = u4[2];
                    bl[2 * p + 1][0] = u4[1]; bl[2 * p + 1][1] = u4[3];
                }
#pragma unroll
                for (int nt = 0; nt < 4; nt++) {
                    MMA16816(accF[nt], aH, bh[nt]);
                    MMA16816(accF[nt], aH, bl[nt]);
                    MMA16816(accF[nt], aL, bh[nt]);
                }
            }
            if (needB) {
                uint32_t aH[4], aL[4];
                LDSM_X4(aH, sb + 16384 + oA);
                LDSM_X4(aL, sb + 24576 + oA);
                uint32_t bh[4][2], bl[4][2];
#pragma unroll
                for (int p = 0; p < 2; p++) {
                    uint32_t o = SWZ((sw * 32 + p * 16 + (lane & 15)) * 128 + abyte);
                    uint32_t t4[4], u4[4];
                    LDSM_X4(t4, sb + 49152 + o);
                    LDSM_X4(u4, sb + 57344 + o);
                    bh[2 * p][0] = t4[0]; bh[2 * p][1] = t4[2];
                    bh[2 * p + 1][0] = t4[1]; bh[2 * p + 1][1] = t4[3];
                    bl[2 * p][0] = u4[0]; bl[2 * p][1] = u4[2];
                    bl[2 * p + 1][0] = u4[1]; bl[2 * p + 1][1] = u4[3];
                }
#pragma unroll
                for (int nt = 0; nt < 4; nt++) {
                    MMA16816(accB[nt], aH, bh[nt]);
                    MMA16816(accB[nt], aH, bl[nt]);
                    MMA16816(accB[nt], aL, bh[nt]);
                }
            }
        }

        uint32_t pH[2][4], pL[2][4];
#pragma unroll
        for (int nt = 0; nt < 4; nt++) {
            float ash[4];
#pragma unroll
            for (int q = 0; q < 4; q++) {
                int trow = t0 + mw * 16 + grp + (q >> 1) * 8;
                int scol = s0 + sw * 32 + nt * 8 + qp * 2 + (q & 1);
                float val;
                if (jt < it) val = accF[nt][q];
                else if (jt > it) val = accB[nt][q];
                else val = (scol > trow) ? accB[nt][q] : accF[nt][q];
                float a = fmaxf(val, 0.f);
                sA[q >> 1] += a;
                float as = (a > 0.f) ? __powf(a + 1e-12f, tau) : 0.f;
                sS[q >> 1] += as;
                ash[q] = as;
            }
            int kc = nt >> 1, half = nt & 1;
            pH[kc][half * 2]     = packsplit(ash[0], ash[1], &pL[kc][half * 2]);
            pH[kc][half * 2 + 1] = packsplit(ash[2], ash[3], &pL[kc][half * 2 + 1]);
        }

#pragma unroll
        for (int kc = 0; kc < 2; kc++) {
#pragma unroll
            for (int dblk = 0; dblk < 4; dblk++) {
                uint32_t ov = SWZ((sw * 32 + kc * 16 + (lane & 15)) * 128
                                  + dblk * 32 + (lane >> 4) * 16);
                uint32_t t4[4], u4[4];
                LDSM_X4_T(t4, sb + 65536 + ov);
                LDSM_X4_T(u4, sb + 73728 + ov);
                uint32_t bvh[2][2] = {{t4[0], t4[1]}, {t4[2], t4[3]}};
                uint32_t bvl[2][2] = {{u4[0], u4[1]}, {u4[2], u4[3]}};
#pragma unroll
                for (int x = 0; x < 2; x++) {
                    int nt = dblk * 2 + x;
                    MMA16816(accY[nt], pH[kc], bvh[x]);
                    MMA16816(accY[nt], pH[kc], bvl[x]);
                    MMA16816(accY[nt], pL[kc], bvh[x]);
                }
            }
        }
        __syncthreads();
    }

#pragma unroll
    for (int qh = 0; qh < 2; qh++) {
        float va = sA[qh], vs = sS[qh];
        va += __shfl_xor_sync(0xFFFFFFFFu, va, 1);
        va += __shfl_xor_sync(0xFFFFFFFFu, va, 2);
        vs += __shfl_xor_sync(0xFFFFFFFFu, vs, 1);
        vs += __shfl_xor_sync(0xFFFFFFFFu, vs, 2);
        if ((lane & 3) == 0) {
            int trow = mw * 16 + grp + qh * 8;
            atomicAdd(&redA[trow], va);
            atomicAdd(&redS[trow], vs);
        }
    }

    float* red = (float*)sm8;
    __syncthreads();
    if (sw == 1) {
#pragma unroll
        for (int nt = 0; nt < 8; nt++) {
            int r0 = mw * 16 + grp;
            int col = nt * 8 + qp * 2;
            *(float2*)&red[(r0)     * 64 + col] = make_float2(accY[nt][0], accY[nt][1]);
            *(float2*)&red[(r0 + 8) * 64 + col] = make_float2(accY[nt][2], accY[nt][3]);
        }
    }
    __syncthreads();
    if (sw == 0) {
        int r0 = mw * 16 + grp;
        int r1 = r0 + 8;
        float sc0 = fmaxf(redA[r0], 1e-12f) / fmaxf(redS[r0], 1e-12f);
        float sc1 = fmaxf(redA[r1], 1e-12f) / fmaxf(redS[r1], 1e-12f);
        float s0 = 0.f, q0 = 0.f, s1 = 0.f, q1 = 0.f;
#pragma unroll
        for (int nt = 0; nt < 8; nt++) {
            int col = nt * 8 + qp * 2;
            float2 o0 = *(float2*)&red[r0 * 64 + col];
            float2 o1 = *(float2*)&red[r1 * 64 + col];
            accY[nt][0] = (accY[nt][0] + o0.x) * sc0;
            accY[nt][1] = (accY[nt][1] + o0.y) * sc0;
            accY[nt][2] = (accY[nt][2] + o1.x) * sc1;
            accY[nt][3] = (accY[nt][3] + o1.y) * sc1;
            s0 += accY[nt][0] + accY[nt][1];
            q0 += accY[nt][0] * accY[nt][0] + accY[nt][1] * accY[nt][1];
            s1 += accY[nt][2] + accY[nt][3];
            q1 += accY[nt][2] * accY[nt][2] + accY[nt][3] * accY[nt][3];
        }
        s0 += __shfl_xor_sync(0xFFFFFFFFu, s0, 1);
        s0 += __shfl_xor_sync(0xFFFFFFFFu, s0, 2);
        q0 += __shfl_xor_sync(0xFFFFFFFFu, q0, 1);
        q0 += __shfl_xor_sync(0xFFFFFFFFu, q0, 2);
        s1 += __shfl_xor_sync(0xFFFFFFFFu, s1, 1);
        s1 += __shfl_xor_sync(0xFFFFFFFFu, s1, 2);
        q1 += __shfl_xor_sync(0xFFFFFFFFu, q1, 1);
        q1 += __shfl_xor_sync(0xFFFFFFFFu, q1, 2);
        float mu0 = s0 * (1.f / 64.f);
        float var0 = q0 * (1.f / 64.f) - mu0 * mu0;
        float inv0 = rsqrtf(var0 + 6.4e-4f);
        float mu1 = s1 * (1.f / 64.f);
        float var1 = q1 * (1.f / 64.f) - mu1 * mu1;
        float inv1 = rsqrtf(var1 + 6.4e-4f);
#pragma unroll
        for (int nt = 0; nt < 8; nt++) {
            int col = nt * 8 + qp * 2;
            int dch = (int)hb + col;
            float2 lg = *(const float2*)&ln_g[dch];
            float2 lb = *(const float2*)&ln_b[dch];
            float2 gg0 = *(const float2*)&g[(size_t)(t0 + r0) * 1024 + dch];
            float2 gg1 = *(const float2*)&g[(size_t)(t0 + r1) * 1024 + dch];
            float ox0 = ((accY[nt][0] - mu0) * inv0 * lg.x + lb.x) * gg0.x;
            float oy0 = ((accY[nt][1] - mu0) * inv0 * lg.y + lb.y) * gg0.y;
            float ox1 = ((accY[nt][2] - mu1) * inv1 * lg.x + lb.x) * gg1.x;
            float oy1 = ((accY[nt][3] - mu1) * inv1 * lg.y + lb.y) * gg1.y;
            __nv_bfloat162 hh, ll;
            split2(ox0, oy0, &hh, &ll);
            *(__nv_bfloat162*)(ygHi + (size_t)(t0 + r0) * 1024 + dch) = hh;
            *(__nv_bfloat162*)(ygLo + (size_t)(t0 + r0) * 1024 + dch) = ll;
            split2(ox1, oy1, &hh, &ll);
            *(__nv_bfloat162*)(ygHi + (size_t)(t0 + r1) * 1024 + dch) = hh;
            *(__nv_bfloat162*)(ygLo + (size_t)(t0 + r1) * 1024 + dch) = ll;
        }
    }
}

// ---------------- launch ----------------
extern "C" void kernel_launch(void* const* d_in, const int* in_sizes, int n_in,
                              void* d_out, int out_size) {
    const float* x          = (const float*)d_in[0];
    const float* maa_x      = (const float*)d_in[1];
    const float* maa_w      = (const float*)d_in[2];
    const float* maa_k      = (const float*)d_in[3];
    const float* maa_v      = (const float*)d_in[4];
    const float* maa_r      = (const float*)d_in[5];
    const float* maa_g      = (const float*)d_in[6];
    const float* maa_w1     = (const float*)d_in[7];
    const float* maa_w2     = (const float*)d_in[8];
    const float* time_decay = (const float*)d_in[9];
    const float* decay_w1   = (const float*)d_in[10];
    const float* decay_w2   = (const float*)d_in[11];
    const float* log_tau    = (const float*)d_in[12];
    const float* Wr         = (const float*)d_in[13];
    const float* Wk         = (const float*)d_in[14];
    const float* Wv         = (const float*)d_in[15];
    const float* Wg         = (const float*)d_in[16];
    const float* Wo         = (const float*)d_in[17];
    const float* ln_g       = (const float*)d_in[18];
    const float* ln_b       = (const float*)d_in[19];

    float* S = nullptr;
    cudaGetSymbolAddress((void**)&S, g_scratch);
    float* zb    = S + OFF_Z;
    float* xwb   = S + OFF_XW;
    float* rkvg  = S + OFF_RKVG;
    float* wb    = S + OFF_W;
    float* csb   = S + OFF_CS;
    float* xxxb  = S + OFF_XXX;
    float* wmidb = S + OFF_WMID;
    __nv_bfloat16* actHi = (__nv_bfloat16*)(S + OFF_ACTHI);
    __nv_bfloat16* actLo = (__nv_bfloat16*)(S + OFF_ACTLO);
    __nv_bfloat16* wtHi  = (__nv_bfloat16*)(S + OFF_WTHI);
    __nv_bfloat16* wtLo  = (__nv_bfloat16*)(S + OFF_WTLO);
    __nv_bfloat16* ygHi  = (__nv_bfloat16*)(S + OFF_YGHI);
    __nv_bfloat16* ygLo  = (__nv_bfloat16*)(S + OFF_YGLO);
    __nv_bfloat16* bfB   = (__nv_bfloat16*)(S + OFF_BF);

    int gemm_smem = 98304;
    cudaFuncSetAttribute(gemm_mma_k, cudaFuncAttributeMaxDynamicSharedMemorySize, gemm_smem);
    int attn_smem = 81920;
    cudaFuncSetAttribute(attn_mma_k, cudaFuncAttributeMaxDynamicSharedMemorySize, attn_smem);

    prep_k<<<(TD + 255) / 256, 256>>>(x, maa_x, zb);
    xxx_k<<<TTOK / 4, 320>>>(zb, maa_w1, xxxb);
    mix_k<<<TTOK / 4, 256>>>(x, xxxb, maa_w2,
                             maa_w, maa_k, maa_v, maa_r, maa_g, xwb, actHi, actLo);
    {
        dim3 grid(32, 32, 5);
        conv_wt_k<<<grid, 256>>>(Wr, Wk, Wv, Wg, Wo, wtHi, wtLo);
    }
    {
        dim3 grid(16, 16, 4);
        gemm_mma_k<<<grid, 256, gemm_smem>>>(actHi, actLo, wtHi, wtLo, rkvg, 3,
                                             bfB + (size_t)8 * TD, bfB + (size_t)9 * TD, 2);
    }
    decay1_k<<<TTOK / 8, 256>>>(xwb, decay_w1, wmidb);
    decay2_k<<<TTOK / 4, 256>>>(wmidb, decay_w2, time_decay, wb);
    cumsum_k<<<DDIM / 32, 1024>>>(wb, csb);
    premult_bf_k<<<(TD + 255) / 256, 256>>>(rkvg, rkvg + (size_t)TD, wb, csb, bfB);
    {
        dim3 grid(32, 16);
        attn_mma_k<<<grid, 256, attn_smem>>>(bfB, log_tau, rkvg + (size_t)3 * TD,
                                             ln_g, ln_b, ygHi, ygLo);
    }
    {
        dim3 grid(16, 16, 1);
        gemm_mma_k<<<grid, 256, gemm_smem>>>(ygHi, ygLo, wtHi + (size_t)4 * 1048576,
                                             wtLo + (size_t)4 * 1048576,
                                             (float*)d_out, -1, nullptr, nullptr, -1);
    }
}

// round 14
// speedup vs baseline: 1.1652x; 1.0638x over previous
#include <cuda_runtime.h>
#include <cuda_bf16.h>
#include <math.h>
#include <stdint.h>

#define TTOK 2048
#define DDIM 1024
#define TD (TTOK*DDIM)

// ---------------- scratch (static device memory; no allocations) ----------------
__device__ float g_scratch[68157440];

#define OFF_Z     ((size_t)1*TD)
#define OFF_XW    ((size_t)2*TD)
#define OFF_RKVG  ((size_t)7*TD)
#define OFF_W     ((size_t)11*TD)
#define OFF_CS    ((size_t)12*TD)
#define OFF_XXX   ((size_t)19*TD)
#define OFF_WMID  (OFF_XXX + (size_t)TTOK*160)
#define OFF_ACTHI ((size_t)20*TD)
#define OFF_ACTLO ((size_t)22*TD)
#define OFF_WTHI  ((size_t)24*TD)
#define OFF_WTLO  (OFF_WTHI + (size_t)2621440)
#define OFF_YGHI  (OFF_WTLO + (size_t)2621440)
#define OFF_YGLO  (OFF_YGHI + (size_t)(TD/2))
#define OFF_BF    (OFF_YGLO + (size_t)(TD/2))

static __device__ __forceinline__ float clip60(float x) {
    return fminf(fmaxf(x, -60.f), 60.f);
}
static __device__ __forceinline__ uint32_t smem_u32(const void* p) {
    uint32_t a;
    asm("{ .reg .u64 t; cvta.to.shared.u64 t, %1; cvt.u32.u64 %0, t; }" : "=r"(a) : "l"(p));
    return a;
}

#define LDSM_X4(r, addr) \
    asm volatile("ldmatrix.sync.aligned.m8n8.x4.shared.b16 {%0,%1,%2,%3}, [%4];" \
                 : "=r"((r)[0]), "=r"((r)[1]), "=r"((r)[2]), "=r"((r)[3]) : "r"(addr))
#define LDSM_X4_T(r, addr) \
    asm volatile("ldmatrix.sync.aligned.m8n8.x4.trans.shared.b16 {%0,%1,%2,%3}, [%4];" \
                 : "=r"((r)[0]), "=r"((r)[1]), "=r"((r)[2]), "=r"((r)[3]) : "r"(addr))
#define MMA16816(d, a, b) \
    asm volatile("mma.sync.aligned.m16n8k16.row.col.f32.bf16.bf16.f32 " \
                 "{%0,%1,%2,%3}, {%4,%5,%6,%7}, {%8,%9}, {%0,%1,%2,%3};" \
                 : "+f"((d)[0]), "+f"((d)[1]), "+f"((d)[2]), "+f"((d)[3]) \
                 : "r"((a)[0]), "r"((a)[1]), "r"((a)[2]), "r"((a)[3]), \
                   "r"((b)[0]), "r"((b)[1]))
#define CPASYNC16(s, g) \
    asm volatile("cp.async.cg.shared.global [%0], [%1], 16;" :: "r"(s), "l"(g))
#define CPCOMMIT() asm volatile("cp.async.commit_group;" ::: "memory")
#define CPWAIT1()  asm volatile("cp.async.wait_group 1;" ::: "memory")
#define CPWAIT0()  asm volatile("cp.async.wait_group 0;" ::: "memory")
#define SWZ(o) ((o) ^ (((o) >> 3) & 0x70))

static __device__ __forceinline__ void split2(float a, float b,
                                              __nv_bfloat162* hi, __nv_bfloat162* lo) {
    __nv_bfloat162 h, l;
    h.x = __float2bfloat16(a);
    h.y = __float2bfloat16(b);
    l.x = __float2bfloat16(a - __bfloat162float(h.x));
    l.y = __float2bfloat16(b - __bfloat162float(h.y));
    *hi = h; *lo = l;
}
static __device__ __forceinline__ uint32_t packsplit(float a, float b, uint32_t* lo) {
    __nv_bfloat162 h, l;
    split2(a, b, &h, &l);
    *lo = *(uint32_t*)&l;
    return *(uint32_t*)&h;
}

// ---------------- 1. token shift -> z only ----------------
__global__ __launch_bounds__(256) void prep_k(const float* __restrict__ x,
                                              const float* __restrict__ maa_x,
                                              float* __restrict__ z) {
    int idx = blockIdx.x * 256 + threadIdx.x;
    if (idx >= TD) return;
    int t = idx >> 10;
    int d = idx & 1023;
    float xv = x[idx];
    float prev = (t > 0) ? x[idx - 1024] : 0.f;
    float nxt  = (t < TTOK - 1) ? x[idx + 1024] : 0.f;
    float dxv = 0.5f * (prev + nxt) - xv;
    z[idx] = xv + dxv * maa_x[d];
}

// ---------------- 2. xxx = tanh(z @ maa_w1): 320 thr, split-K ----------------
__global__ __launch_bounds__(320) void xxx_k(const float* __restrict__ z,
                                             const float* __restrict__ w1,
                                             float* __restrict__ xxx) {
    __shared__ float zs[4][1024];
    __shared__ float part[2][4][160];
    int t0 = blockIdx.x * 4;
    int tid = threadIdx.x;
    for (int i = tid; i < 1024; i += 320) {
        int r = i >> 8, c4 = (i & 255) * 4;
        *(float4*)&zs[r][c4] = *(const float4*)(z + (size_t)(t0 + r) * 1024 + c4);
    }
    __syncthreads();
    int out = (tid < 160) ? tid : (tid - 160);
    int kh = (tid < 160) ? 0 : 1;
    int kb = kh * 512;
    float acc[4] = {0.f, 0.f, 0.f, 0.f};
    for (int dd = 0; dd < 512; dd++) {
        int d = kb + dd;
        float w = w1[d * 160 + out];
        acc[0] += zs[0][d] * w;
        acc[1] += zs[1][d] * w;
        acc[2] += zs[2][d] * w;
        acc[3] += zs[3][d] * w;
    }
#pragma unroll
    for (int r = 0; r < 4; r++) part[kh][r][out] = acc[r];
    __syncthreads();
    if (tid < 160) {
#pragma unroll
        for (int r = 0; r < 4; r++)
            xxx[(size_t)(t0 + r) * 160 + tid] =
                tanhf(part[0][r][tid] + part[1][r][tid]);
    }
}

// ---------------- 3. mixer: dx recomputed inline ----------------
__global__ __launch_bounds__(256) void mix_k(const float* __restrict__ x,
                                             const float* __restrict__ xxx,
                                             const float* __restrict__ w2,
                                             const float* __restrict__ maa_w,
                                             const float* __restrict__ maa_k,
                                             const float* __restrict__ maa_v,
                                             const float* __restrict__ maa_r,
                                             const float* __restrict__ maa_g,
                                             float* __restrict__ xw,
                                             __nv_bfloat16* __restrict__ actHi,
                                             __nv_bfloat16* __restrict__ actLo) {
    __shared__ float xs[4][160];
    int t0 = blockIdx.x * 4;
    int tid = threadIdx.x;
    for (int i = tid; i < 640; i += 256) {
        int r = i / 160, c = i - r * 160;
        xs[r][c] = xxx[(size_t)(t0 + r) * 160 + c];
    }
    __syncthreads();
    int d = tid * 4;
    float4 xv[4], dxv[4];
#pragma unroll
    for (int r = 0; r < 4; r++) {
        int t = t0 + r;
        xv[r] = *(const float4*)(x + (size_t)t * 1024 + d);
        float4 pv = (t > 0) ? *(const float4*)(x + (size_t)(t - 1) * 1024 + d)
                            : make_float4(0.f, 0.f, 0.f, 0.f);
        float4 nv = (t < TTOK - 1) ? *(const float4*)(x + (size_t)(t + 1) * 1024 + d)
                                   : make_float4(0.f, 0.f, 0.f, 0.f);
        dxv[r].x = 0.5f * (pv.x + nv.x) - xv[r].x;
        dxv[r].y = 0.5f * (pv.y + nv.y) - xv[r].y;
        dxv[r].z = 0.5f * (pv.z + nv.z) - xv[r].z;
        dxv[r].w = 0.5f * (pv.w + nv.w) - xv[r].w;
    }
#pragma unroll
    for (int f = 0; f < 5; f++) {
        float4 acc[4];
#pragma unroll
        for (int r = 0; r < 4; r++) acc[r] = make_float4(0.f, 0.f, 0.f, 0.f);
        for (int mi = 0; mi < 32; mi++) {
            float4 w = *(const float4*)(w2 + (size_t)(f * 32 + mi) * 1024 + d);
#pragma unroll
            for (int r = 0; r < 4; r++) {
                float s = xs[r][f * 32 + mi];
                acc[r].x += s * w.x; acc[r].y += s * w.y;
                acc[r].z += s * w.z; acc[r].w += s * w.w;
            }
        }
        const float* maa = (f == 0) ? maa_w : (f == 1) ? maa_k : (f == 2) ? maa_v
                         : (f == 3) ? maa_r : maa_g;
        float4 mv = *(const float4*)(maa + d);
        int slot = (f == 3) ? 0 : (f == 1) ? 1 : (f == 2) ? 2 : 3;
#pragma unroll
        for (int r = 0; r < 4; r++) {
            float4 o;
            o.x = xv[r].x + dxv[r].x * (mv.x + acc[r].x);
            o.y = xv[r].y + dxv[r].y * (mv.y + acc[r].y);
            o.z = xv[r].z + dxv[r].z * (mv.z + acc[r].z);
            o.w = xv[r].w + dxv[r].w * (mv.w + acc[r].w);
            if (f == 0) {
                *(float4*)(xw + (size_t)(t0 + r) * 1024 + d) = o;
            } else {
                size_t ofs = (size_t)slot * TD + (size_t)(t0 + r) * 1024 + d;
                __nv_bfloat162 h0, l0, h1, l1;
                split2(o.x, o.y, &h0, &l0);
                split2(o.z, o.w, &h1, &l1);
                *(__nv_bfloat162*)(actHi + ofs)     = h0;
                *(__nv_bfloat162*)(actHi + ofs + 2) = h1;
                *(__nv_bfloat162*)(actLo + ofs)     = l0;
                *(__nv_bfloat162*)(actLo + ofs + 2) = l1;
            }
        }
    }
}

// ---------------- weight transpose + split ----------------
__global__ __launch_bounds__(256) void conv_wt_k(const float* __restrict__ W0,
                                                 const float* __restrict__ W1,
                                                 const float* __restrict__ W2,
                                                 const float* __restrict__ W3,
                                                 const float* __restrict__ W4,
                                                 __nv_bfloat16* __restrict__ hi,
                                                 __nv_bfloat16* __restrict__ lo) {
    __shared__ float tile[32][33];
    int z = blockIdx.z;
    const float* W = (z == 0) ? W0 : (z == 1) ? W1 : (z == 2) ? W2 : (z == 3) ? W3 : W4;
    int k0 = blockIdx.x * 32, n0 = blockIdx.y * 32;
    int tx = threadIdx.x & 31, ty = threadIdx.x >> 5;
#pragma unroll
    for (int i = 0; i < 32; i += 8)
        tile[ty + i][tx] = W[(size_t)(k0 + ty + i) * 1024 + n0 + tx];
    __syncthreads();
    size_t base = (size_t)z * 1048576;
#pragma unroll
    for (int i = 0; i < 32; i += 8) {
        float v = tile[tx][ty + i];
        size_t o = base + (size_t)(n0 + ty + i) * 1024 + k0 + tx;
        __nv_bfloat16 h = __float2bfloat16(v);
        hi[o] = h;
        lo[o] = __float2bfloat16(v - __bfloat162float(h));
    }
}

// ---------------- mma.sync split-bf16 GEMM: 128x64 tile, occ 2, strength-reduced addr ----------------
__global__ __launch_bounds__(256, 2)
void gemm_mma_k(const __nv_bfloat16* __restrict__ aHi,
                const __nv_bfloat16* __restrict__ aLo,
                const __nv_bfloat16* __restrict__ bHi,
                const __nv_bfloat16* __restrict__ bLo,
                float* __restrict__ C, int siluZ,
                __nv_bfloat16* __restrict__ vHi,
                __nv_bfloat16* __restrict__ vLo, int vz) {
    extern __shared__ unsigned char smraw[];
    const int tid = threadIdx.x;
    const int z = blockIdx.z;
    const int bm = blockIdx.y * 128;
    const int bn = blockIdx.x * 64;
    float* Cz = C + (size_t)z * TD;

    const uint32_t sbase = smem_u32(smraw);
    const int w = tid >> 5, lane = tid & 31;
    const int mw = w >> 1, nw = w & 1;

    // -------- precomputed load-loop addressing --------
    const int ch16 = (tid & 7) * 16;
    const int arow = tid >> 3;                 // 0..31
    // gmem: base + jj*65536(A rows+32) / +c*128
    const char* gA[2] = {
        (const char*)(aHi + (size_t)z * TD) + (size_t)(bm + arow) * 2048 + ch16,
        (const char*)(aLo + (size_t)z * TD) + (size_t)(bm + arow) * 2048 + ch16 };
    const char* gB[2] = {
        (const char*)(bHi + (size_t)z * 1048576) + (size_t)(bn + arow) * 2048 + ch16,
        (const char*)(bLo + (size_t)z * 1048576) + (size_t)(bn + arow) * 2048 + ch16 };
    // smem: swbase + jj*4096 (row+32 keeps row&7)
    const uint32_t swb = arow * 128 + (ch16 ^ ((arow & 7) << 4));

    float acc[2][4][4];
#pragma unroll
    for (int mt = 0; mt < 2; mt++)
#pragma unroll
        for (int nt = 0; nt < 4; nt++)
#pragma unroll
            for (int q = 0; q < 4; q++) acc[mt][nt][q] = 0.f;

    auto issue = [&](int c) {
        uint32_t stg = sbase + (c & 1) * 49152;
        uint32_t cofs = (uint32_t)c * 128;
#pragma unroll
        for (int jj = 0; jj < 8; jj++) {
            int tile = jj >> 2, sub = jj & 3;
            CPASYNC16(stg + tile * 16384 + swb + sub * 4096,
                      gA[tile] + sub * 65536 + cofs);
        }
#pragma unroll
        for (int jb = 0; jb < 4; jb++) {
            int tile = jb >> 1, sub = jb & 1;
            CPASYNC16(stg + 32768 + tile * 8192 + swb + sub * 4096,
                      gB[tile] + sub * 65536 + cofs);
        }
        CPCOMMIT();
    };

    // -------- precomputed compute-loop addressing --------
    // A rows: rA(mt) = mw*32 + mt*16 + lane&15 ; B rows: rB(p) = nw*32 + p*16 + lane&15
    uint32_t aBase[2], bBase[2];
    {
        int l15 = lane & 15;
        int hi16 = (lane >> 4) * 16;
#pragma unroll
        for (int mt = 0; mt < 2; mt++) {
            int r = mw * 32 + mt * 16 + l15;
            aBase[mt] = r * 128 + (hi16 ^ ((r & 7) << 4));   // add ks*32^... careful
        }
#pragma unroll
        for (int p = 0; p < 2; p++) {
            int r = nw * 32 + p * 16 + l15;
            bBase[p] = r * 128 + (hi16 ^ ((r & 7) << 4));
        }
    }
    // per-ks offsets: abyte = ks*32 + hi16 ; sw = r*128 + (abyte ^ xr) where xr = (r&7)<<4.
    // aBase already folds hi16^xr; ks*32 occupies bits 5-6 which are XORed with xr bits 5-6.
    // (hi16 ^ xr) + ks*32 != hi16^xr^(ks*32) in general -> compute ks term via XOR on the xr:
    // sw(ks) = r*128 + ((ks*32 + hi16) ^ xr). Keep xr separately instead.
    uint32_t aRow128[2], aXr[2], bRow128[2], bXr[2];
    {
        int l15 = lane & 15;
#pragma unroll
        for (int mt = 0; mt < 2; mt++) {
            int r = mw * 32 + mt * 16 + l15;
            aRow128[mt] = r * 128;
            aXr[mt] = (r & 7) << 4;
        }
#pragma unroll
        for (int p = 0; p < 2; p++) {
            int r = nw * 32 + p * 16 + l15;
            bRow128[p] = r * 128;
            bXr[p] = (r & 7) << 4;
        }
    }
    const uint32_t hi16 = (lane >> 4) * 16;

    issue(0);
    issue(1);

    for (int c = 0; c < 16; c++) {
        if (c < 15) CPWAIT1(); else CPWAIT0();
        __syncthreads();
        uint32_t st = sbase + (c & 1) * 49152;
#pragma unroll
        for (int kk = 0; kk < 4; kk++) {
            uint32_t abyte = kk * 32 + hi16;
            uint32_t ah[2][4], al[2][4];
#pragma unroll
            for (int mt = 0; mt < 2; mt++) {
                uint32_t o = aRow128[mt] + (abyte ^ aXr[mt]);
                LDSM_X4(ah[mt], st + o);
                LDSM_X4(al[mt], st + 16384 + o);
            }
            uint32_t bh[4][2], bl[4][2];
#pragma unroll
            for (int p = 0; p < 2; p++) {
                uint32_t o = bRow128[p] + (abyte ^ bXr[p]);
                uint32_t t4[4];
                LDSM_X4(t4, st + 32768 + o);
                bh[2 * p][0] = t4[0]; bh[2 * p][1] = t4[2];
                bh[2 * p + 1][0] = t4[1]; bh[2 * p + 1][1] = t4[3];
                LDSM_X4(t4, st + 40960 + o);
                bl[2 * p][0] = t4[0]; bl[2 * p][1] = t4[2];
                bl[2 * p + 1][0] = t4[1]; bl[2 * p + 1][1] = t4[3];
            }
#pragma unroll
            for (int mt = 0; mt < 2; mt++)
#pragma unroll
                for (int nt = 0; nt < 4; nt++) {
                    MMA16816(acc[mt][nt], ah[mt], bh[nt]);
                    MMA16816(acc[mt][nt], ah[mt], bl[nt]);
                    MMA16816(acc[mt][nt], al[mt], bh[nt]);
                }
        }
        __syncthreads();
        if (c + 2 < 16) issue(c + 2);
    }

    bool silu = (z == siluZ);
    bool isv = (z == vz);
    int r0 = bm + mw * 32, c0 = bn + nw * 32;
#pragma unroll
    for (int mt = 0; mt < 2; mt++)
#pragma unroll
        for (int nt = 0; nt < 4; nt++) {
            float* d = acc[mt][nt];
            int row = r0 + mt * 16 + (lane >> 2);
            int col = c0 + nt * 8 + (lane & 3) * 2;
            if (isv) {
                __nv_bfloat162 h, l;
                split2(d[0], d[1], &h, &l);
                *(__nv_bfloat162*)(vHi + (size_t)row * 1024 + col) = h;
                *(__nv_bfloat162*)(vLo + (size_t)row * 1024 + col) = l;
                split2(d[2], d[3], &h, &l);
                *(__nv_bfloat162*)(vHi + (size_t)(row + 8) * 1024 + col) = h;
                *(__nv_bfloat162*)(vLo + (size_t)(row + 8) * 1024 + col) = l;
            } else {
                if (silu) {
#pragma unroll
                    for (int q = 0; q < 4; q++) d[q] = d[q] / (1.f + expf(-d[q]));
                }
                *(float2*)&Cz[(size_t)row * 1024 + col]       = make_float2(d[0], d[1]);
                *(float2*)&Cz[(size_t)(row + 8) * 1024 + col] = make_float2(d[2], d[3]);
            }
        }
}

// ---------------- 5. decay MLP stage 1 ----------------
__global__ __launch_bounds__(256) void decay1_k(const float* __restrict__ xw,
                                                const float* __restrict__ dw1,
                                                float* __restrict__ wmid) {
    __shared__ float xs[8][1024];
    __shared__ float part[4][64][8];
    int t0 = blockIdx.x * 8;
    int tid = threadIdx.x;
    for (int i = tid; i < 8 * 256; i += 256) {
        int r = i >> 8;
        int c4 = (i & 255) * 4;
        *(float4*)(&xs[r][c4]) = *(const float4*)(xw + (size_t)(t0 + r) * 1024 + c4);
    }
    __syncthreads();
    int n = tid & 63;
    int kq = tid >> 6;
    int kbase = kq * 256;
    float acc[8] = {0.f, 0.f, 0.f, 0.f, 0.f, 0.f, 0.f, 0.f};
    for (int dd = 0; dd < 256; dd++) {
        int d = kbase + dd;
        float w = dw1[d * 64 + n];
#pragma unroll
        for (int r = 0; r < 8; r++) acc[r] += xs[r][d] * w;
    }
#pragma unroll
    for (int r = 0; r < 8; r++) part[kq][n][r] = acc[r];
    __syncthreads();
    for (int i = tid; i < 512; i += 256) {
        int nn = i & 63, r = i >> 6;
        float s = part[0][nn][r] + part[1][nn][r] + part[2][nn][r] + part[3][nn][r];
        wmid[(size_t)(t0 + r) * 64 + nn] = tanhf(s);
    }
}

// ---------------- 6. decay MLP stage 2 ----------------
__global__ __launch_bounds__(256) void decay2_k(const float* __restrict__ wmid,
                                                const float* __restrict__ dw2,
                                                const float* __restrict__ td,
                                                float* __restrict__ w) {
    __shared__ float ws[4][64];
    int t0 = blockIdx.x * 4;
    int tid = threadIdx.x;
    {
        int r = tid >> 6, c = tid & 63;
        ws[r][c] = wmid[(size_t)(t0 + r) * 64 + c];
    }
    __syncthreads();
    int d = tid * 4;
    float4 tdv = *(const float4*)(td + d);
    float4 acc[4];
#pragma unroll
    for (int r = 0; r < 4; r++) acc[r] = tdv;
    for (int j = 0; j < 64; j++) {
        float4 wv = *(const float4*)(dw2 + (size_t)j * 1024 + d);
#pragma unroll
        for (int r = 0; r < 4; r++) {
            float s = ws[r][j];
            acc[r].x += s * wv.x; acc[r].y += s * wv.y;
            acc[r].z += s * wv.z; acc[r].w += s * wv.w;
        }
    }
#pragma unroll
    for (int r = 0; r < 4; r++)
        *(float4*)(w + (size_t)(t0 + r) * 1024 + d) = acc[r];
}

// ---------------- 7. per-channel cumsum ----------------
__global__ __launch_bounds__(1024) void cumsum_k(const float* __restrict__ w,
                                                 float* __restrict__ cs) {
    __shared__ float seg[32][33];
    int c = threadIdx.x & 31;
    int j = threadIdx.x >> 5;
    int d = blockIdx.x * 32 + c;
    int tb = j * 64;
    float s = 0.f;
    for (int t = 0; t < 64; t++)
        s -= expf(w[(size_t)(tb + t) * 1024 + d]);
    seg[j][c] = s;
    __syncthreads();
    if (j == 0) {
        float run = 0.f;
        for (int jj = 0; jj < 32; jj++) {
            float tmp = seg[jj][c];
            seg[jj][c] = run;
            run += tmp;
        }
    }
    __syncthreads();
    float run = seg[j][c];
    for (int t = 0; t < 64; t++) {
        run -= expf(w[(size_t)(tb + t) * 1024 + d]);
        cs[(size_t)(tb + t) * 1024 + d] = run;
    }
}

// ---------------- 8. premult -> bf16 hi/lo ----------------
__global__ __launch_bounds__(256) void premult_bf_k(const float* __restrict__ r,
                                                    const float* __restrict__ k,
                                                    const float* __restrict__ w,
                                                    const float* __restrict__ cs,
                                                    __nv_bfloat16* __restrict__ bfB) {
    int idx = blockIdx.x * 256 + threadIdx.x;
    if (idx >= TD) return;
    int d = idx & 1023;
    size_t midoff = (size_t)(TTOK / 2) * 1024 + d;
    float csv = cs[idx];
    float csm = cs[midoff];
    float wh   = -expf(w[idx]);
    float whm  = -expf(w[midoff]);
    float csf = clip60(csv - csm);
    float csb = clip60((csv - wh) - (csm - whm));
    float rv = r[idx], kv = k[idx];
    float vals[4];
    vals[0] = rv * expf(csf);
    vals[1] = kv * expf(-csf);
    vals[2] = rv * expf(-csb);
    vals[3] = kv * expf(csb);
#pragma unroll
    for (int j = 0; j < 4; j++) {
        __nv_bfloat16 h = __float2bfloat16(vals[j]);
        bfB[(size_t)(2 * j) * TD + idx] = h;
        bfB[(size_t)(2 * j + 1) * TD + idx] = __float2bfloat16(vals[j] - __bfloat162float(h));
    }
}

// ---------------- 9. attention + fused groupnorm/gate epilogue ----------------
__global__ __launch_bounds__(256, 2) void attn_mma_k(const __nv_bfloat16* __restrict__ bfB,
                                                     const float* __restrict__ log_tau,
                                                     const float* __restrict__ g,
                                                     const float* __restrict__ ln_g,
                                                     const float* __restrict__ ln_b,
                                                     __nv_bfloat16* __restrict__ ygHi,
                                                     __nv_bfloat16* __restrict__ ygLo) {
    extern __shared__ unsigned char sm8[];
    __shared__ float redA[64], redS[64];
    const uint32_t sb = smem_u32(sm8);
    int h = blockIdx.y, it = blockIdx.x;
    int t0 = it * 64;
    int tid = threadIdx.x, w = tid >> 5, lane = tid & 31;
    int mw = w >> 1, sw = w & 1;
    size_t hb = (size_t)h * 64;
    float tau = expf(log_tau[h]);
    int grp = lane >> 2, qp = lane & 3;

    if (tid < 64) { redA[tid] = 0.f; redS[tid] = 0.f; }

    for (int i = tid; i < 2048; i += 256) {
        int tile = i >> 9, idx = i & 511;
        int row = idx >> 3, ch = idx & 7;
        int arr = (tile & 1) + (tile >> 1) * 4;
        const char* gp = (const char*)(bfB + (size_t)arr * TD
                        + (size_t)(t0 + row) * 1024 + hb) + ch * 16;
        CPASYNC16(sb + tile * 8192 + SWZ(row * 128 + ch * 16), gp);
    }
    CPCOMMIT();
    CPWAIT0();
    __syncthreads();

    // precomputed compute addressing (closed-form swizzle)
    const uint32_t hi16 = (lane >> 4) * 16;
    uint32_t aRow128, aXr;
    {
        int r = mw * 16 + (lane & 15);
        aRow128 = r * 128; aXr = (r & 7) << 4;
    }
    uint32_t bRow128[2], bXr[2];
#pragma unroll
    for (int p = 0; p < 2; p++) {
        int r = sw * 32 + p * 16 + (lane & 15);
        bRow128[p] = r * 128; bXr[p] = (r & 7) << 4;
    }
    uint32_t vRow128[2], vXr[2];
#pragma unroll
    for (int kc = 0; kc < 2; kc++) {
        int r = sw * 32 + kc * 16 + (lane & 15);
        vRow128[kc] = r * 128; vXr[kc] = (r & 7) << 4;
    }

    float accY[8][4];
#pragma unroll
    for (int nt = 0; nt < 8; nt++)
#pragma unroll
        for (int q = 0; q < 4; q++) accY[nt][q] = 0.f;
    float sA[2] = {0.f, 0.f};
    float sS[2] = {0.f, 0.f};

    for (int jt = 0; jt < 32; jt++) {
        int s0 = jt * 64;
        bool needF = (jt <= it);
        bool needB = (jt >= it);
        for (int i = tid; i < 3072; i += 256) {
            int tile = i >> 9;
            if (tile < 2 && !needF) continue;
            if (tile >= 2 && tile < 4 && !needB) continue;
            int idx = i & 511, row = idx >> 3, ch = idx & 7;
            int arr = (tile < 4) ? (2 + (tile & 1) + (tile >> 1) * 4) : (tile + 4);
            const char* gp = (const char*)(bfB + (size_t)arr * TD
                            + (size_t)(s0 + row) * 1024 + hb) + ch * 16;
            CPASYNC16(sb + 32768 + tile * 8192 + SWZ(row * 128 + ch * 16), gp);
        }
        CPCOMMIT();
        CPWAIT0();
        __syncthreads();

        float accF[4][4], accB[4][4];
#pragma unroll
        for (int nt = 0; nt < 4; nt++)
#pragma unroll
            for (int q = 0; q < 4; q++) { accF[nt][q] = 0.f; accB[nt][q] = 0.f; }

#pragma unroll
        for (int ks = 0; ks < 4; ks++) {
            uint32_t abyte = ks * 32 + hi16;
            uint32_t oA = aRow128 + (abyte ^ aXr);
            if (needF) {
                uint32_t aH[4], aL[4];
                LDSM_X4(aH, sb + oA);
                LDSM_X4(aL, sb + 8192 + oA);
                uint32_t bh[4][2], bl[4][2];
#pragma unroll
                for (int p = 0; p < 2; p++) {
                    uint32_t o = bRow128[p] + (abyte ^ bXr[p]);
                    uint32_t t4[4], u4[4];
                    LDSM_X4(t4, sb + 32768 + o);
                    LDSM_X4(u4, sb + 40960 + o);
                    bh[2 * p][0] = t4[0]; bh[2 * p][1] = t4[2];
                    bh[2 * p + 1][0] = t4[1]; bh[2 * p + 1][1] = t4[3];
                    bl[2 * p][0] = u4[0]; bl[2 * p][1] = u4[2];
                    bl[2 * p + 1][0] = u4[1]; bl[2 * p + 1][1] = u4[3];
                }
#pragma unroll
                for (int nt = 0; nt < 4; nt++) {
                    MMA16816(accF[nt], aH, bh[nt]);
                    MMA16816(accF[nt], aH, bl[nt]);
                    MMA16816(accF[nt], aL, bh[nt]);
                }
            }
            if (needB) {
                uint32_t aH[4], aL[4];
                LDSM_X4(aH, sb + 16384 + oA);
                LDSM_X4(aL, sb + 24576 + oA);
                uint32_t bh[4][2], bl[4][2];
#pragma unroll
                for (int p = 0; p < 2; p++) {
                    uint32_t o = bRow128[p] + (abyte ^ bXr[p]);
                    uint32_t t4[4], u4[4];
                    LDSM_X4(t4, sb + 49152 + o);
                    LDSM_X4(u4, sb + 57344 + o);
                    bh[2 * p][0] = t4[0]; bh[2 * p][1] = t4[2];
                    bh[2 * p + 1][0] = t4[1]; bh[2 * p + 1][1] = t4[3];
                    bl[2 * p][0] = u4[0]; bl[2 * p][1] = u4[2];
                    bl[2 * p + 1][0] = u4[1]; bl[2 * p + 1][1] = u4[3];
                }
#pragma unroll
                for (int nt = 0; nt < 4; nt++) {
                    MMA16816(accB[nt], aH, bh[nt]);
                    MMA16816(accB[nt], aH, bl[nt]);
                    MMA16816(accB[nt], aL, bh[nt]);
                }
            }
        }

        uint32_t pH[2][4], pL[2][4];
#pragma unroll
        for (int nt = 0; nt < 4; nt++) {
            float ash[4];
#pragma unroll
            for (int q = 0; q < 4; q++) {
                int trow = t0 + mw * 16 + grp + (q >> 1) * 8;
                int scol = s0 + sw * 32 + nt * 8 + qp * 2 + (q & 1);
                float val;
                if (jt < it) val = accF[nt][q];
                else if (jt > it) val = accB[nt][q];
                else val = (scol > trow) ? accB[nt][q] : accF[nt][q];
                float a = fmaxf(val, 0.f);
                sA[q >> 1] += a;
                float as = (a > 0.f) ? __powf(a + 1e-12f, tau) : 0.f;
                sS[q >> 1] += as;
                ash[q] = as;
            }
            int kc = nt >> 1, half = nt & 1;
            pH[kc][half * 2]     = packsplit(ash[0], ash[1], &pL[kc][half * 2]);
            pH[kc][half * 2 + 1] = packsplit(ash[2], ash[3], &pL[kc][half * 2 + 1]);
        }

#pragma unroll
        for (int kc = 0; kc < 2; kc++) {
#pragma unroll
            for (int dblk = 0; dblk < 4; dblk++) {
                uint32_t db = dblk * 32 + hi16;
                uint32_t ov = vRow128[kc] + (db ^ vXr[kc]);
                uint32_t t4[4], u4[4];
                LDSM_X4_T(t4, sb + 65536 + ov);
                LDSM_X4_T(u4, sb + 73728 + ov);
                uint32_t bvh[2][2] = {{t4[0], t4[1]}, {t4[2], t4[3]}};
                uint32_t bvl[2][2] = {{u4[0], u4[1]}, {u4[2], u4[3]}};
#pragma unroll
                for (int x = 0; x < 2; x++) {
                    int nt = dblk * 2 + x;
                    MMA16816(accY[nt], pH[kc], bvh[x]);
                    MMA16816(accY[nt], pH[kc], bvl[x]);
                    MMA16816(accY[nt], pL[kc], bvh[x]);
                }
            }
        }
        __syncthreads();
    }

#pragma unroll
    for (int qh = 0; qh < 2; qh++) {
        float va = sA[qh], vs = sS[qh];
        va += __shfl_xor_sync(0xFFFFFFFFu, va, 1);
        va += __shfl_xor_sync(0xFFFFFFFFu, va, 2);
        vs += __shfl_xor_sync(0xFFFFFFFFu, vs, 1);
        vs += __shfl_xor_sync(0xFFFFFFFFu, vs, 2);
        if ((lane & 3) == 0) {
            int trow = mw * 16 + grp + qh * 8;
            atomicAdd(&redA[trow], va);
            atomicAdd(&redS[trow], vs);
        }
    }

    float* red = (float*)sm8;
    __syncthreads();
    if (sw == 1) {
#pragma unroll
        for (int nt = 0; nt < 8; nt++) {
            int r0 = mw * 16 + grp;
            int col = nt * 8 + qp * 2;
            *(float2*)&red[(r0)     * 64 + col] = make_float2(accY[nt][0], accY[nt][1]);
            *(float2*)&red[(r0 + 8) * 64 + col] = make_float2(accY[nt][2], accY[nt][3]);
        }
    }
    __syncthreads();
    if (sw == 0) {
        int r0 = mw * 16 + grp;
        int r1 = r0 + 8;
        float sc0 = fmaxf(redA[r0], 1e-12f) / fmaxf(redS[r0], 1e-12f);
        float sc1 = fmaxf(redA[r1], 1e-12f) / fmaxf(redS[r1], 1e-12f);
        float s0 = 0.f, q0 = 0.f, s1 = 0.f, q1 = 0.f;
#pragma unroll
        for (int nt = 0; nt < 8; nt++) {
            int col = nt * 8 + qp * 2;
            float2 o0 = *(float2*)&red[r0 * 64 + col];
            float2 o1 = *(float2*)&red[r1 * 64 + col];
            accY[nt][0] = (accY[nt][0] + o0.x) * sc0;
            accY[nt][1] = (accY[nt][1] + o0.y) * sc0;
            accY[nt][2] = (accY[nt][2] + o1.x) * sc1;
            accY[nt][3] = (accY[nt][3] + o1.y) * sc1;
            s0 += accY[nt][0] + accY[nt][1];
            q0 += accY[nt][0] * accY[nt][0] + accY[nt][1] * accY[nt][1];
            s1 += accY[nt][2] + accY[nt][3];
            q1 += accY[nt][2] * accY[nt][2] + accY[nt][3] * accY[nt][3];
        }
        s0 += __shfl_xor_sync(0xFFFFFFFFu, s0, 1);
        s0 += __shfl_xor_sync(0xFFFFFFFFu, s0, 2);
        q0 += __shfl_xor_sync(0xFFFFFFFFu, q0, 1);
        q0 += __shfl_xor_sync(0xFFFFFFFFu, q0, 2);
        s1 += __shfl_xor_sync(0xFFFFFFFFu, s1, 1);
        s1 += __shfl_xor_sync(0xFFFFFFFFu, s1, 2);
        q1 += __shfl_xor_sync(0xFFFFFFFFu, q1, 1);
        q1 += __shfl_xor_sync(0xFFFFFFFFu, q1, 2);
        float mu0 = s0 * (1.f / 64.f);
        float var0 = q0 * (1.f / 64.f) - mu0 * mu0;
        float inv0 = rsqrtf(var0 + 6.4e-4f);
        float mu1 = s1 * (1.f / 64.f);
        float var1 = q1 * (1.f / 64.f) - mu1 * mu1;
        float inv1 = rsqrtf(var1 + 6.4e-4f);
#pragma unroll
        for (int nt = 0; nt < 8; nt++) {
            int col = nt * 8 + qp * 2;
            int dch = (int)hb + col;
            float2 lg = *(const float2*)&ln_g[dch];
            float2 lb = *(const float2*)&ln_b[dch];
            float2 gg0 = *(const float2*)&g[(size_t)(t0 + r0) * 1024 + dch];
            float2 gg1 = *(const float2*)&g[(size_t)(t0 + r1) * 1024 + dch];
            float ox0 = ((accY[nt][0] - mu0) * inv0 * lg.x + lb.x) * gg0.x;
            float oy0 = ((accY[nt][1] - mu0) * inv0 * lg.y + lb.y) * gg0.y;
            float ox1 = ((accY[nt][2] - mu1) * inv1 * lg.x + lb.x) * gg1.x;
            float oy1 = ((accY[nt][3] - mu1) * inv1 * lg.y + lb.y) * gg1.y;
            __nv_bfloat162 hh, ll;
            split2(ox0, oy0, &hh, &ll);
            *(__nv_bfloat162*)(ygHi + (size_t)(t0 + r0) * 1024 + dch) = hh;
            *(__nv_bfloat162*)(ygLo + (size_t)(t0 + r0) * 1024 + dch) = ll;
            split2(ox1, oy1, &hh, &ll);
            *(__nv_bfloat162*)(ygHi + (size_t)(t0 + r1) * 1024 + dch) = hh;
            *(__nv_bfloat162*)(ygLo + (size_t)(t0 + r1) * 1024 + dch) = ll;
        }
    }
}

// ---------------- launch ----------------
extern "C" void kernel_launch(void* const* d_in, const int* in_sizes, int n_in,
                              void* d_out, int out_size) {
    const float* x          = (const float*)d_in[0];
    const float* maa_x      = (const float*)d_in[1];
    const float* maa_w      = (const float*)d_in[2];
    const float* maa_k      = (const float*)d_in[3];
    const float* maa_v      = (const float*)d_in[4];
    const float* maa_r      = (const float*)d_in[5];
    const float* maa_g      = (const float*)d_in[6];
    const float* maa_w1     = (const float*)d_in[7];
    const float* maa_w2     = (const float*)d_in[8];
    const float* time_decay = (const float*)d_in[9];
    const float* decay_w1   = (const float*)d_in[10];
    const float* decay_w2   = (const float*)d_in[11];
    const float* log_tau    = (const float*)d_in[12];
    const float* Wr         = (const float*)d_in[13];
    const float* Wk         = (const float*)d_in[14];
    const float* Wv         = (const float*)d_in[15];
    const float* Wg         = (const float*)d_in[16];
    const float* Wo         = (const float*)d_in[17];
    const float* ln_g       = (const float*)d_in[18];
    const float* ln_b       = (const float*)d_in[19];

    float* S = nullptr;
    cudaGetSymbolAddress((void**)&S, g_scratch);
    float* zb    = S + OFF_Z;
    float* xwb   = S + OFF_XW;
    float* rkvg  = S + OFF_RKVG;
    float* wb    = S + OFF_W;
    float* csb   = S + OFF_CS;
    float* xxxb  = S + OFF_XXX;
    float* wmidb = S + OFF_WMID;
    __nv_bfloat16* actHi = (__nv_bfloat16*)(S + OFF_ACTHI);
    __nv_bfloat16* actLo = (__nv_bfloat16*)(S + OFF_ACTLO);
    __nv_bfloat16* wtHi  = (__nv_bfloat16*)(S + OFF_WTHI);
    __nv_bfloat16* wtLo  = (__nv_bfloat16*)(S + OFF_WTLO);
    __nv_bfloat16* ygHi  = (__nv_bfloat16*)(S + OFF_YGHI);
    __nv_bfloat16* ygLo  = (__nv_bfloat16*)(S + OFF_YGLO);
    __nv_bfloat16* bfB   = (__nv_bfloat16*)(S + OFF_BF);

    int gemm_smem = 98304;
    cudaFuncSetAttribute(gemm_mma_k, cudaFuncAttributeMaxDynamicSharedMemorySize, gemm_smem);
    int attn_smem = 81920;
    cudaFuncSetAttribute(attn_mma_k, cudaFuncAttributeMaxDynamicSharedMemorySize, attn_smem);

    prep_k<<<(TD + 255) / 256, 256>>>(x, maa_x, zb);
    xxx_k<<<TTOK / 4, 320>>>(zb, maa_w1, xxxb);
    mix_k<<<TTOK / 4, 256>>>(x, xxxb, maa_w2,
                             maa_w, maa_k, maa_v, maa_r, maa_g, xwb, actHi, actLo);
    {
        dim3 grid(32, 32, 5);
        conv_wt_k<<<grid, 256>>>(Wr, Wk, Wv, Wg, Wo, wtHi, wtLo);
    }
    {
        dim3 grid(16, 16, 4);
        gemm_mma_k<<<grid, 256, gemm_smem>>>(actHi, actLo, wtHi, wtLo, rkvg, 3,
                                             bfB + (size_t)8 * TD, bfB + (size_t)9 * TD, 2);
    }
    decay1_k<<<TTOK / 8, 256>>>(xwb, decay_w1, wmidb);
    decay2_k<<<TTOK / 4, 256>>>(wmidb, decay_w2, time_decay, wb);
    cumsum_k<<<DDIM / 32, 1024>>>(wb, csb);
    premult_bf_k<<<(TD + 255) / 256, 256>>>(rkvg, rkvg + (size_t)TD, wb, csb, bfB);
    {
        dim3 grid(32, 16);
        attn_mma_k<<<grid, 256, attn_smem>>>(bfB, log_tau, rkvg + (size_t)3 * TD,
                                             ln_g, ln_b, ygHi, ygLo);
    }
    {
        dim3 grid(16, 16, 1);
        gemm_mma_k<<<grid, 256, gemm_smem>>>(ygHi, ygLo, wtHi + (size_t)4 * 1048576,
                                             wtLo + (size_t)4 * 1048576,
                                             (float*)d_out, -1, nullptr, nullptr, -1);
    }
}

// round 15
// speedup vs baseline: 1.2803x; 1.0987x over previous
#include <cuda_runtime.h>
#include <cuda_bf16.h>
#include <math.h>
#include <stdint.h>

#define TTOK 2048
#define DDIM 1024
#define TD (TTOK*DDIM)

// ---------------- scratch (static device memory; no allocations) ----------------
__device__ float g_scratch[68157440];

#define OFF_Z     ((size_t)1*TD)
#define OFF_XW    ((size_t)2*TD)
#define OFF_RKVG  ((size_t)7*TD)
#define OFF_W     ((size_t)11*TD)
#define OFF_CS    ((size_t)12*TD)
#define OFF_XXX   ((size_t)19*TD)
#define OFF_WMID  (OFF_XXX + (size_t)TTOK*160)
#define OFF_ACTHI ((size_t)20*TD)
#define OFF_ACTLO ((size_t)22*TD)
#define OFF_WTHI  ((size_t)24*TD)
#define OFF_WTLO  (OFF_WTHI + (size_t)2621440)
#define OFF_YGHI  (OFF_WTLO + (size_t)2621440)
#define OFF_YGLO  (OFF_YGHI + (size_t)(TD/2))
#define OFF_BF    (OFF_YGLO + (size_t)(TD/2))

// byte stride of one bf16 operand array
#define ARB ((size_t)TD * 2)

static __device__ __forceinline__ float clip60(float x) {
    return fminf(fmaxf(x, -60.f), 60.f);
}
static __device__ __forceinline__ uint32_t smem_u32(const void* p) {
    uint32_t a;
    asm("{ .reg .u64 t; cvta.to.shared.u64 t, %1; cvt.u32.u64 %0, t; }" : "=r"(a) : "l"(p));
    return a;
}

#define LDSM_X4(r, addr) \
    asm volatile("ldmatrix.sync.aligned.m8n8.x4.shared.b16 {%0,%1,%2,%3}, [%4];" \
                 : "=r"((r)[0]), "=r"((r)[1]), "=r"((r)[2]), "=r"((r)[3]) : "r"(addr))
#define LDSM_X4_T(r, addr) \
    asm volatile("ldmatrix.sync.aligned.m8n8.x4.trans.shared.b16 {%0,%1,%2,%3}, [%4];" \
                 : "=r"((r)[0]), "=r"((r)[1]), "=r"((r)[2]), "=r"((r)[3]) : "r"(addr))
#define MMA16816(d, a, b) \
    asm volatile("mma.sync.aligned.m16n8k16.row.col.f32.bf16.bf16.f32 " \
                 "{%0,%1,%2,%3}, {%4,%5,%6,%7}, {%8,%9}, {%0,%1,%2,%3};" \
                 : "+f"((d)[0]), "+f"((d)[1]), "+f"((d)[2]), "+f"((d)[3]) \
                 : "r"((a)[0]), "r"((a)[1]), "r"((a)[2]), "r"((a)[3]), \
                   "r"((b)[0]), "r"((b)[1]))
#define CPASYNC16(s, g) \
    asm volatile("cp.async.cg.shared.global [%0], [%1], 16;" :: "r"(s), "l"(g))
#define CPCOMMIT() asm volatile("cp.async.commit_group;" ::: "memory")
#define CPWAIT1()  asm volatile("cp.async.wait_group 1;" ::: "memory")
#define CPWAIT0()  asm volatile("cp.async.wait_group 0;" ::: "memory")
#define SWZ(o) ((o) ^ (((o) >> 3) & 0x70))

static __device__ __forceinline__ void split2(float a, float b,
                                              __nv_bfloat162* hi, __nv_bfloat162* lo) {
    __nv_bfloat162 h, l;
    h.x = __float2bfloat16(a);
    h.y = __float2bfloat16(b);
    l.x = __float2bfloat16(a - __bfloat162float(h.x));
    l.y = __float2bfloat16(b - __bfloat162float(h.y));
    *hi = h; *lo = l;
}
static __device__ __forceinline__ uint32_t packsplit(float a, float b, uint32_t* lo) {
    __nv_bfloat162 h, l;
    split2(a, b, &h, &l);
    *lo = *(uint32_t*)&l;
    return *(uint32_t*)&h;
}

// ---------------- 1. token shift -> z only ----------------
__global__ __launch_bounds__(256) void prep_k(const float* __restrict__ x,
                                              const float* __restrict__ maa_x,
                                              float* __restrict__ z) {
    int idx = blockIdx.x * 256 + threadIdx.x;
    if (idx >= TD) return;
    int t = idx >> 10;
    int d = idx & 1023;
    float xv = x[idx];
    float prev = (t > 0) ? x[idx - 1024] : 0.f;
    float nxt  = (t < TTOK - 1) ? x[idx + 1024] : 0.f;
    float dxv = 0.5f * (prev + nxt) - xv;
    z[idx] = xv + dxv * maa_x[d];
}

// ---------------- 2. xxx = tanh(z @ maa_w1): 320 thr, split-K ----------------
__global__ __launch_bounds__(320) void xxx_k(const float* __restrict__ z,
                                             const float* __restrict__ w1,
                                             float* __restrict__ xxx) {
    __shared__ float zs[4][1024];
    __shared__ float part[2][4][160];
    int t0 = blockIdx.x * 4;
    int tid = threadIdx.x;
    for (int i = tid; i < 1024; i += 320) {
        int r = i >> 8, c4 = (i & 255) * 4;
        *(float4*)&zs[r][c4] = *(const float4*)(z + (size_t)(t0 + r) * 1024 + c4);
    }
    __syncthreads();
    int out = (tid < 160) ? tid : (tid - 160);
    int kh = (tid < 160) ? 0 : 1;
    int kb = kh * 512;
    float acc[4] = {0.f, 0.f, 0.f, 0.f};
    for (int dd = 0; dd < 512; dd++) {
        int d = kb + dd;
        float w = w1[d * 160 + out];
        acc[0] += zs[0][d] * w;
        acc[1] += zs[1][d] * w;
        acc[2] += zs[2][d] * w;
        acc[3] += zs[3][d] * w;
    }
#pragma unroll
    for (int r = 0; r < 4; r++) part[kh][r][out] = acc[r];
    __syncthreads();
    if (tid < 160) {
#pragma unroll
        for (int r = 0; r < 4; r++)
            xxx[(size_t)(t0 + r) * 160 + tid] =
                tanhf(part[0][r][tid] + part[1][r][tid]);
    }
}

// ---------------- 3. mixer: dx recomputed inline ----------------
__global__ __launch_bounds__(256) void mix_k(const float* __restrict__ x,
                                             const float* __restrict__ xxx,
                                             const float* __restrict__ w2,
                                             const float* __restrict__ maa_w,
                                             const float* __restrict__ maa_k,
                                             const float* __restrict__ maa_v,
                                             const float* __restrict__ maa_r,
                                             const float* __restrict__ maa_g,
                                             float* __restrict__ xw,
                                             __nv_bfloat16* __restrict__ actHi,
                                             __nv_bfloat16* __restrict__ actLo) {
    __shared__ float xs[4][160];
    int t0 = blockIdx.x * 4;
    int tid = threadIdx.x;
    for (int i = tid; i < 640; i += 256) {
        int r = i / 160, c = i - r * 160;
        xs[r][c] = xxx[(size_t)(t0 + r) * 160 + c];
    }
    __syncthreads();
    int d = tid * 4;
    float4 xv[4], dxv[4];
#pragma unroll
    for (int r = 0; r < 4; r++) {
        int t = t0 + r;
        xv[r] = *(const float4*)(x + (size_t)t * 1024 + d);
        float4 pv = (t > 0) ? *(const float4*)(x + (size_t)(t - 1) * 1024 + d)
                            : make_float4(0.f, 0.f, 0.f, 0.f);
        float4 nv = (t < TTOK - 1) ? *(const float4*)(x + (size_t)(t + 1) * 1024 + d)
                                   : make_float4(0.f, 0.f, 0.f, 0.f);
        dxv[r].x = 0.5f * (pv.x + nv.x) - xv[r].x;
        dxv[r].y = 0.5f * (pv.y + nv.y) - xv[r].y;
        dxv[r].z = 0.5f * (pv.z + nv.z) - xv[r].z;
        dxv[r].w = 0.5f * (pv.w + nv.w) - xv[r].w;
    }
#pragma unroll
    for (int f = 0; f < 5; f++) {
        float4 acc[4];
#pragma unroll
        for (int r = 0; r < 4; r++) acc[r] = make_float4(0.f, 0.f, 0.f, 0.f);
        for (int mi = 0; mi < 32; mi++) {
            float4 w = *(const float4*)(w2 + (size_t)(f * 32 + mi) * 1024 + d);
#pragma unroll
            for (int r = 0; r < 4; r++) {
                float s = xs[r][f * 32 + mi];
                acc[r].x += s * w.x; acc[r].y += s * w.y;
                acc[r].z += s * w.z; acc[r].w += s * w.w;
            }
        }
        const float* maa = (f == 0) ? maa_w : (f == 1) ? maa_k : (f == 2) ? maa_v
                         : (f == 3) ? maa_r : maa_g;
        float4 mv = *(const float4*)(maa + d);
        int slot = (f == 3) ? 0 : (f == 1) ? 1 : (f == 2) ? 2 : 3;
#pragma unroll
        for (int r = 0; r < 4; r++) {
            float4 o;
            o.x = xv[r].x + dxv[r].x * (mv.x + acc[r].x);
            o.y = xv[r].y + dxv[r].y * (mv.y + acc[r].y);
            o.z = xv[r].z + dxv[r].z * (mv.z + acc[r].z);
            o.w = xv[r].w + dxv[r].w * (mv.w + acc[r].w);
            if (f == 0) {
                *(float4*)(xw + (size_t)(t0 + r) * 1024 + d) = o;
            } else {
                size_t ofs = (size_t)slot * TD + (size_t)(t0 + r) * 1024 + d;
                __nv_bfloat162 h0, l0, h1, l1;
                split2(o.x, o.y, &h0, &l0);
                split2(o.z, o.w, &h1, &l1);
                *(__nv_bfloat162*)(actHi + ofs)     = h0;
                *(__nv_bfloat162*)(actHi + ofs + 2) = h1;
                *(__nv_bfloat162*)(actLo + ofs)     = l0;
                *(__nv_bfloat162*)(actLo + ofs + 2) = l1;
            }
        }
    }
}

// ---------------- weight transpose + split ----------------
__global__ __launch_bounds__(256) void conv_wt_k(const float* __restrict__ W0,
                                                 const float* __restrict__ W1,
                                                 const float* __restrict__ W2,
                                                 const float* __restrict__ W3,
                                                 const float* __restrict__ W4,
                                                 __nv_bfloat16* __restrict__ hi,
                                                 __nv_bfloat16* __restrict__ lo) {
    __shared__ float tile[32][33];
    int z = blockIdx.z;
    const float* W = (z == 0) ? W0 : (z == 1) ? W1 : (z == 2) ? W2 : (z == 3) ? W3 : W4;
    int k0 = blockIdx.x * 32, n0 = blockIdx.y * 32;
    int tx = threadIdx.x & 31, ty = threadIdx.x >> 5;
#pragma unroll
    for (int i = 0; i < 32; i += 8)
        tile[ty + i][tx] = W[(size_t)(k0 + ty + i) * 1024 + n0 + tx];
    __syncthreads();
    size_t base = (size_t)z * 1048576;
#pragma unroll
    for (int i = 0; i < 32; i += 8) {
        float v = tile[tx][ty + i];
        size_t o = base + (size_t)(n0 + ty + i) * 1024 + k0 + tx;
        __nv_bfloat16 h = __float2bfloat16(v);
        hi[o] = h;
        lo[o] = __float2bfloat16(v - __bfloat162float(h));
    }
}

// ---------------- mma.sync split-bf16 GEMM: 128x64 tile, occ 2, strength-reduced ----------------
__global__ __launch_bounds__(256, 2)
void gemm_mma_k(const __nv_bfloat16* __restrict__ aHi,
                const __nv_bfloat16* __restrict__ aLo,
                const __nv_bfloat16* __restrict__ bHi,
                const __nv_bfloat16* __restrict__ bLo,
                float* __restrict__ C, int siluZ,
                __nv_bfloat16* __restrict__ vHi,
                __nv_bfloat16* __restrict__ vLo, int vz) {
    extern __shared__ unsigned char smraw[];
    const int tid = threadIdx.x;
    const int z = blockIdx.z;
    const int bm = blockIdx.y * 128;
    const int bn = blockIdx.x * 64;
    float* Cz = C + (size_t)z * TD;

    const uint32_t sbase = smem_u32(smraw);
    const int w = tid >> 5, lane = tid & 31;
    const int mw = w >> 1, nw = w & 1;

    const int ch16 = (tid & 7) * 16;
    const int arow = tid >> 3;
    const char* gA[2] = {
        (const char*)(aHi + (size_t)z * TD) + (size_t)(bm + arow) * 2048 + ch16,
        (const char*)(aLo + (size_t)z * TD) + (size_t)(bm + arow) * 2048 + ch16 };
    const char* gB[2] = {
        (const char*)(bHi + (size_t)z * 1048576) + (size_t)(bn + arow) * 2048 + ch16,
        (const char*)(bLo + (size_t)z * 1048576) + (size_t)(bn + arow) * 2048 + ch16 };
    const uint32_t swb = arow * 128 + (ch16 ^ ((arow & 7) << 4));

    float acc[2][4][4];
#pragma unroll
    for (int mt = 0; mt < 2; mt++)
#pragma unroll
        for (int nt = 0; nt < 4; nt++)
#pragma unroll
            for (int q = 0; q < 4; q++) acc[mt][nt][q] = 0.f;

    auto issue = [&](int c) {
        uint32_t stg = sbase + (c & 1) * 49152;
        uint32_t cofs = (uint32_t)c * 128;
#pragma unroll
        for (int jj = 0; jj < 8; jj++) {
            int tile = jj >> 2, sub = jj & 3;
            CPASYNC16(stg + tile * 16384 + swb + sub * 4096,
                      gA[tile] + sub * 65536 + cofs);
        }
#pragma unroll
        for (int jb = 0; jb < 4; jb++) {
            int tile = jb >> 1, sub = jb & 1;
            CPASYNC16(stg + 32768 + tile * 8192 + swb + sub * 4096,
                      gB[tile] + sub * 65536 + cofs);
        }
        CPCOMMIT();
    };

    uint32_t aRow128[2], aXr[2], bRow128[2], bXr[2];
    {
        int l15 = lane & 15;
#pragma unroll
        for (int mt = 0; mt < 2; mt++) {
            int r = mw * 32 + mt * 16 + l15;
            aRow128[mt] = r * 128;
            aXr[mt] = (r & 7) << 4;
        }
#pragma unroll
        for (int p = 0; p < 2; p++) {
            int r = nw * 32 + p * 16 + l15;
            bRow128[p] = r * 128;
            bXr[p] = (r & 7) << 4;
        }
    }
    const uint32_t hi16 = (lane >> 4) * 16;

    issue(0);
    issue(1);

    for (int c = 0; c < 16; c++) {
        if (c < 15) CPWAIT1(); else CPWAIT0();
        __syncthreads();
        uint32_t st = sbase + (c & 1) * 49152;
#pragma unroll
        for (int kk = 0; kk < 4; kk++) {
            uint32_t abyte = kk * 32 + hi16;
            uint32_t ah[2][4], al[2][4];
#pragma unroll
            for (int mt = 0; mt < 2; mt++) {
                uint32_t o = aRow128[mt] + (abyte ^ aXr[mt]);
                LDSM_X4(ah[mt], st + o);
                LDSM_X4(al[mt], st + 16384 + o);
            }
            uint32_t bh[4][2], bl[4][2];
#pragma unroll
            for (int p = 0; p < 2; p++) {
                uint32_t o = bRow128[p] + (abyte ^ bXr[p]);
                uint32_t t4[4];
                LDSM_X4(t4, st + 32768 + o);
                bh[2 * p][0] = t4[0]; bh[2 * p][1] = t4[2];
                bh[2 * p + 1][0] = t4[1]; bh[2 * p + 1][1] = t4[3];
                LDSM_X4(t4, st + 40960 + o);
                bl[2 * p][0] = t4[0]; bl[2 * p][1] = t4[2];
                bl[2 * p + 1][0] = t4[1]; bl[2 * p + 1][1] = t4[3];
            }
#pragma unroll
            for (int mt = 0; mt < 2; mt++)
#pragma unroll
                for (int nt = 0; nt < 4; nt++) {
                    MMA16816(acc[mt][nt], ah[mt], bh[nt]);
                    MMA16816(acc[mt][nt], ah[mt], bl[nt]);
                    MMA16816(acc[mt][nt], al[mt], bh[nt]);
                }
        }
        __syncthreads();
        if (c + 2 < 16) issue(c + 2);
    }

    bool silu = (z == siluZ);
    bool isv = (z == vz);
    int r0 = bm + mw * 32, c0 = bn + nw * 32;
#pragma unroll
    for (int mt = 0; mt < 2; mt++)
#pragma unroll
        for (int nt = 0; nt < 4; nt++) {
            float* d = acc[mt][nt];
            int row = r0 + mt * 16 + (lane >> 2);
            int col = c0 + nt * 8 + (lane & 3) * 2;
            if (isv) {
                __nv_bfloat162 h, l;
                split2(d[0], d[1], &h, &l);
                *(__nv_bfloat162*)(vHi + (size_t)row * 1024 + col) = h;
                *(__nv_bfloat162*)(vLo + (size_t)row * 1024 + col) = l;
                split2(d[2], d[3], &h, &l);
                *(__nv_bfloat162*)(vHi + (size_t)(row + 8) * 1024 + col) = h;
                *(__nv_bfloat162*)(vLo + (size_t)(row + 8) * 1024 + col) = l;
            } else {
                if (silu) {
#pragma unroll
                    for (int q = 0; q < 4; q++) d[q] = d[q] / (1.f + expf(-d[q]));
                }
                *(float2*)&Cz[(size_t)row * 1024 + col]       = make_float2(d[0], d[1]);
                *(float2*)&Cz[(size_t)(row + 8) * 1024 + col] = make_float2(d[2], d[3]);
            }
        }
}

// ---------------- 5. decay MLP stage 1 ----------------
__global__ __launch_bounds__(256) void decay1_k(const float* __restrict__ xw,
                                                const float* __restrict__ dw1,
                                                float* __restrict__ wmid) {
    __shared__ float xs[8][1024];
    __shared__ float part[4][64][8];
    int t0 = blockIdx.x * 8;
    int tid = threadIdx.x;
    for (int i = tid; i < 8 * 256; i += 256) {
        int r = i >> 8;
        int c4 = (i & 255) * 4;
        *(float4*)(&xs[r][c4]) = *(const float4*)(xw + (size_t)(t0 + r) * 1024 + c4);
    }
    __syncthreads();
    int n = tid & 63;
    int kq = tid >> 6;
    int kbase = kq * 256;
    float acc[8] = {0.f, 0.f, 0.f, 0.f, 0.f, 0.f, 0.f, 0.f};
    for (int dd = 0; dd < 256; dd++) {
        int d = kbase + dd;
        float w = dw1[d * 64 + n];
#pragma unroll
        for (int r = 0; r < 8; r++) acc[r] += xs[r][d] * w;
    }
#pragma unroll
    for (int r = 0; r < 8; r++) part[kq][n][r] = acc[r];
    __syncthreads();
    for (int i = tid; i < 512; i += 256) {
        int nn = i & 63, r = i >> 6;
        float s = part[0][nn][r] + part[1][nn][r] + part[2][nn][r] + part[3][nn][r];
        wmid[(size_t)(t0 + r) * 64 + nn] = tanhf(s);
    }
}

// ---------------- 6. decay MLP stage 2 ----------------
__global__ __launch_bounds__(256) void decay2_k(const float* __restrict__ wmid,
                                                const float* __restrict__ dw2,
                                                const float* __restrict__ td,
                                                float* __restrict__ w) {
    __shared__ float ws[4][64];
    int t0 = blockIdx.x * 4;
    int tid = threadIdx.x;
    {
        int r = tid >> 6, c = tid & 63;
        ws[r][c] = wmid[(size_t)(t0 + r) * 64 + c];
    }
    __syncthreads();
    int d = tid * 4;
    float4 tdv = *(const float4*)(td + d);
    float4 acc[4];
#pragma unroll
    for (int r = 0; r < 4; r++) acc[r] = tdv;
    for (int j = 0; j < 64; j++) {
        float4 wv = *(const float4*)(dw2 + (size_t)j * 1024 + d);
#pragma unroll
        for (int r = 0; r < 4; r++) {
            float s = ws[r][j];
            acc[r].x += s * wv.x; acc[r].y += s * wv.y;
            acc[r].z += s * wv.z; acc[r].w += s * wv.w;
        }
    }
#pragma unroll
    for (int r = 0; r < 4; r++)
        *(float4*)(w + (size_t)(t0 + r) * 1024 + d) = acc[r];
}

// ---------------- 7. per-channel cumsum ----------------
__global__ __launch_bounds__(1024) void cumsum_k(const float* __restrict__ w,
                                                 float* __restrict__ cs) {
    __shared__ float seg[32][33];
    int c = threadIdx.x & 31;
    int j = threadIdx.x >> 5;
    int d = blockIdx.x * 32 + c;
    int tb = j * 64;
    float s = 0.f;
    for (int t = 0; t < 64; t++)
        s -= expf(w[(size_t)(tb + t) * 1024 + d]);
    seg[j][c] = s;
    __syncthreads();
    if (j == 0) {
        float run = 0.f;
        for (int jj = 0; jj < 32; jj++) {
            float tmp = seg[jj][c];
            seg[jj][c] = run;
            run += tmp;
        }
    }
    __syncthreads();
    float run = seg[j][c];
    for (int t = 0; t < 64; t++) {
        run -= expf(w[(size_t)(tb + t) * 1024 + d]);
        cs[(size_t)(tb + t) * 1024 + d] = run;
    }
}

// ---------------- 8. premult -> bf16 hi/lo (2 elems/thread, bf162 stores) ----------------
__global__ __launch_bounds__(256) void premult_bf_k(const float* __restrict__ r,
                                                    const float* __restrict__ k,
                                                    const float* __restrict__ w,
                                                    const float* __restrict__ cs,
                                                    __nv_bfloat16* __restrict__ bfB) {
    int p = blockIdx.x * 256 + threadIdx.x;
    int idx = p * 2;
    if (idx >= TD) return;
    int d = idx & 1023;
    size_t midoff = (size_t)(TTOK / 2) * 1024 + d;
    float2 csv = *(const float2*)&cs[idx];
    float2 csm = *(const float2*)&cs[midoff];
    float2 wv  = *(const float2*)&w[idx];
    float2 wm  = *(const float2*)&w[midoff];
    float wh0  = -expf(wv.x), wh1 = -expf(wv.y);
    float whm0 = -expf(wm.x), whm1 = -expf(wm.y);
    float csf0 = clip60(csv.x - csm.x), csf1 = clip60(csv.y - csm.y);
    float csb0 = clip60((csv.x - wh0) - (csm.x - whm0));
    float csb1 = clip60((csv.y - wh1) - (csm.y - whm1));
    float2 rv = *(const float2*)&r[idx];
    float2 kv = *(const float2*)&k[idx];
    float v0[4], v1[4];
    v0[0] = rv.x * expf(csf0);   v1[0] = rv.y * expf(csf1);
    v0[1] = kv.x * expf(-csf0);  v1[1] = kv.y * expf(-csf1);
    v0[2] = rv.x * expf(-csb0);  v1[2] = rv.y * expf(-csb1);
    v0[3] = kv.x * expf(csb0);   v1[3] = kv.y * expf(csb1);
#pragma unroll
    for (int j = 0; j < 4; j++) {
        __nv_bfloat162 h, l;
        split2(v0[j], v1[j], &h, &l);
        *(__nv_bfloat162*)(bfB + (size_t)(2 * j) * TD + idx) = h;
        *(__nv_bfloat162*)(bfB + (size_t)(2 * j + 1) * TD + idx) = l;
    }
}

// ---------------- 9. attention + fused groupnorm/gate, strength-reduced loads ----------------
__global__ __launch_bounds__(256, 2) void attn_mma_k(const __nv_bfloat16* __restrict__ bfB,
                                                     const float* __restrict__ log_tau,
                                                     const float* __restrict__ g,
                                                     const float* __restrict__ ln_g,
                                                     const float* __restrict__ ln_b,
                                                     __nv_bfloat16* __restrict__ ygHi,
                                                     __nv_bfloat16* __restrict__ ygLo) {
    extern __shared__ unsigned char sm8[];
    __shared__ float redA[64], redS[64];
    const uint32_t sb = smem_u32(sm8);
    int h = blockIdx.y, it = blockIdx.x;
    int t0 = it * 64;
    int tid = threadIdx.x, w = tid >> 5, lane = tid & 31;
    int mw = w >> 1, sw = w & 1;
    size_t hb = (size_t)h * 64;
    float tau = expf(log_tau[h]);
    int grp = lane >> 2, qp = lane & 3;

    if (tid < 64) { redA[tid] = 0.f; redS[tid] = 0.f; }

    // ---- strength-reduced load addressing ----
    const int row0 = tid >> 3;
    const uint32_t ch16 = (tid & 7) * 16;
    const uint32_t swoff = row0 * 128 + (ch16 ^ ((row0 & 7) << 4));
    const char* gbase = (const char*)bfB + (size_t)row0 * 2048 + hb * 2 + ch16;

    // r tiles: arrays {0,1,4,5} -> smem 0..32K
    {
        const char* gt = gbase + (size_t)t0 * 2048;
        CPASYNC16(sb + swoff,                  gt);
        CPASYNC16(sb + swoff + 4096,           gt + 65536);
        CPASYNC16(sb + 8192 + swoff,           gt + 1 * ARB);
        CPASYNC16(sb + 8192 + swoff + 4096,    gt + 1 * ARB + 65536);
        CPASYNC16(sb + 16384 + swoff,          gt + 4 * ARB);
        CPASYNC16(sb + 16384 + swoff + 4096,   gt + 4 * ARB + 65536);
        CPASYNC16(sb + 24576 + swoff,          gt + 5 * ARB);
        CPASYNC16(sb + 24576 + swoff + 4096,   gt + 5 * ARB + 65536);
    }
    CPCOMMIT();
    CPWAIT0();
    __syncthreads();

    const uint32_t dstk = sb + 32768 + swoff;

    // compute addressing (closed-form swizzle)
    const uint32_t hi16 = (lane >> 4) * 16;
    uint32_t aRow128, aXr;
    {
        int r = mw * 16 + (lane & 15);
        aRow128 = r * 128; aXr = (r & 7) << 4;
    }
    uint32_t bRow128[2], bXr[2];
#pragma unroll
    for (int p = 0; p < 2; p++) {
        int r = sw * 32 + p * 16 + (lane & 15);
        bRow128[p] = r * 128; bXr[p] = (r & 7) << 4;
    }
    uint32_t vRow128[2], vXr[2];
#pragma unroll
    for (int kc = 0; kc < 2; kc++) {
        int r = sw * 32 + kc * 16 + (lane & 15);
        vRow128[kc] = r * 128; vXr[kc] = (r & 7) << 4;
    }

    float accY[8][4];
#pragma unroll
    for (int nt = 0; nt < 8; nt++)
#pragma unroll
        for (int q = 0; q < 4; q++) accY[nt][q] = 0.f;
    float sA[2] = {0.f, 0.f};
    float sS[2] = {0.f, 0.f};

    for (int jt = 0; jt < 32; jt++) {
        int s0 = jt * 64;
        bool needF = (jt <= it);
        bool needB = (jt >= it);
        {
            const char* gs = gbase + (size_t)s0 * 2048;
            if (needF) {
                CPASYNC16(dstk,                  gs + 2 * ARB);
                CPASYNC16(dstk + 4096,           gs + 2 * ARB + 65536);
                CPASYNC16(dstk + 8192,           gs + 3 * ARB);
                CPASYNC16(dstk + 8192 + 4096,    gs + 3 * ARB + 65536);
            }
            if (needB) {
                CPASYNC16(dstk + 16384,          gs + 6 * ARB);
                CPASYNC16(dstk + 16384 + 4096,   gs + 6 * ARB + 65536);
                CPASYNC16(dstk + 24576,          gs + 7 * ARB);
                CPASYNC16(dstk + 24576 + 4096,   gs + 7 * ARB + 65536);
            }
            CPASYNC16(dstk + 32768,              gs + 8 * ARB);
            CPASYNC16(dstk + 32768 + 4096,       gs + 8 * ARB + 65536);
            CPASYNC16(dstk + 40960,              gs + 9 * ARB);
            CPASYNC16(dstk + 40960 + 4096,       gs + 9 * ARB + 65536);
        }
        CPCOMMIT();
        CPWAIT0();
        __syncthreads();

        float accF[4][4], accB[4][4];
#pragma unroll
        for (int nt = 0; nt < 4; nt++)
#pragma unroll
            for (int q = 0; q < 4; q++) { accF[nt][q] = 0.f; accB[nt][q] = 0.f; }

#pragma unroll
        for (int ks = 0; ks < 4; ks++) {
            uint32_t abyte = ks * 32 + hi16;
            uint32_t oA = aRow128 + (abyte ^ aXr);
            if (needF) {
                uint32_t aH[4], aL[4];
                LDSM_X4(aH, sb + oA);
                LDSM_X4(aL, sb + 8192 + oA);
                uint32_t bh[4][2], bl[4][2];
#pragma unroll
                for (int p = 0; p < 2; p++) {
                    uint32_t o = bRow128[p] + (abyte ^ bXr[p]);
                    uint32_t t4[4], u4[4];
                    LDSM_X4(t4, sb + 32768 + o);
                    LDSM_X4(u4, sb + 40960 + o);
                    bh[2 * p][0] = t4[0]; bh[2 * p][1] = t4[2];
                    bh[2 * p + 1][0] = t4[1]; bh[2 * p + 1][1] = t4[3];
                    bl[2 * p][0] = u4[0]; bl[2 * p][1] = u4[2];
                    bl[2 * p + 1][0] = u4[1]; bl[2 * p + 1][1] = u4[3];
                }
#pragma unroll
                for (int nt = 0; nt < 4; nt++) {
                    MMA16816(accF[nt], aH, bh[nt]);
                    MMA16816(accF[nt], aH, bl[nt]);
                    MMA16816(accF[nt], aL, bh[nt]);
                }
            }
            if (needB) {
                uint32_t aH[4], aL[4];
                LDSM_X4(aH, sb + 16384 + oA);
                LDSM_X4(aL, sb + 24576 + oA);
                uint32_t bh[4][2], bl[4][2];
#pragma unroll
                for (int p = 0; p < 2; p++) {
                    uint32_t o = bRow128[p] + (abyte ^ bXr[p]);
                    uint32_t t4[4], u4[4];
                    LDSM_X4(t4, sb + 49152 + o);
                    LDSM_X4(u4, sb + 57344 + o);
                    bh[2 * p][0] = t4[0]; bh[2 * p][1] = t4[2];
                    bh[2 * p + 1][0] = t4[1]; bh[2 * p + 1][1] = t4[3];
                    bl[2 * p][0] = u4[0]; bl[2 * p][1] = u4[2];
                    bl[2 * p + 1][0] = u4[1]; bl[2 * p + 1][1] = u4[3];
                }
#pragma unroll
                for (int nt = 0; nt < 4; nt++) {
                    MMA16816(accB[nt], aH, bh[nt]);
                    MMA16816(accB[nt], aH, bl[nt]);
                    MMA16816(accB[nt], aL, bh[nt]);
                }
            }
        }

        uint32_t pH[2][4], pL[2][4];
#pragma unroll
        for (int nt = 0; nt < 4; nt++) {
            float ash[4];
#pragma unroll
            for (int q = 0; q < 4; q++) {
                int trow = t0 + mw * 16 + grp + (q >> 1) * 8;
                int scol = s0 + sw * 32 + nt * 8 + qp * 2 + (q & 1);
                float val;
                if (jt < it) val = accF[nt][q];
                else if (jt > it) val = accB[nt][q];
                else val = (scol > trow) ? accB[nt][q] : accF[nt][q];
                float a = fmaxf(val, 0.f);
                sA[q >> 1] += a;
                float as = (a > 0.f) ? __powf(a + 1e-12f, tau) : 0.f;
                sS[q >> 1] += as;
                ash[q] = as;
            }
            int kc = nt >> 1, half = nt & 1;
            pH[kc][half * 2]     = packsplit(ash[0], ash[1], &pL[kc][half * 2]);
            pH[kc][half * 2 + 1] = packsplit(ash[2], ash[3], &pL[kc][half * 2 + 1]);
        }

#pragma unroll
        for (int kc = 0; kc < 2; kc++) {
#pragma unroll
            for (int dblk = 0; dblk < 4; dblk++) {
                uint32_t db = dblk * 32 + hi16;
                uint32_t ov = vRow128[kc] + (db ^ vXr[kc]);
                uint32_t t4[4], u4[4];
                LDSM_X4_T(t4, sb + 65536 + ov);
                LDSM_X4_T(u4, sb + 73728 + ov);
                uint32_t bvh[2][2] = {{t4[0], t4[1]}, {t4[2], t4[3]}};
                uint32_t bvl[2][2] = {{u4[0], u4[1]}, {u4[2], u4[3]}};
#pragma unroll
                for (int x = 0; x < 2; x++) {
                    int nt = dblk * 2 + x;
                    MMA16816(accY[nt], pH[kc], bvh[x]);
                    MMA16816(accY[nt], pH[kc], bvl[x]);
                    MMA16816(accY[nt], pL[kc], bvh[x]);
                }
            }
        }
        __syncthreads();
    }

#pragma unroll
    for (int qh = 0; qh < 2; qh++) {
        float va = sA[qh], vs = sS[qh];
        va += __shfl_xor_sync(0xFFFFFFFFu, va, 1);
        va += __shfl_xor_sync(0xFFFFFFFFu, va, 2);
        vs += __shfl_xor_sync(0xFFFFFFFFu, vs, 1);
        vs += __shfl_xor_sync(0xFFFFFFFFu, vs, 2);
        if ((lane & 3) == 0) {
            int trow = mw * 16 + grp + qh * 8;
            atomicAdd(&redA[trow], va);
            atomicAdd(&redS[trow], vs);
        }
    }

    float* red = (float*)sm8;
    __syncthreads();
    if (sw == 1) {
#pragma unroll
        for (int nt = 0; nt < 8; nt++) {
            int r0 = mw * 16 + grp;
            int col = nt * 8 + qp * 2;
            *(float2*)&red[(r0)     * 64 + col] = make_float2(accY[nt][0], accY[nt][1]);
            *(float2*)&red[(r0 + 8) * 64 + col] = make_float2(accY[nt][2], accY[nt][3]);
        }
    }
    __syncthreads();
    if (sw == 0) {
        int r0 = mw * 16 + grp;
        int r1 = r0 + 8;
        float sc0 = fmaxf(redA[r0], 1e-12f) / fmaxf(redS[r0], 1e-12f);
        float sc1 = fmaxf(redA[r1], 1e-12f) / fmaxf(redS[r1], 1e-12f);
        float s0 = 0.f, q0 = 0.f, s1 = 0.f, q1 = 0.f;
#pragma unroll
        for (int nt = 0; nt < 8; nt++) {
            int col = nt * 8 + qp * 2;
            float2 o0 = *(float2*)&red[r0 * 64 + col];
            float2 o1 = *(float2*)&red[r1 * 64 + col];
            accY[nt][0] = (accY[nt][0] + o0.x) * sc0;
            accY[nt][1] = (accY[nt][1] + o0.y) * sc0;
            accY[nt][2] = (accY[nt][2] + o1.x) * sc1;
            accY[nt][3] = (accY[nt][3] + o1.y) * sc1;
            s0 += accY[nt][0] + accY[nt][1];
            q0 += accY[nt][0] * accY[nt][0] + accY[nt][1] * accY[nt][1];
            s1 += accY[nt][2] + accY[nt][3];
            q1 += accY[nt][2] * accY[nt][2] + accY[nt][3] * accY[nt][3];
        }
        s0 += __shfl_xor_sync(0xFFFFFFFFu, s0, 1);
        s0 += __shfl_xor_sync(0xFFFFFFFFu, s0, 2);
        q0 += __shfl_xor_sync(0xFFFFFFFFu, q0, 1);
        q0 += __shfl_xor_sync(0xFFFFFFFFu, q0, 2);
        s1 += __shfl_xor_sync(0xFFFFFFFFu, s1, 1);
        s1 += __shfl_xor_sync(0xFFFFFFFFu, s1, 2);
        q1 += __shfl_xor_sync(0xFFFFFFFFu, q1, 1);
        q1 += __shfl_xor_sync(0xFFFFFFFFu, q1, 2);
        float mu0 = s0 * (1.f / 64.f);
        float var0 = q0 * (1.f / 64.f) - mu0 * mu0;
        float inv0 = rsqrtf(var0 + 6.4e-4f);
        float mu1 = s1 * (1.f / 64.f);
        float var1 = q1 * (1.f / 64.f) - mu1 * mu1;
        float inv1 = rsqrtf(var1 + 6.4e-4f);
#pragma unroll
        for (int nt = 0; nt < 8; nt++) {
            int col = nt * 8 + qp * 2;
            int dch = (int)hb + col;
            float2 lg = *(const float2*)&ln_g[dch];
            float2 lb = *(const float2*)&ln_b[dch];
            float2 gg0 = *(const float2*)&g[(size_t)(t0 + r0) * 1024 + dch];
            float2 gg1 = *(const float2*)&g[(size_t)(t0 + r1) * 1024 + dch];
            float ox0 = ((accY[nt][0] - mu0) * inv0 * lg.x + lb.x) * gg0.x;
            float oy0 = ((accY[nt][1] - mu0) * inv0 * lg.y + lb.y) * gg0.y;
            float ox1 = ((accY[nt][2] - mu1) * inv1 * lg.x + lb.x) * gg1.x;
            float oy1 = ((accY[nt][3] - mu1) * inv1 * lg.y + lb.y) * gg1.y;
            __nv_bfloat162 hh, ll;
            split2(ox0, oy0, &hh, &ll);
            *(__nv_bfloat162*)(ygHi + (size_t)(t0 + r0) * 1024 + dch) = hh;
            *(__nv_bfloat162*)(ygLo + (size_t)(t0 + r0) * 1024 + dch) = ll;
            split2(ox1, oy1, &hh, &ll);
            *(__nv_bfloat162*)(ygHi + (size_t)(t0 + r1) * 1024 + dch) = hh;
            *(__nv_bfloat162*)(ygLo + (size_t)(t0 + r1) * 1024 + dch) = ll;
        }
    }
}

// ---------------- launch ----------------
extern "C" void kernel_launch(void* const* d_in, const int* in_sizes, int n_in,
                              void* d_out, int out_size) {
    const float* x          = (const float*)d_in[0];
    const float* maa_x      = (const float*)d_in[1];
    const float* maa_w      = (const float*)d_in[2];
    const float* maa_k      = (const float*)d_in[3];
    const float* maa_v      = (const float*)d_in[4];
    const float* maa_r      = (const float*)d_in[5];
    const float* maa_g      = (const float*)d_in[6];
    const float* maa_w1     = (const float*)d_in[7];
    const float* maa_w2     = (const float*)d_in[8];
    const float* time_decay = (const float*)d_in[9];
    const float* decay_w1   = (const float*)d_in[10];
    const float* decay_w2   = (const float*)d_in[11];
    const float* log_tau    = (const float*)d_in[12];
    const float* Wr         = (const float*)d_in[13];
    const float* Wk         = (const float*)d_in[14];
    const float* Wv         = (const float*)d_in[15];
    const float* Wg         = (const float*)d_in[16];
    const float* Wo         = (const float*)d_in[17];
    const float* ln_g       = (const float*)d_in[18];
    const float* ln_b       = (const float*)d_in[19];

    float* S = nullptr;
    cudaGetSymbolAddress((void**)&S, g_scratch);
    float* zb    = S + OFF_Z;
    float* xwb   = S + OFF_XW;
    float* rkvg  = S + OFF_RKVG;
    float* wb    = S + OFF_W;
    float* csb   = S + OFF_CS;
    float* xxxb  = S + OFF_XXX;
    float* wmidb = S + OFF_WMID;
    __nv_bfloat16* actHi = (__nv_bfloat16*)(S + OFF_ACTHI);
    __nv_bfloat16* actLo = (__nv_bfloat16*)(S + OFF_ACTLO);
    __nv_bfloat16* wtHi  = (__nv_bfloat16*)(S + OFF_WTHI);
    __nv_bfloat16* wtLo  = (__nv_bfloat16*)(S + OFF_WTLO);
    __nv_bfloat16* ygHi  = (__nv_bfloat16*)(S + OFF_YGHI);
    __nv_bfloat16* ygLo  = (__nv_bfloat16*)(S + OFF_YGLO);
    __nv_bfloat16* bfB   = (__nv_bfloat16*)(S + OFF_BF);

    int gemm_smem = 98304;
    cudaFuncSetAttribute(gemm_mma_k, cudaFuncAttributeMaxDynamicSharedMemorySize, gemm_smem);
    int attn_smem = 81920;
    cudaFuncSetAttribute(attn_mma_k, cudaFuncAttributeMaxDynamicSharedMemorySize, attn_smem);

    prep_k<<<(TD + 255) / 256, 256>>>(x, maa_x, zb);
    xxx_k<<<TTOK / 4, 320>>>(zb, maa_w1, xxxb);
    mix_k<<<TTOK / 4, 256>>>(x, xxxb, maa_w2,
                             maa_w, maa_k, maa_v, maa_r, maa_g, xwb, actHi, actLo);
    {
        dim3 grid(32, 32, 5);
        conv_wt_k<<<grid, 256>>>(Wr, Wk, Wv, Wg, Wo, wtHi, wtLo);
    }
    {
        dim3 grid(16, 16, 4);
        gemm_mma_k<<<grid, 256, gemm_smem>>>(actHi, actLo, wtHi, wtLo, rkvg, 3,
                                             bfB + (size_t)8 * TD, bfB + (size_t)9 * TD, 2);
    }
    decay1_k<<<TTOK / 8, 256>>>(xwb, decay_w1, wmidb);
    decay2_k<<<TTOK / 4, 256>>>(wmidb, decay_w2, time_decay, wb);
    cumsum_k<<<DDIM / 32, 1024>>>(wb, csb);
    premult_bf_k<<<(TD / 2 + 255) / 256, 256>>>(rkvg, rkvg + (size_t)TD, wb, csb, bfB);
    {
        dim3 grid(32, 16);
        attn_mma_k<<<grid, 256, attn_smem>>>(bfB, log_tau, rkvg + (size_t)3 * TD,
                                             ln_g, ln_b, ygHi, ygLo);
    }
    {
        dim3 grid(16, 16, 1);
        gemm_mma_k<<<grid, 256, gemm_smem>>>(ygHi, ygLo, wtHi + (size_t)4 * 1048576,
                                             wtLo + (size_t)4 * 1048576,
                                             (float*)d_out, -1, nullptr, nullptr, -1);
    }
}

// round 16
// speedup vs baseline: 1.2926x; 1.0096x over previous
#include <cuda_runtime.h>
#include <cuda_bf16.h>
#include <math.h>
#include <stdint.h>

#define TTOK 2048
#define DDIM 1024
#define TD (TTOK*DDIM)

// ---------------- scratch (static device memory; no allocations) ----------------
__device__ float g_scratch[68157440];

#define OFF_Z     ((size_t)1*TD)
#define OFF_XW    ((size_t)2*TD)
#define OFF_RKVG  ((size_t)7*TD)
#define OFF_W     ((size_t)11*TD)
#define OFF_CS    ((size_t)12*TD)
#define OFF_XXX   ((size_t)19*TD)
#define OFF_WMID  (OFF_XXX + (size_t)TTOK*160)
#define OFF_ACTHI ((size_t)20*TD)
#define OFF_ACTLO ((size_t)22*TD)
#define OFF_WTHI  ((size_t)24*TD)
#define OFF_WTLO  (OFF_WTHI + (size_t)2621440)
#define OFF_YGHI  (OFF_WTLO + (size_t)2621440)
#define OFF_YGLO  (OFF_YGHI + (size_t)(TD/2))
#define OFF_BF    (OFF_YGLO + (size_t)(TD/2))

// byte stride of one bf16 operand array
#define ARB ((size_t)TD * 2)

static __device__ __forceinline__ float clip60(float x) {
    return fminf(fmaxf(x, -60.f), 60.f);
}
static __device__ __forceinline__ uint32_t smem_u32(const void* p) {
    uint32_t a;
    asm("{ .reg .u64 t; cvta.to.shared.u64 t, %1; cvt.u32.u64 %0, t; }" : "=r"(a) : "l"(p));
    return a;
}

#define LDSM_X4(r, addr) \
    asm volatile("ldmatrix.sync.aligned.m8n8.x4.shared.b16 {%0,%1,%2,%3}, [%4];" \
                 : "=r"((r)[0]), "=r"((r)[1]), "=r"((r)[2]), "=r"((r)[3]) : "r"(addr))
#define LDSM_X4_T(r, addr) \
    asm volatile("ldmatrix.sync.aligned.m8n8.x4.trans.shared.b16 {%0,%1,%2,%3}, [%4];" \
                 : "=r"((r)[0]), "=r"((r)[1]), "=r"((r)[2]), "=r"((r)[3]) : "r"(addr))
#define MMA16816(d, a, b) \
    asm volatile("mma.sync.aligned.m16n8k16.row.col.f32.bf16.bf16.f32 " \
                 "{%0,%1,%2,%3}, {%4,%5,%6,%7}, {%8,%9}, {%0,%1,%2,%3};" \
                 : "+f"((d)[0]), "+f"((d)[1]), "+f"((d)[2]), "+f"((d)[3]) \
                 : "r"((a)[0]), "r"((a)[1]), "r"((a)[2]), "r"((a)[3]), \
                   "r"((b)[0]), "r"((b)[1]))
#define CPASYNC16(s, g) \
    asm volatile("cp.async.cg.shared.global [%0], [%1], 16;" :: "r"(s), "l"(g))
#define CPCOMMIT() asm volatile("cp.async.commit_group;" ::: "memory")
#define CPWAIT1()  asm volatile("cp.async.wait_group 1;" ::: "memory")
#define CPWAIT0()  asm volatile("cp.async.wait_group 0;" ::: "memory")
#define SWZ(o) ((o) ^ (((o) >> 3) & 0x70))

static __device__ __forceinline__ void split2(float a, float b,
                                              __nv_bfloat162* hi, __nv_bfloat162* lo) {
    __nv_bfloat162 h, l;
    h.x = __float2bfloat16(a);
    h.y = __float2bfloat16(b);
    l.x = __float2bfloat16(a - __bfloat162float(h.x));
    l.y = __float2bfloat16(b - __bfloat162float(h.y));
    *hi = h; *lo = l;
}
static __device__ __forceinline__ uint32_t packsplit(float a, float b, uint32_t* lo) {
    __nv_bfloat162 h, l;
    split2(a, b, &h, &l);
    *lo = *(uint32_t*)&l;
    return *(uint32_t*)&h;
}

// ---------------- 1. token shift -> z only ----------------
__global__ __launch_bounds__(256) void prep_k(const float* __restrict__ x,
                                              const float* __restrict__ maa_x,
                                              float* __restrict__ z) {
    int idx = blockIdx.x * 256 + threadIdx.x;
    if (idx >= TD) return;
    int t = idx >> 10;
    int d = idx & 1023;
    float xv = x[idx];
    float prev = (t > 0) ? x[idx - 1024] : 0.f;
    float nxt  = (t < TTOK - 1) ? x[idx + 1024] : 0.f;
    float dxv = 0.5f * (prev + nxt) - xv;
    z[idx] = xv + dxv * maa_x[d];
}

// ---------------- 2. xxx = tanh(z @ maa_w1): 320 thr, split-K ----------------
__global__ __launch_bounds__(320) void xxx_k(const float* __restrict__ z,
                                             const float* __restrict__ w1,
                                             float* __restrict__ xxx) {
    __shared__ float zs[4][1024];
    __shared__ float part[2][4][160];
    int t0 = blockIdx.x * 4;
    int tid = threadIdx.x;
    for (int i = tid; i < 1024; i += 320) {
        int r = i >> 8, c4 = (i & 255) * 4;
        *(float4*)&zs[r][c4] = *(const float4*)(z + (size_t)(t0 + r) * 1024 + c4);
    }
    __syncthreads();
    int out = (tid < 160) ? tid : (tid - 160);
    int kh = (tid < 160) ? 0 : 1;
    int kb = kh * 512;
    float acc[4] = {0.f, 0.f, 0.f, 0.f};
    for (int dd = 0; dd < 512; dd++) {
        int d = kb + dd;
        float w = w1[d * 160 + out];
        acc[0] += zs[0][d] * w;
        acc[1] += zs[1][d] * w;
        acc[2] += zs[2][d] * w;
        acc[3] += zs[3][d] * w;
    }
#pragma unroll
    for (int r = 0; r < 4; r++) part[kh][r][out] = acc[r];
    __syncthreads();
    if (tid < 160) {
#pragma unroll
        for (int r = 0; r < 4; r++)
            xxx[(size_t)(t0 + r) * 160 + tid] =
                tanhf(part[0][r][tid] + part[1][r][tid]);
    }
}

// ---------------- 3. mixer: dx recomputed inline ----------------
__global__ __launch_bounds__(256) void mix_k(const float* __restrict__ x,
                                             const float* __restrict__ xxx,
                                             const float* __restrict__ w2,
                                             const float* __restrict__ maa_w,
                                             const float* __restrict__ maa_k,
                                             const float* __restrict__ maa_v,
                                             const float* __restrict__ maa_r,
                                             const float* __restrict__ maa_g,
                                             float* __restrict__ xw,
                                             __nv_bfloat16* __restrict__ actHi,
                                             __nv_bfloat16* __restrict__ actLo) {
    __shared__ float xs[4][160];
    int t0 = blockIdx.x * 4;
    int tid = threadIdx.x;
    for (int i = tid; i < 640; i += 256) {
        int r = i / 160, c = i - r * 160;
        xs[r][c] = xxx[(size_t)(t0 + r) * 160 + c];
    }
    __syncthreads();
    int d = tid * 4;
    float4 xv[4], dxv[4];
#pragma unroll
    for (int r = 0; r < 4; r++) {
        int t = t0 + r;
        xv[r] = *(const float4*)(x + (size_t)t * 1024 + d);
        float4 pv = (t > 0) ? *(const float4*)(x + (size_t)(t - 1) * 1024 + d)
                            : make_float4(0.f, 0.f, 0.f, 0.f);
        float4 nv = (t < TTOK - 1) ? *(const float4*)(x + (size_t)(t + 1) * 1024 + d)
                                   : make_float4(0.f, 0.f, 0.f, 0.f);
        dxv[r].x = 0.5f * (pv.x + nv.x) - xv[r].x;
        dxv[r].y = 0.5f * (pv.y + nv.y) - xv[r].y;
        dxv[r].z = 0.5f * (pv.z + nv.z) - xv[r].z;
        dxv[r].w = 0.5f * (pv.w + nv.w) - xv[r].w;
    }
#pragma unroll
    for (int f = 0; f < 5; f++) {
        float4 acc[4];
#pragma unroll
        for (int r = 0; r < 4; r++) acc[r] = make_float4(0.f, 0.f, 0.f, 0.f);
        for (int mi = 0; mi < 32; mi++) {
            float4 w = *(const float4*)(w2 + (size_t)(f * 32 + mi) * 1024 + d);
#pragma unroll
            for (int r = 0; r < 4; r++) {
                float s = xs[r][f * 32 + mi];
                acc[r].x += s * w.x; acc[r].y += s * w.y;
                acc[r].z += s * w.z; acc[r].w += s * w.w;
            }
        }
        const float* maa = (f == 0) ? maa_w : (f == 1) ? maa_k : (f == 2) ? maa_v
                         : (f == 3) ? maa_r : maa_g;
        float4 mv = *(const float4*)(maa + d);
        int slot = (f == 3) ? 0 : (f == 1) ? 1 : (f == 2) ? 2 : 3;
#pragma unroll
        for (int r = 0; r < 4; r++) {
            float4 o;
            o.x = xv[r].x + dxv[r].x * (mv.x + acc[r].x);
            o.y = xv[r].y + dxv[r].y * (mv.y + acc[r].y);
            o.z = xv[r].z + dxv[r].z * (mv.z + acc[r].z);
            o.w = xv[r].w + dxv[r].w * (mv.w + acc[r].w);
            if (f == 0) {
                *(float4*)(xw + (size_t)(t0 + r) * 1024 + d) = o;
            } else {
                size_t ofs = (size_t)slot * TD + (size_t)(t0 + r) * 1024 + d;
                __nv_bfloat162 h0, l0, h1, l1;
                split2(o.x, o.y, &h0, &l0);
                split2(o.z, o.w, &h1, &l1);
                *(__nv_bfloat162*)(actHi + ofs)     = h0;
                *(__nv_bfloat162*)(actHi + ofs + 2) = h1;
                *(__nv_bfloat162*)(actLo + ofs)     = l0;
                *(__nv_bfloat162*)(actLo + ofs + 2) = l1;
            }
        }
    }
}

// ---------------- weight transpose + split ----------------
__global__ __launch_bounds__(256) void conv_wt_k(const float* __restrict__ W0,
                                                 const float* __restrict__ W1,
                                                 const float* __restrict__ W2,
                                                 const float* __restrict__ W3,
                                                 const float* __restrict__ W4,
                                                 __nv_bfloat16* __restrict__ hi,
                                                 __nv_bfloat16* __restrict__ lo) {
    __shared__ float tile[32][33];
    int z = blockIdx.z;
    const float* W = (z == 0) ? W0 : (z == 1) ? W1 : (z == 2) ? W2 : (z == 3) ? W3 : W4;
    int k0 = blockIdx.x * 32, n0 = blockIdx.y * 32;
    int tx = threadIdx.x & 31, ty = threadIdx.x >> 5;
#pragma unroll
    for (int i = 0; i < 32; i += 8)
        tile[ty + i][tx] = W[(size_t)(k0 + ty + i) * 1024 + n0 + tx];
    __syncthreads();
    size_t base = (size_t)z * 1048576;
#pragma unroll
    for (int i = 0; i < 32; i += 8) {
        float v = tile[tx][ty + i];
        size_t o = base + (size_t)(n0 + ty + i) * 1024 + k0 + tx;
        __nv_bfloat16 h = __float2bfloat16(v);
        hi[o] = h;
        lo[o] = __float2bfloat16(v - __bfloat162float(h));
    }
}

// ---------------- mma.sync split-bf16 GEMM: 128x64 tile, occ 2, strength-reduced ----------------
__global__ __launch_bounds__(256, 2)
void gemm_mma_k(const __nv_bfloat16* __restrict__ aHi,
                const __nv_bfloat16* __restrict__ aLo,
                const __nv_bfloat16* __restrict__ bHi,
                const __nv_bfloat16* __restrict__ bLo,
                float* __restrict__ C, int siluZ,
                __nv_bfloat16* __restrict__ vHi,
                __nv_bfloat16* __restrict__ vLo, int vz) {
    extern __shared__ unsigned char smraw[];
    const int tid = threadIdx.x;
    const int z = blockIdx.z;
    const int bm = blockIdx.y * 128;
    const int bn = blockIdx.x * 64;
    float* Cz = C + (size_t)z * TD;

    const uint32_t sbase = smem_u32(smraw);
    const int w = tid >> 5, lane = tid & 31;
    const int mw = w >> 1, nw = w & 1;

    const int ch16 = (tid & 7) * 16;
    const int arow = tid >> 3;
    const char* gA[2] = {
        (const char*)(aHi + (size_t)z * TD) + (size_t)(bm + arow) * 2048 + ch16,
        (const char*)(aLo + (size_t)z * TD) + (size_t)(bm + arow) * 2048 + ch16 };
    const char* gB[2] = {
        (const char*)(bHi + (size_t)z * 1048576) + (size_t)(bn + arow) * 2048 + ch16,
        (const char*)(bLo + (size_t)z * 1048576) + (size_t)(bn + arow) * 2048 + ch16 };
    const uint32_t swb = arow * 128 + (ch16 ^ ((arow & 7) << 4));

    float acc[2][4][4];
#pragma unroll
    for (int mt = 0; mt < 2; mt++)
#pragma unroll
        for (int nt = 0; nt < 4; nt++)
#pragma unroll
            for (int q = 0; q < 4; q++) acc[mt][nt][q] = 0.f;

    auto issue = [&](int c) {
        uint32_t stg = sbase + (c & 1) * 49152;
        uint32_t cofs = (uint32_t)c * 128;
#pragma unroll
        for (int jj = 0; jj < 8; jj++) {
            int tile = jj >> 2, sub = jj & 3;
            CPASYNC16(stg + tile * 16384 + swb + sub * 4096,
                      gA[tile] + sub * 65536 + cofs);
        }
#pragma unroll
        for (int jb = 0; jb < 4; jb++) {
            int tile = jb >> 1, sub = jb & 1;
            CPASYNC16(stg + 32768 + tile * 8192 + swb + sub * 4096,
                      gB[tile] + sub * 65536 + cofs);
        }
        CPCOMMIT();
    };

    uint32_t aRow128[2], aXr[2], bRow128[2], bXr[2];
    {
        int l15 = lane & 15;
#pragma unroll
        for (int mt = 0; mt < 2; mt++) {
            int r = mw * 32 + mt * 16 + l15;
            aRow128[mt] = r * 128;
            aXr[mt] = (r & 7) << 4;
        }
#pragma unroll
        for (int p = 0; p < 2; p++) {
            int r = nw * 32 + p * 16 + l15;
            bRow128[p] = r * 128;
            bXr[p] = (r & 7) << 4;
        }
    }
    const uint32_t hi16 = (lane >> 4) * 16;

    issue(0);
    issue(1);

    for (int c = 0; c < 16; c++) {
        if (c < 15) CPWAIT1(); else CPWAIT0();
        __syncthreads();
        uint32_t st = sbase + (c & 1) * 49152;
#pragma unroll
        for (int kk = 0; kk < 4; kk++) {
            uint32_t abyte = kk * 32 + hi16;
            uint32_t ah[2][4], al[2][4];
#pragma unroll
            for (int mt = 0; mt < 2; mt++) {
                uint32_t o = aRow128[mt] + (abyte ^ aXr[mt]);
                LDSM_X4(ah[mt], st + o);
                LDSM_X4(al[mt], st + 16384 + o);
            }
            uint32_t bh[4][2], bl[4][2];
#pragma unroll
            for (int p = 0; p < 2; p++) {
                uint32_t o = bRow128[p] + (abyte ^ bXr[p]);
                uint32_t t4[4];
                LDSM_X4(t4, st + 32768 + o);
                bh[2 * p][0] = t4[0]; bh[2 * p][1] = t4[2];
                bh[2 * p + 1][0] = t4[1]; bh[2 * p + 1][1] = t4[3];
                LDSM_X4(t4, st + 40960 + o);
                bl[2 * p][0] = t4[0]; bl[2 * p][1] = t4[2];
                bl[2 * p + 1][0] = t4[1]; bl[2 * p + 1][1] = t4[3];
            }
#pragma unroll
            for (int mt = 0; mt < 2; mt++)
#pragma unroll
                for (int nt = 0; nt < 4; nt++) {
                    MMA16816(acc[mt][nt], ah[mt], bh[nt]);
                    MMA16816(acc[mt][nt], ah[mt], bl[nt]);
                    MMA16816(acc[mt][nt], al[mt], bh[nt]);
                }
        }
        __syncthreads();
        if (c + 2 < 16) issue(c + 2);
    }

    bool silu = (z == siluZ);
    bool isv = (z == vz);
    int r0 = bm + mw * 32, c0 = bn + nw * 32;
#pragma unroll
    for (int mt = 0; mt < 2; mt++)
#pragma unroll
        for (int nt = 0; nt < 4; nt++) {
            float* d = acc[mt][nt];
            int row = r0 + mt * 16 + (lane >> 2);
            int col = c0 + nt * 8 + (lane & 3) * 2;
            if (isv) {
                __nv_bfloat162 h, l;
                split2(d[0], d[1], &h, &l);
                *(__nv_bfloat162*)(vHi + (size_t)row * 1024 + col) = h;
                *(__nv_bfloat162*)(vLo + (size_t)row * 1024 + col) = l;
                split2(d[2], d[3], &h, &l);
                *(__nv_bfloat162*)(vHi + (size_t)(row + 8) * 1024 + col) = h;
                *(__nv_bfloat162*)(vLo + (size_t)(row + 8) * 1024 + col) = l;
            } else {
                if (silu) {
#pragma unroll
                    for (int q = 0; q < 4; q++) d[q] = d[q] / (1.f + expf(-d[q]));
                }
                *(float2*)&Cz[(size_t)row * 1024 + col]       = make_float2(d[0], d[1]);
                *(float2*)&Cz[(size_t)(row + 8) * 1024 + col] = make_float2(d[2], d[3]);
            }
        }
}

// ---------------- 5. decay MLP stage 1 ----------------
__global__ __launch_bounds__(256) void decay1_k(const float* __restrict__ xw,
                                                const float* __restrict__ dw1,
                                                float* __restrict__ wmid) {
    __shared__ float xs[8][1024];
    __shared__ float part[4][64][8];
    int t0 = blockIdx.x * 8;
    int tid = threadIdx.x;
    for (int i = tid; i < 8 * 256; i += 256) {
        int r = i >> 8;
        int c4 = (i & 255) * 4;
        *(float4*)(&xs[r][c4]) = *(const float4*)(xw + (size_t)(t0 + r) * 1024 + c4);
    }
    __syncthreads();
    int n = tid & 63;
    int kq = tid >> 6;
    int kbase = kq * 256;
    float acc[8] = {0.f, 0.f, 0.f, 0.f, 0.f, 0.f, 0.f, 0.f};
    for (int dd = 0; dd < 256; dd++) {
        int d = kbase + dd;
        float w = dw1[d * 64 + n];
#pragma unroll
        for (int r = 0; r < 8; r++) acc[r] += xs[r][d] * w;
    }
#pragma unroll
    for (int r = 0; r < 8; r++) part[kq][n][r] = acc[r];
    __syncthreads();
    for (int i = tid; i < 512; i += 256) {
        int nn = i & 63, r = i >> 6;
        float s = part[0][nn][r] + part[1][nn][r] + part[2][nn][r] + part[3][nn][r];
        wmid[(size_t)(t0 + r) * 64 + nn] = tanhf(s);
    }
}

// ---------------- 6. decay MLP stage 2 ----------------
__global__ __launch_bounds__(256) void decay2_k(const float* __restrict__ wmid,
                                                const float* __restrict__ dw2,
                                                const float* __restrict__ td,
                                                float* __restrict__ w) {
    __shared__ float ws[4][64];
    int t0 = blockIdx.x * 4;
    int tid = threadIdx.x;
    {
        int r = tid >> 6, c = tid & 63;
        ws[r][c] = wmid[(size_t)(t0 + r) * 64 + c];
    }
    __syncthreads();
    int d = tid * 4;
    float4 tdv = *(const float4*)(td + d);
    float4 acc[4];
#pragma unroll
    for (int r = 0; r < 4; r++) acc[r] = tdv;
    for (int j = 0; j < 64; j++) {
        float4 wv = *(const float4*)(dw2 + (size_t)j * 1024 + d);
#pragma unroll
        for (int r = 0; r < 4; r++) {
            float s = ws[r][j];
            acc[r].x += s * wv.x; acc[r].y += s * wv.y;
            acc[r].z += s * wv.z; acc[r].w += s * wv.w;
        }
    }
#pragma unroll
    for (int r = 0; r < 4; r++)
        *(float4*)(w + (size_t)(t0 + r) * 1024 + d) = acc[r];
}

// ---------------- 7. per-channel cumsum ----------------
__global__ __launch_bounds__(1024) void cumsum_k(const float* __restrict__ w,
                                                 float* __restrict__ cs) {
    __shared__ float seg[32][33];
    int c = threadIdx.x & 31;
    int j = threadIdx.x >> 5;
    int d = blockIdx.x * 32 + c;
    int tb = j * 64;
    float s = 0.f;
    for (int t = 0; t < 64; t++)
        s -= expf(w[(size_t)(tb + t) * 1024 + d]);
    seg[j][c] = s;
    __syncthreads();
    if (j == 0) {
        float run = 0.f;
        for (int jj = 0; jj < 32; jj++) {
            float tmp = seg[jj][c];
            seg[jj][c] = run;
            run += tmp;
        }
    }
    __syncthreads();
    float run = seg[j][c];
    for (int t = 0; t < 64; t++) {
        run -= expf(w[(size_t)(tb + t) * 1024 + d]);
        cs[(size_t)(tb + t) * 1024 + d] = run;
    }
}

// ---------------- 8. premult -> bf16 hi/lo (2 elems/thread) ----------------
__global__ __launch_bounds__(256) void premult_bf_k(const float* __restrict__ r,
                                                    const float* __restrict__ k,
                                                    const float* __restrict__ w,
                                                    const float* __restrict__ cs,
                                                    __nv_bfloat16* __restrict__ bfB) {
    int p = blockIdx.x * 256 + threadIdx.x;
    int idx = p * 2;
    if (idx >= TD) return;
    int d = idx & 1023;
    size_t midoff = (size_t)(TTOK / 2) * 1024 + d;
    float2 csv = *(const float2*)&cs[idx];
    float2 csm = *(const float2*)&cs[midoff];
    float2 wv  = *(const float2*)&w[idx];
    float2 wm  = *(const float2*)&w[midoff];
    float wh0  = -expf(wv.x), wh1 = -expf(wv.y);
    float whm0 = -expf(wm.x), whm1 = -expf(wm.y);
    float csf0 = clip60(csv.x - csm.x), csf1 = clip60(csv.y - csm.y);
    float csb0 = clip60((csv.x - wh0) - (csm.x - whm0));
    float csb1 = clip60((csv.y - wh1) - (csm.y - whm1));
    float2 rv = *(const float2*)&r[idx];
    float2 kv = *(const float2*)&k[idx];
    float v0[4], v1[4];
    v0[0] = rv.x * expf(csf0);   v1[0] = rv.y * expf(csf1);
    v0[1] = kv.x * expf(-csf0);  v1[1] = kv.y * expf(-csf1);
    v0[2] = rv.x * expf(-csb0);  v1[2] = rv.y * expf(-csb1);
    v0[3] = kv.x * expf(csb0);   v1[3] = kv.y * expf(csb1);
#pragma unroll
    for (int j = 0; j < 4; j++) {
        __nv_bfloat162 h, l;
        split2(v0[j], v1[j], &h, &l);
        *(__nv_bfloat162*)(bfB + (size_t)(2 * j) * TD + idx) = h;
        *(__nv_bfloat162*)(bfB + (size_t)(2 * j + 1) * TD + idx) = l;
    }
}

// ---------------- 9. attention + fused groupnorm/gate, split-group loads ----------------
__global__ __launch_bounds__(256, 2) void attn_mma_k(const __nv_bfloat16* __restrict__ bfB,
                                                     const float* __restrict__ log_tau,
                                                     const float* __restrict__ g,
                                                     const float* __restrict__ ln_g,
                                                     const float* __restrict__ ln_b,
                                                     __nv_bfloat16* __restrict__ ygHi,
                                                     __nv_bfloat16* __restrict__ ygLo) {
    extern __shared__ unsigned char sm8[];
    __shared__ float redA[64], redS[64];
    const uint32_t sb = smem_u32(sm8);
    int h = blockIdx.y, it = blockIdx.x;
    int t0 = it * 64;
    int tid = threadIdx.x, w = tid >> 5, lane = tid & 31;
    int mw = w >> 1, sw = w & 1;
    size_t hb = (size_t)h * 64;
    float tau = expf(log_tau[h]);
    int grp = lane >> 2, qp = lane & 3;

    if (tid < 64) { redA[tid] = 0.f; redS[tid] = 0.f; }

    const int row0 = tid >> 3;
    const uint32_t ch16 = (tid & 7) * 16;
    const uint32_t swoff = row0 * 128 + (ch16 ^ ((row0 & 7) << 4));
    const char* gbase = (const char*)bfB + (size_t)row0 * 2048 + hb * 2 + ch16;

    {
        const char* gt = gbase + (size_t)t0 * 2048;
        CPASYNC16(sb + swoff,                  gt);
        CPASYNC16(sb + swoff + 4096,           gt + 65536);
        CPASYNC16(sb + 8192 + swoff,           gt + 1 * ARB);
        CPASYNC16(sb + 8192 + swoff + 4096,    gt + 1 * ARB + 65536);
        CPASYNC16(sb + 16384 + swoff,          gt + 4 * ARB);
        CPASYNC16(sb + 16384 + swoff + 4096,   gt + 4 * ARB + 65536);
        CPASYNC16(sb + 24576 + swoff,          gt + 5 * ARB);
        CPASYNC16(sb + 24576 + swoff + 4096,   gt + 5 * ARB + 65536);
    }
    CPCOMMIT();
    CPWAIT0();
    __syncthreads();

    const uint32_t dstk = sb + 32768 + swoff;

    const uint32_t hi16 = (lane >> 4) * 16;
    uint32_t aRow128, aXr;
    {
        int r = mw * 16 + (lane & 15);
        aRow128 = r * 128; aXr = (r & 7) << 4;
    }
    uint32_t bRow128[2], bXr[2];
#pragma unroll
    for (int p = 0; p < 2; p++) {
        int r = sw * 32 + p * 16 + (lane & 15);
        bRow128[p] = r * 128; bXr[p] = (r & 7) << 4;
    }
    uint32_t vRow128[2], vXr[2];
#pragma unroll
    for (int kc = 0; kc < 2; kc++) {
        int r = sw * 32 + kc * 16 + (lane & 15);
        vRow128[kc] = r * 128; vXr[kc] = (r & 7) << 4;
    }

    float accY[8][4];
#pragma unroll
    for (int nt = 0; nt < 8; nt++)
#pragma unroll
        for (int q = 0; q < 4; q++) accY[nt][q] = 0.f;
    float sA[2] = {0.f, 0.f};
    float sS[2] = {0.f, 0.f};

    for (int jt = 0; jt < 32; jt++) {
        int s0 = jt * 64;
        bool needF = (jt <= it);
        bool needB = (jt >= it);
        {
            const char* gs = gbase + (size_t)s0 * 2048;
            // group A: k tiles (scores)
            if (needF) {
                CPASYNC16(dstk,                  gs + 2 * ARB);
                CPASYNC16(dstk + 4096,           gs + 2 * ARB + 65536);
                CPASYNC16(dstk + 8192,           gs + 3 * ARB);
                CPASYNC16(dstk + 8192 + 4096,    gs + 3 * ARB + 65536);
            }
            if (needB) {
                CPASYNC16(dstk + 16384,          gs + 6 * ARB);
                CPASYNC16(dstk + 16384 + 4096,   gs + 6 * ARB + 65536);
                CPASYNC16(dstk + 24576,          gs + 7 * ARB);
                CPASYNC16(dstk + 24576 + 4096,   gs + 7 * ARB + 65536);
            }
            CPCOMMIT();
            // group B: v tiles (AV) — overlapped with score compute
            CPASYNC16(dstk + 32768,              gs + 8 * ARB);
            CPASYNC16(dstk + 32768 + 4096,       gs + 8 * ARB + 65536);
            CPASYNC16(dstk + 40960,              gs + 9 * ARB);
            CPASYNC16(dstk + 40960 + 4096,       gs + 9 * ARB + 65536);
            CPCOMMIT();
        }
        CPWAIT1();           // k tiles ready; v still in flight
        __syncthreads();

        float accF[4][4], accB[4][4];
#pragma unroll
        for (int nt = 0; nt < 4; nt++)
#pragma unroll
            for (int q = 0; q < 4; q++) { accF[nt][q] = 0.f; accB[nt][q] = 0.f; }

#pragma unroll
        for (int ks = 0; ks < 4; ks++) {
            uint32_t abyte = ks * 32 + hi16;
            uint32_t oA = aRow128 + (abyte ^ aXr);
            if (needF) {
                uint32_t aH[4], aL[4];
                LDSM_X4(aH, sb + oA);
                LDSM_X4(aL, sb + 8192 + oA);
                uint32_t bh[4][2], bl[4][2];
#pragma unroll
                for (int p = 0; p < 2; p++) {
                    uint32_t o = bRow128[p] + (abyte ^ bXr[p]);
                    uint32_t t4[4], u4[4];
                    LDSM_X4(t4, sb + 32768 + o);
                    LDSM_X4(u4, sb + 40960 + o);
                    bh[2 * p][0] = t4[0]; bh[2 * p][1] = t4[2];
                    bh[2 * p + 1][0] = t4[1]; bh[2 * p + 1][1] = t4[3];
                    bl[2 * p][0] = u4[0]; bl[2 * p][1] = u4[2];
                    bl[2 * p + 1][0] = u4[1]; bl[2 * p + 1][1] = u4[3];
                }
#pragma unroll
                for (int nt = 0; nt < 4; nt++) {
                    MMA16816(accF[nt], aH, bh[nt]);
                    MMA16816(accF[nt], aH, bl[nt]);
                    MMA16816(accF[nt], aL, bh[nt]);
                }
            }
            if (needB) {
                uint32_t aH[4], aL[4];
                LDSM_X4(aH, sb + 16384 + oA);
                LDSM_X4(aL, sb + 24576 + oA);
                uint32_t bh[4][2], bl[4][2];
#pragma unroll
                for (int p = 0; p < 2; p++) {
                    uint32_t o = bRow128[p] + (abyte ^ bXr[p]);
                    uint32_t t4[4], u4[4];
                    LDSM_X4(t4, sb + 49152 + o);
                    LDSM_X4(u4, sb + 57344 + o);
                    bh[2 * p][0] = t4[0]; bh[2 * p][1] = t4[2];
                    bh[2 * p + 1][0] = t4[1]; bh[2 * p + 1][1] = t4[3];
                    bl[2 * p][0] = u4[0]; bl[2 * p][1] = u4[2];
                    bl[2 * p + 1][0] = u4[1]; bl[2 * p + 1][1] = u4[3];
                }
#pragma unroll
                for (int nt = 0; nt < 4; nt++) {
                    MMA16816(accB[nt], aH, bh[nt]);
                    MMA16816(accB[nt], aH, bl[nt]);
                    MMA16816(accB[nt], aL, bh[nt]);
                }
            }
        }

        uint32_t pH[2][4], pL[2][4];
#pragma unroll
        for (int nt = 0; nt < 4; nt++) {
            float ash[4];
#pragma unroll
            for (int q = 0; q < 4; q++) {
                int trow = t0 + mw * 16 + grp + (q >> 1) * 8;
                int scol = s0 + sw * 32 + nt * 8 + qp * 2 + (q & 1);
                float val;
                if (jt < it) val = accF[nt][q];
                else if (jt > it) val = accB[nt][q];
                else val = (scol > trow) ? accB[nt][q] : accF[nt][q];
                float a = fmaxf(val, 0.f);
                sA[q >> 1] += a;
                float as = (a > 0.f) ? __powf(a + 1e-12f, tau) : 0.f;
                sS[q >> 1] += as;
                ash[q] = as;
            }
            int kc = nt >> 1, half = nt & 1;
            pH[kc][half * 2]     = packsplit(ash[0], ash[1], &pL[kc][half * 2]);
            pH[kc][half * 2 + 1] = packsplit(ash[2], ash[3], &pL[kc][half * 2 + 1]);
        }

        CPWAIT0();           // v tiles ready
        __syncthreads();

#pragma unroll
        for (int kc = 0; kc < 2; kc++) {
#pragma unroll
            for (int dblk = 0; dblk < 4; dblk++) {
                uint32_t db = dblk * 32 + hi16;
                uint32_t ov = vRow128[kc] + (db ^ vXr[kc]);
                uint32_t t4[4], u4[4];
                LDSM_X4_T(t4, sb + 65536 + ov);
                LDSM_X4_T(u4, sb + 73728 + ov);
                uint32_t bvh[2][2] = {{t4[0], t4[1]}, {t4[2], t4[3]}};
                uint32_t bvl[2][2] = {{u4[0], u4[1]}, {u4[2], u4[3]}};
#pragma unroll
                for (int x = 0; x < 2; x++) {
                    int nt = dblk * 2 + x;
                    MMA16816(accY[nt], pH[kc], bvh[x]);
                    MMA16816(accY[nt], pH[kc], bvl[x]);
                    MMA16816(accY[nt], pL[kc], bvh[x]);
                }
            }
        }
        __syncthreads();
    }

#pragma unroll
    for (int qh = 0; qh < 2; qh++) {
        float va = sA[qh], vs = sS[qh];
        va += __shfl_xor_sync(0xFFFFFFFFu, va, 1);
        va += __shfl_xor_sync(0xFFFFFFFFu, va, 2);
        vs += __shfl_xor_sync(0xFFFFFFFFu, vs, 1);
        vs += __shfl_xor_sync(0xFFFFFFFFu, vs, 2);
        if ((lane & 3) == 0) {
            int trow = mw * 16 + grp + qh * 8;
            atomicAdd(&redA[trow], va);
            atomicAdd(&redS[trow], vs);
        }
    }

    float* red = (float*)sm8;
    __syncthreads();
    if (sw == 1) {
#pragma unroll
        for (int nt = 0; nt < 8; nt++) {
            int r0 = mw * 16 + grp;
            int col = nt * 8 + qp * 2;
            *(float2*)&red[(r0)     * 64 + col] = make_float2(accY[nt][0], accY[nt][1]);
            *(float2*)&red[(r0 + 8) * 64 + col] = make_float2(accY[nt][2], accY[nt][3]);
        }
    }
    __syncthreads();
    if (sw == 0) {
        int r0 = mw * 16 + grp;
        int r1 = r0 + 8;
        float sc0 = fmaxf(redA[r0], 1e-12f) / fmaxf(redS[r0], 1e-12f);
        float sc1 = fmaxf(redA[r1], 1e-12f) / fmaxf(redS[r1], 1e-12f);
        float s0 = 0.f, q0 = 0.f, s1 = 0.f, q1 = 0.f;
#pragma unroll
        for (int nt = 0; nt < 8; nt++) {
            int col = nt * 8 + qp * 2;
            float2 o0 = *(float2*)&red[r0 * 64 + col];
            float2 o1 = *(float2*)&red[r1 * 64 + col];
            accY[nt][0] = (accY[nt][0] + o0.x) * sc0;
            accY[nt][1] = (accY[nt][1] + o0.y) * sc0;
            accY[nt][2] = (accY[nt][2] + o1.x) * sc1;
            accY[nt][3] = (accY[nt][3] + o1.y) * sc1;
            s0 += accY[nt][0] + accY[nt][1];
            q0 += accY[nt][0] * accY[nt][0] + accY[nt][1] * accY[nt][1];
            s1 += accY[nt][2] + accY[nt][3];
            q1 += accY[nt][2] * accY[nt][2] + accY[nt][3] * accY[nt][3];
        }
        s0 += __shfl_xor_sync(0xFFFFFFFFu, s0, 1);
        s0 += __shfl_xor_sync(0xFFFFFFFFu, s0, 2);
        q0 += __shfl_xor_sync(0xFFFFFFFFu, q0, 1);
        q0 += __shfl_xor_sync(0xFFFFFFFFu, q0, 2);
        s1 += __shfl_xor_sync(0xFFFFFFFFu, s1, 1);
        s1 += __shfl_xor_sync(0xFFFFFFFFu, s1, 2);
        q1 += __shfl_xor_sync(0xFFFFFFFFu, q1, 1);
        q1 += __shfl_xor_sync(0xFFFFFFFFu, q1, 2);
        float mu0 = s0 * (1.f / 64.f);
        float var0 = q0 * (1.f / 64.f) - mu0 * mu0;
        float inv0 = rsqrtf(var0 + 6.4e-4f);
        float mu1 = s1 * (1.f / 64.f);
        float var1 = q1 * (1.f / 64.f) - mu1 * mu1;
        float inv1 = rsqrtf(var1 + 6.4e-4f);
#pragma unroll
        for (int nt = 0; nt < 8; nt++) {
            int col = nt * 8 + qp * 2;
            int dch = (int)hb + col;
            float2 lg = *(const float2*)&ln_g[dch];
            float2 lb = *(const float2*)&ln_b[dch];
            float2 gg0 = *(const float2*)&g[(size_t)(t0 + r0) * 1024 + dch];
            float2 gg1 = *(const float2*)&g[(size_t)(t0 + r1) * 1024 + dch];
            float ox0 = ((accY[nt][0] - mu0) * inv0 * lg.x + lb.x) * gg0.x;
            float oy0 = ((accY[nt][1] - mu0) * inv0 * lg.y + lb.y) * gg0.y;
            float ox1 = ((accY[nt][2] - mu1) * inv1 * lg.x + lb.x) * gg1.x;
            float oy1 = ((accY[nt][3] - mu1) * inv1 * lg.y + lb.y) * gg1.y;
            __nv_bfloat162 hh, ll;
            split2(ox0, oy0, &hh, &ll);
            *(__nv_bfloat162*)(ygHi + (size_t)(t0 + r0) * 1024 + dch) = hh;
            *(__nv_bfloat162*)(ygLo + (size_t)(t0 + r0) * 1024 + dch) = ll;
            split2(ox1, oy1, &hh, &ll);
            *(__nv_bfloat162*)(ygHi + (size_t)(t0 + r1) * 1024 + dch) = hh;
            *(__nv_bfloat162*)(ygLo + (size_t)(t0 + r1) * 1024 + dch) = ll;
        }
    }
}

// ---------------- launch ----------------
extern "C" void kernel_launch(void* const* d_in, const int* in_sizes, int n_in,
                              void* d_out, int out_size) {
    const float* x          = (const float*)d_in[0];
    const float* maa_x      = (const float*)d_in[1];
    const float* maa_w      = (const float*)d_in[2];
    const float* maa_k      = (const float*)d_in[3];
    const float* maa_v      = (const float*)d_in[4];
    const float* maa_r      = (const float*)d_in[5];
    const float* maa_g      = (const float*)d_in[6];
    const float* maa_w1     = (const float*)d_in[7];
    const float* maa_w2     = (const float*)d_in[8];
    const float* time_decay = (const float*)d_in[9];
    const float* decay_w1   = (const float*)d_in[10];
    const float* decay_w2   = (const float*)d_in[11];
    const float* log_tau    = (const float*)d_in[12];
    const float* Wr         = (const float*)d_in[13];
    const float* Wk         = (const float*)d_in[14];
    const float* Wv         = (const float*)d_in[15];
    const float* Wg         = (const float*)d_in[16];
    const float* Wo         = (const float*)d_in[17];
    const float* ln_g       = (const float*)d_in[18];
    const float* ln_b       = (const float*)d_in[19];

    float* S = nullptr;
    cudaGetSymbolAddress((void**)&S, g_scratch);
    float* zb    = S + OFF_Z;
    float* xwb   = S + OFF_XW;
    float* rkvg  = S + OFF_RKVG;
    float* wb    = S + OFF_W;
    float* csb   = S + OFF_CS;
    float* xxxb  = S + OFF_XXX;
    float* wmidb = S + OFF_WMID;
    __nv_bfloat16* actHi = (__nv_bfloat16*)(S + OFF_ACTHI);
    __nv_bfloat16* actLo = (__nv_bfloat16*)(S + OFF_ACTLO);
    __nv_bfloat16* wtHi  = (__nv_bfloat16*)(S + OFF_WTHI);
    __nv_bfloat16* wtLo  = (__nv_bfloat16*)(S + OFF_WTLO);
    __nv_bfloat16* ygHi  = (__nv_bfloat16*)(S + OFF_YGHI);
    __nv_bfloat16* ygLo  = (__nv_bfloat16*)(S + OFF_YGLO);
    __nv_bfloat16* bfB   = (__nv_bfloat16*)(S + OFF_BF);

    int gemm_smem = 98304;
    cudaFuncSetAttribute(gemm_mma_k, cudaFuncAttributeMaxDynamicSharedMemorySize, gemm_smem);
    int attn_smem = 81920;
    cudaFuncSetAttribute(attn_mma_k, cudaFuncAttributeMaxDynamicSharedMemorySize, attn_smem);

    prep_k<<<(TD + 255) / 256, 256>>>(x, maa_x, zb);
    xxx_k<<<TTOK / 4, 320>>>(zb, maa_w1, xxxb);
    mix_k<<<TTOK / 4, 256>>>(x, xxxb, maa_w2,
                             maa_w, maa_k, maa_v, maa_r, maa_g, xwb, actHi, actLo);
    {
        dim3 grid(32, 32, 5);
        conv_wt_k<<<grid, 256>>>(Wr, Wk, Wv, Wg, Wo, wtHi, wtLo);
    }
    {
        dim3 grid(16, 16, 4);
        gemm_mma_k<<<grid, 256, gemm_smem>>>(actHi, actLo, wtHi, wtLo, rkvg, 3,
                                             bfB + (size_t)8 * TD, bfB + (size_t)9 * TD, 2);
    }
    decay1_k<<<TTOK / 8, 256>>>(xwb, decay_w1, wmidb);
    decay2_k<<<TTOK / 4, 256>>>(wmidb, decay_w2, time_decay, wb);
    cumsum_k<<<DDIM / 32, 1024>>>(wb, csb);
    premult_bf_k<<<(TD / 2 + 255) / 256, 256>>>(rkvg, rkvg + (size_t)TD, wb, csb, bfB);
    {
        dim3 grid(32, 16);
        attn_mma_k<<<grid, 256, attn_smem>>>(bfB, log_tau, rkvg + (size_t)3 * TD,
                                             ln_g, ln_b, ygHi, ygLo);
    }
    {
        dim3 grid(16, 16, 1);
        gemm_mma_k<<<grid, 256, gemm_smem>>>(ygHi, ygLo, wtHi + (size_t)4 * 1048576,
                                             wtLo + (size_t)4 * 1048576,
                                             (float*)d_out, -1, nullptr, nullptr, -1);
    }
}